// round 3
// baseline (speedup 1.0000x reference)
#include <cuda_runtime.h>

#define EPSF 1e-5f

// ---------------- scratch (static device globals; no allocation) ----------------
__device__ float g_h[(size_t)4 * 21504 * 512];      // region GEMM out / activated in-place
__device__ float g_y[(size_t)12 * 21504 * 512];     // class GEMM out (pre-BN)
__device__ float g_hmean[(size_t)4 * 1024 * 512];   // seq-mean of activated h
__device__ float g_fv[(size_t)1024 * 12 * 512];     // f_v
__device__ float g_hg[(size_t)1024 * 12 * 512];     // GAT projection
__device__ float g_gat[(size_t)1024 * 12 * 512];    // GAT output (g)
__device__ float g_v[(size_t)1024 * 12 * 512];      // temporal conv out (pre-BN)
__device__ float g_rstats[4 * 512 * 2];             // region BN sum/sumsq
__device__ float g_cstats[12 * 512 * 2];            // class BN sum/sumsq
__device__ float g_tstats[24];                      // temporal BN sum/sumsq per class

__constant__ int c_sel[12]  = {0, 0, 0, 1, 0, 3, 2, 2, 2, 3, 3, 3};
__constant__ int c_start[4] = {0, 14, 28, 28};
__constant__ float c_adj[144] = {
    0,0,0,1,0,1,1,1,1,1,1,1,
    0,0,0,1,0,1,1,1,1,1,1,1,
    0,0,0,1,0,1,1,1,1,1,1,1,
    1,1,1,0,1,1,1,1,1,1,1,1,
    0,0,0,1,0,1,1,1,1,1,1,1,
    1,1,1,1,1,0,1,1,1,0,0,0,
    1,1,1,1,1,1,0,0,0,1,1,1,
    1,1,1,1,1,1,0,0,0,1,1,1,
    1,1,1,1,1,1,0,0,0,1,1,1,
    1,1,1,1,1,0,1,1,1,0,0,0,
    1,1,1,1,1,0,1,1,1,0,0,0,
    1,1,1,1,1,0,1,1,1,0,0,0
};

// ---------------- stats zeroing ----------------
__global__ void zero_stats_kernel() {
    int i = blockIdx.x * blockDim.x + threadIdx.x;
    if (i < 4 * 512 * 2)  g_rstats[i] = 0.f;
    if (i < 12 * 512 * 2) g_cstats[i] = 0.f;
    if (i < 24)           g_tstats[i] = 0.f;
}

// ---------------- 128x128x8 fp32 GEMM, bias + fused BN-statistics epilogue ----------------
// mode 0: region   A = x  (grid of 49 positions, region slice per z), Y = g_h,  stats = g_rstats
// mode 1: class    A = g_h[sel[z]],                                  Y = g_y,  stats = g_cstats
// mode 2: gat      A = g_fv (plain rows),                            Y = g_hg, no stats
__global__ __launch_bounds__(256)
void gemm_k(const float* __restrict__ A_ext,
            const float* __restrict__ W,
            const float* __restrict__ bias,
            int M, int mode)
{
    __shared__ float As[8][132];   // padded to kill store conflicts, float4-aligned
    __shared__ float Bs[8][128];
    __shared__ float cstat[256];

    const float* A;
    float* Y;
    float* stats;
    if (mode == 0)      { A = A_ext; Y = g_h;  stats = g_rstats; }
    else if (mode == 1) { A = g_h;   Y = g_y;  stats = g_cstats; }
    else                { A = g_fv;  Y = g_hg; stats = nullptr;  }

    const int z   = blockIdx.z;
    const int n0  = blockIdx.x * 128;
    const int m0  = blockIdx.y * 128;
    const int tid = threadIdx.x;

    // A tile loader mapping: thread -> (row in tile, half of 8-wide k strip)
    const int lrow = tid >> 1;
    const int ka   = (tid & 1) * 4;
    const int m    = m0 + lrow;
    const float* arow;
    if (mode == 0) {
        int bt = m / 21;
        int s  = m - bt * 21;
        arow = A + ((size_t)bt * 49 + c_start[z] + s) * 512 + ka;
    } else if (mode == 1) {
        arow = A + ((size_t)c_sel[z] * M + m) * 512 + ka;
    } else {
        arow = A + (size_t)m * 512 + ka;
    }
    // B tile loader mapping
    const int bk = tid >> 5;
    const int bc = (tid & 31) * 4;
    const float* wrow = W + (size_t)z * 512 * 512 + (size_t)bk * 512 + n0 + bc;

    const int tx = tid & 15;
    const int ty = tid >> 4;

    float acc[8][8];
    #pragma unroll
    for (int i = 0; i < 8; ++i)
        #pragma unroll
        for (int j = 0; j < 8; ++j) acc[i][j] = 0.f;

    for (int kt = 0; kt < 64; ++kt) {
        const float4 av = *(const float4*)(arow + kt * 8);
        const float4 bv = *(const float4*)(wrow + (size_t)kt * 8 * 512);
        __syncthreads();
        As[ka + 0][lrow] = av.x;
        As[ka + 1][lrow] = av.y;
        As[ka + 2][lrow] = av.z;
        As[ka + 3][lrow] = av.w;
        *(float4*)&Bs[bk][bc] = bv;
        __syncthreads();
        #pragma unroll
        for (int k = 0; k < 8; ++k) {
            float4 a0 = *(const float4*)&As[k][ty * 4];
            float4 a1 = *(const float4*)&As[k][64 + ty * 4];
            float4 b0 = *(const float4*)&Bs[k][tx * 4];
            float4 b1 = *(const float4*)&Bs[k][64 + tx * 4];
            float aa[8] = {a0.x, a0.y, a0.z, a0.w, a1.x, a1.y, a1.z, a1.w};
            float bb[8] = {b0.x, b0.y, b0.z, b0.w, b1.x, b1.y, b1.z, b1.w};
            #pragma unroll
            for (int i = 0; i < 8; ++i)
                #pragma unroll
                for (int j = 0; j < 8; ++j)
                    acc[i][j] = fmaf(aa[i], bb[j], acc[i][j]);
        }
    }

    // epilogue: bias add, store, accumulate per-column sum / sumsq
    float bcol[8];
    #pragma unroll
    for (int j = 0; j < 8; ++j) {
        int lc = (j < 4) ? (tx * 4 + j) : (64 + tx * 4 + j - 4);
        bcol[j] = bias ? bias[(size_t)z * 512 + n0 + lc] : 0.f;
    }
    float vsum[8], vsq[8];
    #pragma unroll
    for (int j = 0; j < 8; ++j) { vsum[j] = 0.f; vsq[j] = 0.f; }

    #pragma unroll
    for (int i = 0; i < 8; ++i) {
        int row = m0 + ((i < 4) ? (ty * 4 + i) : (64 + ty * 4 + i - 4));
        float* yrow = Y + ((size_t)z * M + row) * 512 + n0;
        float v[8];
        #pragma unroll
        for (int j = 0; j < 8; ++j) {
            v[j] = acc[i][j] + bcol[j];
            vsum[j] += v[j];
            vsq[j]  += v[j] * v[j];
        }
        *(float4*)(yrow + tx * 4)      = make_float4(v[0], v[1], v[2], v[3]);
        *(float4*)(yrow + 64 + tx * 4) = make_float4(v[4], v[5], v[6], v[7]);
    }

    if (stats) {
        if (tid < 256) cstat[tid] = 0.f;
        __syncthreads();
        #pragma unroll
        for (int j = 0; j < 8; ++j) {
            int lc = (j < 4) ? (tx * 4 + j) : (64 + tx * 4 + j - 4);
            atomicAdd(&cstat[lc],       vsum[j]);
            atomicAdd(&cstat[128 + lc], vsq[j]);
        }
        __syncthreads();
        if (tid < 128) {
            atomicAdd(&stats[((size_t)z * 512 + n0 + tid) * 2],     cstat[tid]);
            atomicAdd(&stats[((size_t)z * 512 + n0 + tid) * 2 + 1], cstat[128 + tid]);
        }
    }
}

// ---------------- BN+ReLU on h (in place) + seq-mean ----------------
__global__ void bn_h_kernel(const float* __restrict__ gamma, const float* __restrict__ beta)
{
    const int bt = blockIdx.x;
    const int r  = blockIdx.y;
    const int c  = threadIdx.x;
    const float s1 = g_rstats[(r * 512 + c) * 2];
    const float s2 = g_rstats[(r * 512 + c) * 2 + 1];
    const float inv_n = 1.f / 21504.f;
    const float mean  = s1 * inv_n;
    const float var   = s2 * inv_n - mean * mean;
    const float rstd  = rsqrtf(var + EPSF);
    const float sc = gamma[r * 512 + c] * rstd;
    const float sh = beta[r * 512 + c] - mean * sc;
    size_t base = ((size_t)r * 21504 + (size_t)bt * 21) * 512 + c;
    float accv = 0.f;
    #pragma unroll
    for (int s = 0; s < 21; ++s) {
        float v = g_h[base + (size_t)s * 512];
        v = fmaxf(fmaf(v, sc, sh), 0.f);
        g_h[base + (size_t)s * 512] = v;
        accv += v;
    }
    g_hmean[((size_t)r * 1024 + bt) * 512 + c] = accv * (1.f / 21.f);
}

// ---------------- BN+ReLU on y + seq-mean -> f_v (no store of activated y) ----------------
__global__ void bn_y_kernel(const float* __restrict__ gamma, const float* __restrict__ beta)
{
    const int bt = blockIdx.x;
    const int n  = blockIdx.y;
    const int c  = threadIdx.x;
    const float s1 = g_cstats[(n * 512 + c) * 2];
    const float s2 = g_cstats[(n * 512 + c) * 2 + 1];
    const float inv_n = 1.f / 21504.f;
    const float mean  = s1 * inv_n;
    const float var   = s2 * inv_n - mean * mean;
    const float rstd  = rsqrtf(var + EPSF);
    const float sc = gamma[n * 512 + c] * rstd;
    const float sh = beta[n * 512 + c] - mean * sc;
    size_t base = ((size_t)n * 21504 + (size_t)bt * 21) * 512 + c;
    float accv = 0.f;
    #pragma unroll
    for (int s = 0; s < 21; ++s) {
        float v = g_y[base + (size_t)s * 512];
        accv += fmaxf(fmaf(v, sc, sh), 0.f);
    }
    g_fv[((size_t)bt * 12 + n) * 512 + c] = accv * (1.f / 21.f);
}

// ---------------- small prediction heads ----------------
__global__ void preds_kernel(const float* __restrict__ upW,  const float* __restrict__ upb,
                             const float* __restrict__ midW, const float* __restrict__ midb,
                             const float* __restrict__ d1W,  const float* __restrict__ d1b,
                             const float* __restrict__ d2W,  const float* __restrict__ d2b,
                             float* __restrict__ out)
{
    __shared__ float sm[4 * 512];
    const int bt = blockIdx.x;
    for (int i = threadIdx.x; i < 2048; i += blockDim.x)
        sm[i] = g_hmean[((size_t)(i >> 9) * 1024 + bt) * 512 + (i & 511)];
    __syncthreads();
    const int t = threadIdx.x;
    if (t < 42) {
        int r, j, nout;
        const float* Wp;
        const float* bp;
        float* op;
        if (t < 16)      { r = 0; j = t;      Wp = upW;  bp = upb;  op = out + (size_t)bt * 16;          nout = 16; }
        else if (t < 18) { r = 1; j = t - 16; Wp = midW; bp = midb; op = out + 16384 + (size_t)bt * 2;   nout = 2;  }
        else if (t < 26) { r = 2; j = t - 18; Wp = d1W;  bp = d1b;  op = out + 18432 + (size_t)bt * 8;   nout = 8;  }
        else             { r = 3; j = t - 26; Wp = d2W;  bp = d2b;  op = out + 26624 + (size_t)bt * 16;  nout = 16; }
        float accv = bp[j];
        const float* s = sm + r * 512;
        for (int c = 0; c < 512; ++c) accv += s[c] * Wp[c * nout + j];
        op[j] = accv;
    }
}

// ---------------- GAT: projections, attention, aggregation + residual ----------------
__global__ void gat_kernel(const float* __restrict__ adj_mask,
                           const float* __restrict__ al,
                           const float* __restrict__ ar)
{
    __shared__ float hs[12 * 512];
    __shared__ float alp[12], arp[12];
    __shared__ float att[144];
    const int bt = blockIdx.x;
    const float* hgb = g_hg + (size_t)bt * 12 * 512;
    for (int i = threadIdx.x; i < 6144; i += 256) hs[i] = hgb[i];
    __syncthreads();
    const int w = threadIdx.x >> 5, lane = threadIdx.x & 31;
    for (int d = w; d < 24; d += 8) {
        int node = d >> 1;
        const float* vec = (d & 1) ? ar : al;
        float s = 0.f;
        for (int c = lane; c < 512; c += 32) s += hs[node * 512 + c] * vec[c];
        #pragma unroll
        for (int o = 16; o; o >>= 1) s += __shfl_xor_sync(0xFFFFFFFFu, s, o);
        if (lane == 0) { if (d & 1) arp[node] = s; else alp[node] = s; }
    }
    __syncthreads();
    if (threadIdx.x < 144) {
        int i = threadIdx.x / 12, j = threadIdx.x % 12;
        float a = c_adj[threadIdx.x] * adj_mask[(size_t)bt * 144 + threadIdx.x] + (i == j ? 1.f : 0.f);
        float e = alp[i] + arp[j];
        e = (e > 0.f) ? e : 0.2f * e;
        att[threadIdx.x] = (a > 0.1f) ? e : -1e9f;
    }
    __syncthreads();
    if (threadIdx.x < 12) {
        int i = threadIdx.x;
        float mx = -1e30f;
        for (int j = 0; j < 12; ++j) mx = fmaxf(mx, att[i * 12 + j]);
        float tmp[12];
        float sum = 0.f;
        for (int j = 0; j < 12; ++j) { float ev = expf(att[i * 12 + j] - mx); tmp[j] = ev; sum += ev; }
        float invs = 1.f / sum;
        for (int j = 0; j < 12; ++j) att[i * 12 + j] = tmp[j] * invs;
    }
    __syncthreads();
    const float* fvb = g_fv + (size_t)bt * 12 * 512;
    float* gb = g_gat + (size_t)bt * 12 * 512;
    for (int idx = threadIdx.x; idx < 6144; idx += 256) {
        int n = idx >> 9, c = idx & 511;
        float s = fvb[idx];
        #pragma unroll
        for (int j = 0; j < 12; ++j) s += att[n * 12 + j] * hs[j * 512 + c];
        gb[idx] = s;
    }
}

// ---------------- depthwise temporal conv (k=5, pad=2) + BN statistics ----------------
__global__ void tconv_kernel(const float* __restrict__ W, const float* __restrict__ bias)
{
    const int bt = blockIdx.x;
    const int n  = blockIdx.y;
    const int b  = bt >> 5, t = bt & 31;
    const int c  = threadIdx.x;
    const float* wp = W + ((size_t)n * 512 + c) * 5;
    float v = bias[n * 512 + c];
    #pragma unroll
    for (int k = 0; k < 5; ++k) {
        int tt = t + k - 2;
        if (tt >= 0 && tt < 32)
            v += g_gat[(((size_t)(b * 32 + tt)) * 12 + n) * 512 + c] * wp[k];
    }
    g_v[((size_t)bt * 12 + n) * 512 + c] = v;

    // stats reduce (sum, sumsq) over the 512 channels of this (bt, n)
    float s = v, s2 = v * v;
    #pragma unroll
    for (int o = 16; o; o >>= 1) {
        s  += __shfl_xor_sync(0xFFFFFFFFu, s, o);
        s2 += __shfl_xor_sync(0xFFFFFFFFu, s2, o);
    }
    __shared__ float wsum[16], wsq[16];
    const int lane = c & 31, wrp = c >> 5;
    if (lane == 0) { wsum[wrp] = s; wsq[wrp] = s2; }
    __syncthreads();
    if (c == 0) {
        float a = 0.f, b2 = 0.f;
        #pragma unroll
        for (int i = 0; i < 16; ++i) { a += wsum[i]; b2 += wsq[i]; }
        atomicAdd(&g_tstats[n * 2],     a);
        atomicAdd(&g_tstats[n * 2 + 1], b2);
    }
}

// ---------------- final per-class BN + ReLU -> output ----------------
__global__ void tbn_kernel(const float* __restrict__ gamma, const float* __restrict__ beta,
                           float* __restrict__ out)
{
    const int bt = blockIdx.x;
    const int n  = blockIdx.y;
    const int c  = threadIdx.x;
    const float cnt = 1.f / (1024.f * 512.f);
    const float mean = g_tstats[n * 2] * cnt;
    const float var  = g_tstats[n * 2 + 1] * cnt - mean * mean;
    const float rstd = rsqrtf(var + EPSF);
    const float sc = gamma[n] * rstd;
    const float sh = beta[n] - mean * sc;
    size_t idx = ((size_t)bt * 12 + n) * 512 + c;
    out[43008 + idx] = fmaxf(fmaf(g_v[idx], sc, sh), 0.f);
}

// ---------------- launch ----------------
extern "C" void kernel_launch(void* const* d_in, const int* in_sizes, int n_in,
                              void* d_out, int out_size)
{
    const float* x            = (const float*)d_in[0];
    const float* adj_mask     = (const float*)d_in[1];
    const float* region_W     = (const float*)d_in[2];
    const float* region_b     = (const float*)d_in[3];
    const float* region_gamma = (const float*)d_in[4];
    const float* region_beta  = (const float*)d_in[5];
    const float* upfc_W  = (const float*)d_in[6];
    const float* upfc_b  = (const float*)d_in[7];
    const float* midfc_W = (const float*)d_in[8];
    const float* midfc_b = (const float*)d_in[9];
    const float* d1fc_W  = (const float*)d_in[10];
    const float* d1fc_b  = (const float*)d_in[11];
    const float* d2fc_W  = (const float*)d_in[12];
    const float* d2fc_b  = (const float*)d_in[13];
    const float* class_W     = (const float*)d_in[14];
    const float* class_b     = (const float*)d_in[15];
    const float* class_gamma = (const float*)d_in[16];
    const float* class_beta  = (const float*)d_in[17];
    const float* gat_W  = (const float*)d_in[18];
    const float* gat_al = (const float*)d_in[19];
    const float* gat_ar = (const float*)d_in[20];
    const float* tconv_W   = (const float*)d_in[21];
    const float* tconv_b   = (const float*)d_in[22];
    const float* tbn_gamma = (const float*)d_in[23];
    const float* tbn_beta  = (const float*)d_in[24];
    float* out = (float*)d_out;

    zero_stats_kernel<<<48, 256>>>();
    // region GEMMs: 4 x [21504, 512] = [21504, 512] @ [512, 512] (+bias, +stats)
    gemm_k<<<dim3(4, 168, 4), 256>>>(x, region_W, region_b, 21504, 0);
    bn_h_kernel<<<dim3(1024, 4), 512>>>(region_gamma, region_beta);
    preds_kernel<<<1024, 64>>>(upfc_W, upfc_b, midfc_W, midfc_b,
                               d1fc_W, d1fc_b, d2fc_W, d2fc_b, out);
    // class GEMMs: 12 x [21504, 512] @ [512, 512] (+bias, +stats)
    gemm_k<<<dim3(4, 168, 12), 256>>>(nullptr, class_W, class_b, 21504, 1);
    bn_y_kernel<<<dim3(1024, 12), 512>>>(class_gamma, class_beta);
    // GAT projection GEMM: [12288, 512] @ [512, 512]
    gemm_k<<<dim3(4, 96, 1), 256>>>(nullptr, gat_W, nullptr, 12288, 2);
    gat_kernel<<<1024, 256>>>(adj_mask, gat_al, gat_ar);
    tconv_kernel<<<dim3(1024, 12), 512>>>(tconv_W, tconv_b);
    tbn_kernel<<<dim3(1024, 12), 512>>>(tbn_gamma, tbn_beta, out);
}

// round 5
// speedup vs baseline: 2.1376x; 2.1376x over previous
#include <cuda_runtime.h>
#include <cstdint>

#define EPSF 1e-5f

// ---------------- scratch (static device globals; no allocation) ----------------
__device__ float g_h[(size_t)4 * 21504 * 512];      // region GEMM out; activated+tf32 in place
__device__ float g_y[(size_t)12 * 21504 * 512];     // class GEMM out (pre-BN)
__device__ float g_xr[(size_t)1024 * 49 * 512];     // tf32-rounded input
__device__ float g_wt[(size_t)17 * 512 * 512];      // transposed tf32-rounded weights
__device__ float g_hmean[(size_t)4 * 1024 * 512];   // seq-mean of activated h
__device__ float g_fv[(size_t)1024 * 12 * 512];     // f_v exact
__device__ float g_fvr[(size_t)1024 * 12 * 512];    // f_v tf32-rounded (GEMM operand)
__device__ float g_hg[(size_t)1024 * 12 * 512];     // GAT projection
__device__ float g_gat[(size_t)1024 * 12 * 512];    // GAT output
__device__ float g_v[(size_t)1024 * 12 * 512];      // temporal conv out (pre-BN)
__device__ float g_rstats[4 * 512 * 2];
__device__ float g_cstats[12 * 512 * 2];
__device__ float g_tstats[24];
__device__ float g_rsc[4 * 512], g_rsh[4 * 512];

__constant__ int c_sel[12]  = {0, 0, 0, 1, 0, 3, 2, 2, 2, 3, 3, 3};
__constant__ int c_start[4] = {0, 14, 28, 28};
__constant__ float c_adj[144] = {
    0,0,0,1,0,1,1,1,1,1,1,1,
    0,0,0,1,0,1,1,1,1,1,1,1,
    0,0,0,1,0,1,1,1,1,1,1,1,
    1,1,1,0,1,1,1,1,1,1,1,1,
    0,0,0,1,0,1,1,1,1,1,1,1,
    1,1,1,1,1,0,1,1,1,0,0,0,
    1,1,1,1,1,1,0,0,0,1,1,1,
    1,1,1,1,1,1,0,0,0,1,1,1,
    1,1,1,1,1,1,0,0,0,1,1,1,
    1,1,1,1,1,0,1,1,1,0,0,0,
    1,1,1,1,1,0,1,1,1,0,0,0,
    1,1,1,1,1,0,1,1,1,0,0,0
};

// ---------------- helpers ----------------
__device__ __forceinline__ uint32_t smem_u32(const void* p) {
    uint32_t a;
    asm("{ .reg .u64 t; cvta.to.shared.u64 t, %1; cvt.u32.u64 %0, t; }" : "=r"(a) : "l"(p));
    return a;
}
__device__ __forceinline__ float to_tf32(float v) {
    float r;
    asm("cvt.rna.tf32.f32 %0, %1;" : "=f"(r) : "f"(v));
    return r;
}
#define CP_ASYNC16(dst, src) \
    asm volatile("cp.async.ca.shared.global [%0], [%1], 16;" :: "r"(dst), "l"(src) : "memory")
#define CP_COMMIT() asm volatile("cp.async.commit_group;" ::: "memory")
#define CP_WAIT1()  asm volatile("cp.async.wait_group 1;" ::: "memory")
#define CP_WAIT0()  asm volatile("cp.async.wait_group 0;" ::: "memory")

#define MMA_TF32(D, A, B) \
    asm volatile("mma.sync.aligned.m16n8k8.row.col.f32.tf32.tf32.f32 " \
        "{%0,%1,%2,%3}, {%4,%5,%6,%7}, {%8,%9}, {%0,%1,%2,%3};" \
        : "+f"((D)[0]), "+f"((D)[1]), "+f"((D)[2]), "+f"((D)[3]) \
        : "r"((A)[0]), "r"((A)[1]), "r"((A)[2]), "r"((A)[3]), \
          "r"((B)[0]), "r"((B)[1]))

// ---------------- stats zeroing ----------------
__global__ void zero_stats_kernel() {
    int i = blockIdx.x * blockDim.x + threadIdx.x;
    if (i < 4 * 512 * 2)  g_rstats[i] = 0.f;
    if (i < 12 * 512 * 2) g_cstats[i] = 0.f;
    if (i < 24)           g_tstats[i] = 0.f;
}

// ---------------- round input to tf32 ----------------
__global__ void round_x_kernel(const float* __restrict__ x) {
    size_t i = ((size_t)blockIdx.x * blockDim.x + threadIdx.x) * 4;
    float4 v = *(const float4*)(x + i);
    v.x = to_tf32(v.x); v.y = to_tf32(v.y); v.z = to_tf32(v.z); v.w = to_tf32(v.w);
    *(float4*)(g_xr + i) = v;
}

// ---------------- weight transpose + tf32 rounding (17 matrices) ----------------
__global__ void transpose_wt(const float* __restrict__ rW,
                             const float* __restrict__ cW,
                             const float* __restrict__ gW) {
    __shared__ float t[32][33];
    const int z = blockIdx.z;
    const float* src = (z < 4) ? rW + (size_t)z * 262144
                     : (z < 16) ? cW + (size_t)(z - 4) * 262144 : gW;
    float* dst = g_wt + (size_t)z * 262144;
    const int tx = threadIdx.x, ty = threadIdx.y;
    const int x = blockIdx.x * 32 + tx;
    const int y = blockIdx.y * 32 + ty;
    #pragma unroll
    for (int i = 0; i < 32; i += 8)
        t[ty + i][tx] = to_tf32(src[(size_t)(y + i) * 512 + x]);
    __syncthreads();
    const int x2 = blockIdx.y * 32 + tx;
    const int y2 = blockIdx.x * 32 + ty;
    #pragma unroll
    for (int i = 0; i < 32; i += 8)
        dst[(size_t)(y2 + i) * 512 + x2] = t[tx][ty + i];
}

// ================= tf32 mma.sync GEMM: 128x128 tile, K=512, fused bias + BN stats =================
// mode 0: A = g_xr (region row gather),  Y = g_h,  stats = g_rstats
// mode 1: A = g_h  (activated, rounded), Y = g_y,  stats = g_cstats
// mode 2: A = g_fvr,                     Y = g_hg, no stats/bias
#define SMEM_DYN 67584
__global__ void __launch_bounds__(256) gemm_s(const float* __restrict__ bias, int M, int mode)
{
    extern __shared__ float sm[];
    float* As = sm;                 // [2][128*20]
    float* Bs = sm + 2 * 2560;      // [2][128*20]
    float* stage = sm;              // reuse after mainloop: [128][132]
    __shared__ float s_bias[128], s_cs1[128], s_cs2[128];

    const int tid = threadIdx.x;
    const int w = tid >> 5, l = tid & 31;
    const int wm = w >> 1, wn = w & 1;     // warp tile: rows wm*32, cols wn*64
    const int g = l >> 2, t = l & 3;
    const int z  = blockIdx.z;
    const int n0 = blockIdx.x * 128;
    const int m0 = blockIdx.y * 128;

    const float* A;
    float* Y;
    if (mode == 0)      { A = g_xr; Y = g_h; }
    else if (mode == 1) { A = g_h;  Y = g_y; }
    else                { A = g_fvr; Y = g_hg; }

    if (tid < 128) {
        s_bias[tid] = bias ? bias[(size_t)z * 512 + n0 + tid] : 0.f;
        s_cs1[tid] = 0.f;
        s_cs2[tid] = 0.f;
    }

    // ---- loader pointers: this thread loads 2 A-chunks + 2 B-chunks (16B each) per stage
    const int lrow = tid >> 2;      // 0..63
    const int quad = tid & 3;       // 16B chunk within 64B row-slab
    const float *ga0, *ga1;
    {
        int mA0 = m0 + lrow, mA1 = mA0 + 64;
        if (mode == 0) {
            int bt0 = mA0 / 21, s0 = mA0 - bt0 * 21;
            int bt1 = mA1 / 21, s1 = mA1 - bt1 * 21;
            ga0 = A + ((size_t)bt0 * 49 + c_start[z] + s0) * 512 + quad * 4;
            ga1 = A + ((size_t)bt1 * 49 + c_start[z] + s1) * 512 + quad * 4;
        } else if (mode == 1) {
            int sel = c_sel[z];
            ga0 = A + ((size_t)sel * 21504 + mA0) * 512 + quad * 4;
            ga1 = A + ((size_t)sel * 21504 + mA1) * 512 + quad * 4;
        } else {
            ga0 = A + (size_t)mA0 * 512 + quad * 4;
            ga1 = A + (size_t)mA1 * 512 + quad * 4;
        }
    }
    const int zw = (mode == 0) ? z : (mode == 1) ? 4 + z : 16;
    const float* gb0 = g_wt + (size_t)zw * 262144 + (size_t)(n0 + lrow) * 512 + quad * 4;
    const float* gb1 = gb0 + (size_t)64 * 512;

    const uint32_t s_as = smem_u32(As);
    const uint32_t s_bs = smem_u32(Bs);
    const uint32_t dstA0 = s_as + lrow * 80 + quad * 16;
    const uint32_t dstA1 = dstA0 + 64 * 80;
    const uint32_t dstB0 = s_bs + lrow * 80 + quad * 16;
    const uint32_t dstB1 = dstB0 + 64 * 80;

    float d[2][8][4];
    #pragma unroll
    for (int mf = 0; mf < 2; ++mf)
        #pragma unroll
        for (int nf = 0; nf < 8; ++nf)
            #pragma unroll
            for (int q = 0; q < 4; ++q) d[mf][nf][q] = 0.f;

    // prologue: stage 0
    CP_ASYNC16(dstA0, ga0);
    CP_ASYNC16(dstA1, ga1);
    CP_ASYNC16(dstB0, gb0);
    CP_ASYNC16(dstB1, gb1);
    CP_COMMIT();

    for (int kt = 0; kt < 32; ++kt) {
        const int buf = kt & 1;
        if (kt < 31) {
            const int k1 = (kt + 1) * 16;
            const uint32_t bo = (buf ^ 1) * 10240;
            CP_ASYNC16(dstA0 + bo, ga0 + k1);
            CP_ASYNC16(dstA1 + bo, ga1 + k1);
            CP_ASYNC16(dstB0 + bo, gb0 + k1);
            CP_ASYNC16(dstB1 + bo, gb1 + k1);
            CP_COMMIT();
            CP_WAIT1();
        } else {
            CP_WAIT0();
        }
        __syncthreads();
        const float* Ab = As + buf * 2560;
        const float* Bb = Bs + buf * 2560;
        #pragma unroll
        for (int ks = 0; ks < 16; ks += 8) {
            uint32_t af[2][4], bf[8][2];
            #pragma unroll
            for (int mf = 0; mf < 2; ++mf) {
                int r0 = wm * 32 + mf * 16 + g;
                af[mf][0] = __float_as_uint(Ab[r0 * 20 + ks + t]);
                af[mf][1] = __float_as_uint(Ab[(r0 + 8) * 20 + ks + t]);
                af[mf][2] = __float_as_uint(Ab[r0 * 20 + ks + t + 4]);
                af[mf][3] = __float_as_uint(Ab[(r0 + 8) * 20 + ks + t + 4]);
            }
            #pragma unroll
            for (int nf = 0; nf < 8; ++nf) {
                int nn = wn * 64 + nf * 8 + g;
                bf[nf][0] = __float_as_uint(Bb[nn * 20 + ks + t]);
                bf[nf][1] = __float_as_uint(Bb[nn * 20 + ks + t + 4]);
            }
            #pragma unroll
            for (int mf = 0; mf < 2; ++mf)
                #pragma unroll
                for (int nf = 0; nf < 8; ++nf)
                    MMA_TF32(d[mf][nf], af[mf], bf[nf]);
        }
        __syncthreads();
    }

    // ---- epilogue: bias, stage to SMEM, column stats via shfl ----
    float cs[16], cq[16];
    #pragma unroll
    for (int i = 0; i < 16; ++i) { cs[i] = 0.f; cq[i] = 0.f; }
    #pragma unroll
    for (int mf = 0; mf < 2; ++mf) {
        #pragma unroll
        for (int nf = 0; nf < 8; ++nf) {
            int colb = wn * 64 + nf * 8 + 2 * t;
            float b0 = s_bias[colb], b1 = s_bias[colb + 1];
            int r0 = wm * 32 + mf * 16 + g;
            float v00 = d[mf][nf][0] + b0;
            float v01 = d[mf][nf][1] + b1;
            float v10 = d[mf][nf][2] + b0;
            float v11 = d[mf][nf][3] + b1;
            stage[r0 * 132 + colb]       = v00;
            stage[r0 * 132 + colb + 1]   = v01;
            stage[(r0 + 8) * 132 + colb]     = v10;
            stage[(r0 + 8) * 132 + colb + 1] = v11;
            cs[nf * 2]     += v00 + v10;
            cq[nf * 2]     += v00 * v00 + v10 * v10;
            cs[nf * 2 + 1] += v01 + v11;
            cq[nf * 2 + 1] += v01 * v01 + v11 * v11;
        }
    }
    if (mode != 2) {
        #pragma unroll
        for (int i = 0; i < 16; ++i) {
            #pragma unroll
            for (int msk = 4; msk <= 16; msk <<= 1) {
                cs[i] += __shfl_xor_sync(0xFFFFFFFFu, cs[i], msk);
                cq[i] += __shfl_xor_sync(0xFFFFFFFFu, cq[i], msk);
            }
        }
        if (l < 4) {
            #pragma unroll
            for (int nf = 0; nf < 8; ++nf) {
                int col = wn * 64 + nf * 8 + 2 * l;
                atomicAdd(&s_cs1[col],     cs[nf * 2]);
                atomicAdd(&s_cs2[col],     cq[nf * 2]);
                atomicAdd(&s_cs1[col + 1], cs[nf * 2 + 1]);
                atomicAdd(&s_cs2[col + 1], cq[nf * 2 + 1]);
            }
        }
    }
    __syncthreads();

    // coalesced readout: one thread = half a row
    {
        const int r = tid >> 1, hh = tid & 1;
        float* yrow = Y + ((size_t)z * M + m0 + r) * 512 + n0 + hh * 64;
        const float* srow = stage + r * 132 + hh * 64;
        #pragma unroll
        for (int q = 0; q < 16; ++q)
            *(float4*)(yrow + q * 4) = *(const float4*)(srow + q * 4);
    }
    if (mode != 2 && tid < 128) {
        float* stats = (mode == 0) ? g_rstats : g_cstats;
        atomicAdd(&stats[((size_t)z * 512 + n0 + tid) * 2],     s_cs1[tid]);
        atomicAdd(&stats[((size_t)z * 512 + n0 + tid) * 2 + 1], s_cs2[tid]);
    }
}

// ---------------- region BN finalize ----------------
__global__ void finalize_rs(const float* __restrict__ gamma, const float* __restrict__ beta) {
    int i = blockIdx.x * 512 + threadIdx.x;
    float s1 = g_rstats[i * 2], s2 = g_rstats[i * 2 + 1];
    float mean = s1 * (1.f / 21504.f);
    float var  = s2 * (1.f / 21504.f) - mean * mean;
    float rstd = rsqrtf(var + EPSF);
    float sc = gamma[i] * rstd;
    g_rsc[i] = sc;
    g_rsh[i] = beta[i] - mean * sc;
}

// ---------------- activate h in place (tf32-rounded) + seq-mean ----------------
__global__ void hmean_kernel() {
    const int bt = blockIdx.x, r = blockIdx.y, c = threadIdx.x;
    const float sc = g_rsc[r * 512 + c];
    const float sh = g_rsh[r * 512 + c];
    size_t base = ((size_t)r * 21504 + (size_t)bt * 21) * 512 + c;
    float accv = 0.f;
    #pragma unroll
    for (int s = 0; s < 21; ++s) {
        float v = fmaxf(fmaf(g_h[base + (size_t)s * 512], sc, sh), 0.f);
        accv += v;
        g_h[base + (size_t)s * 512] = to_tf32(v);
    }
    g_hmean[((size_t)r * 1024 + bt) * 512 + c] = accv * (1.f / 21.f);
}

// ---------------- BN+ReLU on y + seq-mean -> f_v (exact + rounded) ----------------
__global__ void bn_y_kernel(const float* __restrict__ gamma, const float* __restrict__ beta) {
    const int bt = blockIdx.x, n = blockIdx.y, c = threadIdx.x;
    const float s1 = g_cstats[(n * 512 + c) * 2];
    const float s2 = g_cstats[(n * 512 + c) * 2 + 1];
    const float mean = s1 * (1.f / 21504.f);
    const float var  = s2 * (1.f / 21504.f) - mean * mean;
    const float rstd = rsqrtf(var + EPSF);
    const float sc = gamma[n * 512 + c] * rstd;
    const float sh = beta[n * 512 + c] - mean * sc;
    size_t base = ((size_t)n * 21504 + (size_t)bt * 21) * 512 + c;
    float accv = 0.f;
    #pragma unroll
    for (int s = 0; s < 21; ++s)
        accv += fmaxf(fmaf(g_y[base + (size_t)s * 512], sc, sh), 0.f);
    float fv = accv * (1.f / 21.f);
    g_fv[((size_t)bt * 12 + n) * 512 + c]  = fv;
    g_fvr[((size_t)bt * 12 + n) * 512 + c] = to_tf32(fv);
}

// ---------------- prediction heads ----------------
__global__ void preds_kernel(const float* __restrict__ upW,  const float* __restrict__ upb,
                             const float* __restrict__ midW, const float* __restrict__ midb,
                             const float* __restrict__ d1W,  const float* __restrict__ d1b,
                             const float* __restrict__ d2W,  const float* __restrict__ d2b,
                             float* __restrict__ out)
{
    __shared__ float smh[2048];
    const int bt = blockIdx.x;
    for (int i = threadIdx.x; i < 2048; i += 256)
        smh[i] = g_hmean[((size_t)(i >> 9) * 1024 + bt) * 512 + (i & 511)];
    __syncthreads();
    const int w = threadIdx.x >> 5, l = threadIdx.x & 31;
    for (int o = w; o < 42; o += 8) {
        int r, j, nout;
        const float* Wp;
        const float* bp;
        float* op;
        if (o < 16)      { r = 0; j = o;      Wp = upW;  bp = upb;  op = out + (size_t)bt * 16;         nout = 16; }
        else if (o < 18) { r = 1; j = o - 16; Wp = midW; bp = midb; op = out + 16384 + (size_t)bt * 2;  nout = 2;  }
        else if (o < 26) { r = 2; j = o - 18; Wp = d1W;  bp = d1b;  op = out + 18432 + (size_t)bt * 8;  nout = 8;  }
        else             { r = 3; j = o - 26; Wp = d2W;  bp = d2b;  op = out + 26624 + (size_t)bt * 16; nout = 16; }
        float a = 0.f;
        for (int c = l; c < 512; c += 32) a += smh[r * 512 + c] * Wp[c * nout + j];
        #pragma unroll
        for (int off = 16; off; off >>= 1) a += __shfl_xor_sync(0xFFFFFFFFu, a, off);
        if (l == 0) op[j] = a + bp[j];
    }
}

// ---------------- GAT ----------------
__global__ void gat_kernel(const float* __restrict__ adj_mask,
                           const float* __restrict__ al,
                           const float* __restrict__ ar)
{
    __shared__ float hs[12 * 512];
    __shared__ float alp[12], arp[12];
    __shared__ float att[144];
    const int bt = blockIdx.x;
    const float* hgb = g_hg + (size_t)bt * 12 * 512;
    for (int i = threadIdx.x; i < 6144; i += 256) hs[i] = hgb[i];
    __syncthreads();
    const int w = threadIdx.x >> 5, lane = threadIdx.x & 31;
    for (int dd = w; dd < 24; dd += 8) {
        int node = dd >> 1;
        const float* vec = (dd & 1) ? ar : al;
        float s = 0.f;
        for (int c = lane; c < 512; c += 32) s += hs[node * 512 + c] * vec[c];
        #pragma unroll
        for (int o = 16; o; o >>= 1) s += __shfl_xor_sync(0xFFFFFFFFu, s, o);
        if (lane == 0) { if (dd & 1) arp[node] = s; else alp[node] = s; }
    }
    __syncthreads();
    if (threadIdx.x < 144) {
        int i = threadIdx.x / 12, j = threadIdx.x % 12;
        float a = c_adj[threadIdx.x] * adj_mask[(size_t)bt * 144 + threadIdx.x] + (i == j ? 1.f : 0.f);
        float e = alp[i] + arp[j];
        e = (e > 0.f) ? e : 0.2f * e;
        att[threadIdx.x] = (a > 0.1f) ? e : -1e9f;
    }
    __syncthreads();
    if (threadIdx.x < 12) {
        int i = threadIdx.x;
        float mx = -1e30f;
        for (int j = 0; j < 12; ++j) mx = fmaxf(mx, att[i * 12 + j]);
        float tmp[12];
        float sum = 0.f;
        for (int j = 0; j < 12; ++j) { float ev = expf(att[i * 12 + j] - mx); tmp[j] = ev; sum += ev; }
        float invs = 1.f / sum;
        for (int j = 0; j < 12; ++j) att[i * 12 + j] = tmp[j] * invs;
    }
    __syncthreads();
    const float* fvb = g_fv + (size_t)bt * 12 * 512;
    float* gb = g_gat + (size_t)bt * 12 * 512;
    for (int idx = threadIdx.x; idx < 6144; idx += 256) {
        int n = idx >> 9, c = idx & 511;
        float s = fvb[idx];
        #pragma unroll
        for (int j = 0; j < 12; ++j) s += att[n * 12 + j] * hs[j * 512 + c];
        gb[idx] = s;
    }
}

// ---------------- depthwise temporal conv + BN stats ----------------
__global__ void tconv_kernel(const float* __restrict__ W, const float* __restrict__ bias) {
    const int bt = blockIdx.x, n = blockIdx.y;
    const int b = bt >> 5, t = bt & 31;
    const int c = threadIdx.x;
    const float* wp = W + ((size_t)n * 512 + c) * 5;
    float v = bias[n * 512 + c];
    #pragma unroll
    for (int k = 0; k < 5; ++k) {
        int tt = t + k - 2;
        if (tt >= 0 && tt < 32)
            v += g_gat[(((size_t)(b * 32 + tt)) * 12 + n) * 512 + c] * wp[k];
    }
    g_v[((size_t)bt * 12 + n) * 512 + c] = v;
    float s = v, s2 = v * v;
    #pragma unroll
    for (int o = 16; o; o >>= 1) {
        s  += __shfl_xor_sync(0xFFFFFFFFu, s, o);
        s2 += __shfl_xor_sync(0xFFFFFFFFu, s2, o);
    }
    __shared__ float wsum[16], wsq[16];
    const int lane = c & 31, wrp = c >> 5;
    if (lane == 0) { wsum[wrp] = s; wsq[wrp] = s2; }
    __syncthreads();
    if (c == 0) {
        float a = 0.f, b2 = 0.f;
        #pragma unroll
        for (int i = 0; i < 16; ++i) { a += wsum[i]; b2 += wsq[i]; }
        atomicAdd(&g_tstats[n * 2],     a);
        atomicAdd(&g_tstats[n * 2 + 1], b2);
    }
}

// ---------------- final per-class BN + ReLU ----------------
__global__ void tbn_kernel(const float* __restrict__ gamma, const float* __restrict__ beta,
                           float* __restrict__ out) {
    const int bt = blockIdx.x, n = blockIdx.y, c = threadIdx.x;
    const float cnt = 1.f / (1024.f * 512.f);
    const float mean = g_tstats[n * 2] * cnt;
    const float var  = g_tstats[n * 2 + 1] * cnt - mean * mean;
    const float rstd = rsqrtf(var + EPSF);
    const float sc = gamma[n] * rstd;
    const float sh = beta[n] - mean * sc;
    size_t idx = ((size_t)bt * 12 + n) * 512 + c;
    out[43008 + idx] = fmaxf(fmaf(g_v[idx], sc, sh), 0.f);
}

// ---------------- launch ----------------
extern "C" void kernel_launch(void* const* d_in, const int* in_sizes, int n_in,
                              void* d_out, int out_size)
{
    const float* x            = (const float*)d_in[0];
    const float* adj_mask     = (const float*)d_in[1];
    const float* region_W     = (const float*)d_in[2];
    const float* region_b     = (const float*)d_in[3];
    const float* region_gamma = (const float*)d_in[4];
    const float* region_beta  = (const float*)d_in[5];
    const float* upfc_W  = (const float*)d_in[6];
    const float* upfc_b  = (const float*)d_in[7];
    const float* midfc_W = (const float*)d_in[8];
    const float* midfc_b = (const float*)d_in[9];
    const float* d1fc_W  = (const float*)d_in[10];
    const float* d1fc_b  = (const float*)d_in[11];
    const float* d2fc_W  = (const float*)d_in[12];
    const float* d2fc_b  = (const float*)d_in[13];
    const float* class_W     = (const float*)d_in[14];
    const float* class_b     = (const float*)d_in[15];
    const float* class_gamma = (const float*)d_in[16];
    const float* class_beta  = (const float*)d_in[17];
    const float* gat_W  = (const float*)d_in[18];
    const float* gat_al = (const float*)d_in[19];
    const float* gat_ar = (const float*)d_in[20];
    const float* tconv_W   = (const float*)d_in[21];
    const float* tconv_b   = (const float*)d_in[22];
    const float* tbn_gamma = (const float*)d_in[23];
    const float* tbn_beta  = (const float*)d_in[24];
    float* out = (float*)d_out;

    cudaFuncSetAttribute(gemm_s, cudaFuncAttributeMaxDynamicSharedMemorySize, SMEM_DYN);

    zero_stats_kernel<<<48, 256>>>();
    round_x_kernel<<<25088, 256>>>(x);
    transpose_wt<<<dim3(16, 16, 17), dim3(32, 8)>>>(region_W, class_W, gat_W);
    gemm_s<<<dim3(4, 168, 4), 256, SMEM_DYN>>>(region_b, 21504, 0);
    finalize_rs<<<4, 512>>>(region_gamma, region_beta);
    hmean_kernel<<<dim3(1024, 4), 512>>>();
    preds_kernel<<<1024, 256>>>(upfc_W, upfc_b, midfc_W, midfc_b,
                                d1fc_W, d1fc_b, d2fc_W, d2fc_b, out);
    gemm_s<<<dim3(4, 168, 12), 256, SMEM_DYN>>>(class_b, 21504, 1);
    bn_y_kernel<<<dim3(1024, 12), 512>>>(class_gamma, class_beta);
    gemm_s<<<dim3(4, 96, 1), 256, SMEM_DYN>>>(nullptr, 12288, 2);
    gat_kernel<<<1024, 256>>>(adj_mask, gat_al, gat_ar);
    tconv_kernel<<<dim3(1024, 12), 512>>>(tconv_W, tconv_b);
    tbn_kernel<<<dim3(1024, 12), 512>>>(tbn_gamma, tbn_beta, out);
}

// round 7
// speedup vs baseline: 2.1950x; 1.0269x over previous
#include <cuda_runtime.h>
#include <cstdint>

#define EPSF 1e-5f

// ---------------- scratch (static device globals; no allocation) ----------------
__device__ float g_h[(size_t)4 * 21504 * 512];      // region GEMM out (raw pre-BN)
__device__ float g_y[(size_t)12 * 21504 * 512];     // class GEMM out (pre-BN)
__device__ float g_wt[(size_t)17 * 512 * 512];      // transposed tf32-rounded weights
__device__ float g_hmean[(size_t)4 * 1024 * 512];   // seq-mean of activated h
__device__ float g_fv[(size_t)1024 * 12 * 512];     // f_v
__device__ float g_hg[(size_t)1024 * 12 * 512];     // GAT projection
__device__ float g_gat[(size_t)1024 * 12 * 512];    // GAT output
__device__ float g_v[(size_t)1024 * 12 * 512];      // temporal conv out (pre-BN)
__device__ float g_rstats[4 * 512 * 2];
__device__ float g_cstats[12 * 512 * 2];
__device__ float g_tstats[24];
__device__ float g_rsc[4 * 512], g_rsh[4 * 512];

__constant__ int c_sel[12]  = {0, 0, 0, 1, 0, 3, 2, 2, 2, 3, 3, 3};
__constant__ int c_start[4] = {0, 14, 28, 28};
__constant__ float c_adj[144] = {
    0,0,0,1,0,1,1,1,1,1,1,1,
    0,0,0,1,0,1,1,1,1,1,1,1,
    0,0,0,1,0,1,1,1,1,1,1,1,
    1,1,1,0,1,1,1,1,1,1,1,1,
    0,0,0,1,0,1,1,1,1,1,1,1,
    1,1,1,1,1,0,1,1,1,0,0,0,
    1,1,1,1,1,1,0,0,0,1,1,1,
    1,1,1,1,1,1,0,0,0,1,1,1,
    1,1,1,1,1,1,0,0,0,1,1,1,
    1,1,1,1,1,0,1,1,1,0,0,0,
    1,1,1,1,1,0,1,1,1,0,0,0,
    1,1,1,1,1,0,1,1,1,0,0,0
};

// ---------------- helpers ----------------
__device__ __forceinline__ uint32_t smem_u32(const void* p) {
    uint32_t a;
    asm("{ .reg .u64 t; cvta.to.shared.u64 t, %1; cvt.u32.u64 %0, t; }" : "=r"(a) : "l"(p));
    return a;
}
__device__ __forceinline__ float to_tf32(float v) {
    float r;
    asm("cvt.rna.tf32.f32 %0, %1;" : "=f"(r) : "f"(v));
    return r;
}
#define CP_ASYNC16(dst, src) \
    asm volatile("cp.async.ca.shared.global [%0], [%1], 16;" :: "r"(dst), "l"(src) : "memory")
#define CP_COMMIT() asm volatile("cp.async.commit_group;" ::: "memory")
#define CP_WAIT0()  asm volatile("cp.async.wait_group 0;" ::: "memory")

#define MMA_TF32(D, A, B) \
    asm volatile("mma.sync.aligned.m16n8k8.row.col.f32.tf32.tf32.f32 " \
        "{%0,%1,%2,%3}, {%4,%5,%6,%7}, {%8,%9}, {%0,%1,%2,%3};" \
        : "+f"((D)[0]), "+f"((D)[1]), "+f"((D)[2]), "+f"((D)[3]) \
        : "r"((A)[0]), "r"((A)[1]), "r"((A)[2]), "r"((A)[3]), \
          "r"((B)[0]), "r"((B)[1]))

// ---------------- stats zeroing ----------------
__global__ void zero_stats_kernel() {
    int i = blockIdx.x * blockDim.x + threadIdx.x;
    if (i < 4 * 512 * 2)  g_rstats[i] = 0.f;
    if (i < 12 * 512 * 2) g_cstats[i] = 0.f;
    if (i < 24)           g_tstats[i] = 0.f;
}

// ---------------- weight transpose + tf32 rounding (17 matrices) ----------------
__global__ void transpose_wt(const float* __restrict__ rW,
                             const float* __restrict__ cW,
                             const float* __restrict__ gW) {
    __shared__ float t[32][33];
    const int z = blockIdx.z;
    const float* src = (z < 4) ? rW + (size_t)z * 262144
                     : (z < 16) ? cW + (size_t)(z - 4) * 262144 : gW;
    float* dst = g_wt + (size_t)z * 262144;
    const int tx = threadIdx.x, ty = threadIdx.y;
    const int x = blockIdx.x * 32 + tx;
    const int y = blockIdx.y * 32 + ty;
    #pragma unroll
    for (int i = 0; i < 32; i += 8)
        t[ty + i][tx] = to_tf32(src[(size_t)(y + i) * 512 + x]);
    __syncthreads();
    const int x2 = blockIdx.y * 32 + tx;
    const int y2 = blockIdx.x * 32 + ty;
    #pragma unroll
    for (int i = 0; i < 32; i += 8)
        dst[(size_t)(y2 + i) * 512 + x2] = t[tx][ty + i];
}

// ================= tf32 mma.sync GEMM v2: 128x128 tile, 4 warps x (64x64) =================
// mode 0: A = x (region gather, tf32 round in loader),      Y = g_h,  stats = g_rstats
// mode 1: A = relu(affine(g_h)) rounded in loader,          Y = g_y,  stats = g_cstats
// mode 2: A = g_fv rounded in loader,                       Y = g_hg, no stats/bias
#define SMEM_DYN 67584
__global__ void __launch_bounds__(128) gemm_s(const float* __restrict__ A_ext,
                                              const float* __restrict__ bias, int M, int mode)
{
    extern __shared__ float sm[];
    float* As = sm;                 // [2][128*20]  (buffer stride 2560 floats)
    float* Bs = sm + 2 * 2560;      // [2][128*20]
    float* stage = sm;              // epilogue reuse: [128][132]
    __shared__ float s_bias[128], s_cs1[128], s_cs2[128];
    __shared__ float s_sc[512], s_sh[512];

    const int tid = threadIdx.x;
    const int w = tid >> 5, l = tid & 31;
    const int wm = w >> 1, wn = w & 1;     // warp tile: rows wm*64, cols wn*64
    const int g = l >> 2, t = l & 3;
    const int z  = blockIdx.z;
    const int n0 = blockIdx.x * 128;
    const int m0 = blockIdx.y * 128;

    const float* A;
    float* Y;
    int sel = 0;
    if (mode == 0)      { A = A_ext; Y = g_h; }
    else if (mode == 1) { A = g_h;   Y = g_y; sel = c_sel[z]; }
    else                { A = g_fv;  Y = g_hg; }

    if (tid < 128) {
        s_bias[tid] = bias ? bias[(size_t)z * 512 + n0 + tid] : 0.f;
        s_cs1[tid] = 0.f;
        s_cs2[tid] = 0.f;
    }
    if (mode == 1) {
        *(float4*)&s_sc[tid * 4] = *(const float4*)&g_rsc[sel * 512 + tid * 4];
        *(float4*)&s_sh[tid * 4] = *(const float4*)&g_rsh[sel * 512 + tid * 4];
    }

    // ---- loader: thread covers rows lrow+{0,32,64,96}, 16B k-chunk quad
    const int lrow = tid >> 2;
    const int quad = tid & 3;
    const float* gaP[4];
    const float* gbP[4];
    #pragma unroll
    for (int i = 0; i < 4; ++i) {
        int m = m0 + lrow + 32 * i;
        if (mode == 0) {
            int bt = m / 21, s = m - bt * 21;
            gaP[i] = A + ((size_t)bt * 49 + c_start[z] + s) * 512 + quad * 4;
        } else if (mode == 1) {
            gaP[i] = A + ((size_t)sel * 21504 + m) * 512 + quad * 4;
        } else {
            gaP[i] = A + (size_t)m * 512 + quad * 4;
        }
        int zw = (mode == 0) ? z : (mode == 1) ? 4 + z : 16;
        gbP[i] = g_wt + (size_t)zw * 262144 + (size_t)(n0 + lrow + 32 * i) * 512 + quad * 4;
    }
    const uint32_t s_as = smem_u32(As);
    const uint32_t s_bs = smem_u32(Bs);
    const uint32_t stB = s_bs + lrow * 80 + quad * 16;
    const int aoff = lrow * 20 + quad * 4;   // float offset within an A buffer

    float d[4][8][4];
    #pragma unroll
    for (int mf = 0; mf < 4; ++mf)
        #pragma unroll
        for (int nf = 0; nf < 8; ++nf)
            #pragma unroll
            for (int q = 0; q < 4; ++q) d[mf][nf][q] = 0.f;

    __syncthreads();   // s_sc/s_sh ready before loader transform

    // transform helper applied to a float4 by mode (k = channel index of A column)
    auto xf = [&](float4 v, int kt) -> float4 {
        if (mode == 1) {
            int k = kt * 16 + quad * 4;
            float4 sc = *(const float4*)&s_sc[k];
            float4 sh = *(const float4*)&s_sh[k];
            v.x = fmaxf(fmaf(v.x, sc.x, sh.x), 0.f);
            v.y = fmaxf(fmaf(v.y, sc.y, sh.y), 0.f);
            v.z = fmaxf(fmaf(v.z, sc.z, sh.z), 0.f);
            v.w = fmaxf(fmaf(v.w, sc.w, sh.w), 0.f);
        }
        v.x = to_tf32(v.x); v.y = to_tf32(v.y);
        v.z = to_tf32(v.z); v.w = to_tf32(v.w);
        return v;
    };

    // prologue: stage 0
    {
        float4 a0 = *(const float4*)gaP[0];
        float4 a1 = *(const float4*)gaP[1];
        float4 a2 = *(const float4*)gaP[2];
        float4 a3 = *(const float4*)gaP[3];
        #pragma unroll
        for (int i = 0; i < 4; ++i) CP_ASYNC16(stB + i * 2560, gbP[i]);
        CP_COMMIT();
        float* Ad = As + aoff;
        *(float4*)(Ad)        = xf(a0, 0);
        *(float4*)(Ad + 640)  = xf(a1, 0);
        *(float4*)(Ad + 1280) = xf(a2, 0);
        *(float4*)(Ad + 1920) = xf(a3, 0);
        CP_WAIT0();
    }
    __syncthreads();

    for (int kt = 0; kt < 32; ++kt) {
        const int buf = kt & 1;
        float4 a0, a1, a2, a3;
        if (kt < 31) {
            const int k1 = (kt + 1) * 16;
            a0 = *(const float4*)(gaP[0] + k1);
            a1 = *(const float4*)(gaP[1] + k1);
            a2 = *(const float4*)(gaP[2] + k1);
            a3 = *(const float4*)(gaP[3] + k1);
            const uint32_t bo = (buf ^ 1) * 10240;   // bytes: buffer stride 2560 floats
            #pragma unroll
            for (int i = 0; i < 4; ++i) CP_ASYNC16(stB + bo + i * 2560, gbP[i] + k1);
            CP_COMMIT();
        }
        const float* Ab = As + buf * 2560;
        const float* Bb = Bs + buf * 2560;
        #pragma unroll
        for (int ks = 0; ks < 16; ks += 8) {
            uint32_t af[4][4], bf[8][2];
            #pragma unroll
            for (int mf = 0; mf < 4; ++mf) {
                int r0 = wm * 64 + mf * 16 + g;
                af[mf][0] = __float_as_uint(Ab[r0 * 20 + ks + t]);
                af[mf][1] = __float_as_uint(Ab[(r0 + 8) * 20 + ks + t]);
                af[mf][2] = __float_as_uint(Ab[r0 * 20 + ks + t + 4]);
                af[mf][3] = __float_as_uint(Ab[(r0 + 8) * 20 + ks + t + 4]);
            }
            #pragma unroll
            for (int nf = 0; nf < 8; ++nf) {
                int nn = wn * 64 + nf * 8 + g;
                bf[nf][0] = __float_as_uint(Bb[nn * 20 + ks + t]);
                bf[nf][1] = __float_as_uint(Bb[nn * 20 + ks + t + 4]);
            }
            #pragma unroll
            for (int mf = 0; mf < 4; ++mf)
                #pragma unroll
                for (int nf = 0; nf < 8; ++nf)
                    MMA_TF32(d[mf][nf], af[mf], bf[nf]);
        }
        if (kt < 31) {
            const int kn = kt + 1;
            // FIX (R6 bug): next-stage A buffer offset is 2560 floats, not 640.
            float* Ad = As + (buf ^ 1) * 2560 + aoff;
            *(float4*)(Ad)        = xf(a0, kn);
            *(float4*)(Ad + 640)  = xf(a1, kn);
            *(float4*)(Ad + 1280) = xf(a2, kn);
            *(float4*)(Ad + 1920) = xf(a3, kn);
            CP_WAIT0();
        }
        __syncthreads();
    }

    // ---- epilogue: bias, stage, column stats ----
    float cs[16], cq[16];
    #pragma unroll
    for (int i = 0; i < 16; ++i) { cs[i] = 0.f; cq[i] = 0.f; }
    #pragma unroll
    for (int mf = 0; mf < 4; ++mf) {
        #pragma unroll
        for (int nf = 0; nf < 8; ++nf) {
            int colb = wn * 64 + nf * 8 + 2 * t;
            float b0 = s_bias[colb], b1 = s_bias[colb + 1];
            int r0 = wm * 64 + mf * 16 + g;
            float v00 = d[mf][nf][0] + b0;
            float v01 = d[mf][nf][1] + b1;
            float v10 = d[mf][nf][2] + b0;
            float v11 = d[mf][nf][3] + b1;
            stage[r0 * 132 + colb]           = v00;
            stage[r0 * 132 + colb + 1]       = v01;
            stage[(r0 + 8) * 132 + colb]     = v10;
            stage[(r0 + 8) * 132 + colb + 1] = v11;
            cs[nf * 2]     += v00 + v10;
            cq[nf * 2]     += v00 * v00 + v10 * v10;
            cs[nf * 2 + 1] += v01 + v11;
            cq[nf * 2 + 1] += v01 * v01 + v11 * v11;
        }
    }
    if (mode != 2) {
        #pragma unroll
        for (int i = 0; i < 16; ++i) {
            #pragma unroll
            for (int msk = 4; msk <= 16; msk <<= 1) {
                cs[i] += __shfl_xor_sync(0xFFFFFFFFu, cs[i], msk);
                cq[i] += __shfl_xor_sync(0xFFFFFFFFu, cq[i], msk);
            }
        }
        if (l < 4) {
            #pragma unroll
            for (int nf = 0; nf < 8; ++nf) {
                int col = wn * 64 + nf * 8 + 2 * l;
                atomicAdd(&s_cs1[col],     cs[nf * 2]);
                atomicAdd(&s_cs2[col],     cq[nf * 2]);
                atomicAdd(&s_cs1[col + 1], cs[nf * 2 + 1]);
                atomicAdd(&s_cs2[col + 1], cq[nf * 2 + 1]);
            }
        }
    }
    __syncthreads();

    // coalesced readout: one thread = one row
    {
        float* yrow = Y + ((size_t)z * M + m0 + tid) * 512 + n0;
        const float* srow = stage + tid * 132;
        #pragma unroll
        for (int q = 0; q < 32; ++q)
            *(float4*)(yrow + q * 4) = *(const float4*)(srow + q * 4);
    }
    if (mode != 2) {
        float* stats = (mode == 0) ? g_rstats : g_cstats;
        atomicAdd(&stats[((size_t)z * 512 + n0 + tid) * 2],     s_cs1[tid]);
        atomicAdd(&stats[((size_t)z * 512 + n0 + tid) * 2 + 1], s_cs2[tid]);
    }
}

// ---------------- region BN finalize ----------------
__global__ void finalize_rs(const float* __restrict__ gamma, const float* __restrict__ beta) {
    int i = blockIdx.x * 512 + threadIdx.x;
    float s1 = g_rstats[i * 2], s2 = g_rstats[i * 2 + 1];
    float mean = s1 * (1.f / 21504.f);
    float var  = s2 * (1.f / 21504.f) - mean * mean;
    float rstd = rsqrtf(var + EPSF);
    float sc = gamma[i] * rstd;
    g_rsc[i] = sc;
    g_rsh[i] = beta[i] - mean * sc;
}

// ---------------- seq-mean of activated h (read-only, float4) ----------------
__global__ void hmean_kernel() {
    const int bt = blockIdx.x, r = blockIdx.y;
    const int c = threadIdx.x * 4;
    const float4 sc = *(const float4*)&g_rsc[r * 512 + c];
    const float4 sh = *(const float4*)&g_rsh[r * 512 + c];
    size_t base = ((size_t)r * 21504 + (size_t)bt * 21) * 512 + c;
    float4 acc = make_float4(0.f, 0.f, 0.f, 0.f);
    #pragma unroll
    for (int s = 0; s < 21; ++s) {
        float4 v = *(const float4*)(g_h + base + (size_t)s * 512);
        acc.x += fmaxf(fmaf(v.x, sc.x, sh.x), 0.f);
        acc.y += fmaxf(fmaf(v.y, sc.y, sh.y), 0.f);
        acc.z += fmaxf(fmaf(v.z, sc.z, sh.z), 0.f);
        acc.w += fmaxf(fmaf(v.w, sc.w, sh.w), 0.f);
    }
    const float inv = 1.f / 21.f;
    acc.x *= inv; acc.y *= inv; acc.z *= inv; acc.w *= inv;
    *(float4*)(g_hmean + ((size_t)r * 1024 + bt) * 512 + c) = acc;
}

// ---------------- BN+ReLU on y + seq-mean -> f_v (float4) ----------------
__global__ void bn_y_kernel(const float* __restrict__ gamma, const float* __restrict__ beta) {
    const int bt = blockIdx.x, n = blockIdx.y;
    const int c = threadIdx.x * 4;
    float4 sc, sh;
    {
        float* pc = &sc.x;
        float* ph = &sh.x;
        #pragma unroll
        for (int j = 0; j < 4; ++j) {
            int i = n * 512 + c + j;
            float mean = g_cstats[i * 2] * (1.f / 21504.f);
            float var  = g_cstats[i * 2 + 1] * (1.f / 21504.f) - mean * mean;
            float rstd = rsqrtf(var + EPSF);
            pc[j] = gamma[i] * rstd;
            ph[j] = beta[i] - mean * pc[j];
        }
    }
    size_t base = ((size_t)n * 21504 + (size_t)bt * 21) * 512 + c;
    float4 acc = make_float4(0.f, 0.f, 0.f, 0.f);
    #pragma unroll
    for (int s = 0; s < 21; ++s) {
        float4 v = *(const float4*)(g_y + base + (size_t)s * 512);
        acc.x += fmaxf(fmaf(v.x, sc.x, sh.x), 0.f);
        acc.y += fmaxf(fmaf(v.y, sc.y, sh.y), 0.f);
        acc.z += fmaxf(fmaf(v.z, sc.z, sh.z), 0.f);
        acc.w += fmaxf(fmaf(v.w, sc.w, sh.w), 0.f);
    }
    const float inv = 1.f / 21.f;
    acc.x *= inv; acc.y *= inv; acc.z *= inv; acc.w *= inv;
    *(float4*)(g_fv + ((size_t)bt * 12 + n) * 512 + c) = acc;
}

// ---------------- prediction heads ----------------
__global__ void preds_kernel(const float* __restrict__ upW,  const float* __restrict__ upb,
                             const float* __restrict__ midW, const float* __restrict__ midb,
                             const float* __restrict__ d1W,  const float* __restrict__ d1b,
                             const float* __restrict__ d2W,  const float* __restrict__ d2b,
                             float* __restrict__ out)
{
    __shared__ float smh[2048];
    const int bt = blockIdx.x;
    for (int i = threadIdx.x; i < 2048; i += 256)
        smh[i] = g_hmean[((size_t)(i >> 9) * 1024 + bt) * 512 + (i & 511)];
    __syncthreads();
    const int w = threadIdx.x >> 5, l = threadIdx.x & 31;
    for (int o = w; o < 42; o += 8) {
        int r, j, nout;
        const float* Wp;
        const float* bp;
        float* op;
        if (o < 16)      { r = 0; j = o;      Wp = upW;  bp = upb;  op = out + (size_t)bt * 16;         nout = 16; }
        else if (o < 18) { r = 1; j = o - 16; Wp = midW; bp = midb; op = out + 16384 + (size_t)bt * 2;  nout = 2;  }
        else if (o < 26) { r = 2; j = o - 18; Wp = d1W;  bp = d1b;  op = out + 18432 + (size_t)bt * 8;  nout = 8;  }
        else             { r = 3; j = o - 26; Wp = d2W;  bp = d2b;  op = out + 26624 + (size_t)bt * 16; nout = 16; }
        float a = 0.f;
        for (int c = l; c < 512; c += 32) a += smh[r * 512 + c] * Wp[c * nout + j];
        #pragma unroll
        for (int off = 16; off; off >>= 1) a += __shfl_xor_sync(0xFFFFFFFFu, a, off);
        if (l == 0) op[j] = a + bp[j];
    }
}

// ---------------- GAT ----------------
__global__ void gat_kernel(const float* __restrict__ adj_mask,
                           const float* __restrict__ al,
                           const float* __restrict__ ar)
{
    __shared__ float hs[12 * 512];
    __shared__ float alp[12], arp[12];
    __shared__ float att[144];
    const int bt = blockIdx.x;
    const float* hgb = g_hg + (size_t)bt * 12 * 512;
    for (int i = threadIdx.x; i < 6144; i += 256) hs[i] = hgb[i];
    __syncthreads();
    const int w = threadIdx.x >> 5, lane = threadIdx.x & 31;
    for (int dd = w; dd < 24; dd += 8) {
        int node = dd >> 1;
        const float* vec = (dd & 1) ? ar : al;
        float s = 0.f;
        for (int c = lane; c < 512; c += 32) s += hs[node * 512 + c] * vec[c];
        #pragma unroll
        for (int o = 16; o; o >>= 1) s += __shfl_xor_sync(0xFFFFFFFFu, s, o);
        if (lane == 0) { if (dd & 1) arp[node] = s; else alp[node] = s; }
    }
    __syncthreads();
    if (threadIdx.x < 144) {
        int i = threadIdx.x / 12, j = threadIdx.x % 12;
        float a = c_adj[threadIdx.x] * adj_mask[(size_t)bt * 144 + threadIdx.x] + (i == j ? 1.f : 0.f);
        float e = alp[i] + arp[j];
        e = (e > 0.f) ? e : 0.2f * e;
        att[threadIdx.x] = (a > 0.1f) ? e : -1e9f;
    }
    __syncthreads();
    if (threadIdx.x < 12) {
        int i = threadIdx.x;
        float mx = -1e30f;
        for (int j = 0; j < 12; ++j) mx = fmaxf(mx, att[i * 12 + j]);
        float tmp[12];
        float sum = 0.f;
        for (int j = 0; j < 12; ++j) { float ev = expf(att[i * 12 + j] - mx); tmp[j] = ev; sum += ev; }
        float invs = 1.f / sum;
        for (int j = 0; j < 12; ++j) att[i * 12 + j] = tmp[j] * invs;
    }
    __syncthreads();
    const float* fvb = g_fv + (size_t)bt * 12 * 512;
    float* gb = g_gat + (size_t)bt * 12 * 512;
    for (int idx = threadIdx.x; idx < 6144; idx += 256) {
        int n = idx >> 9, c = idx & 511;
        float s = fvb[idx];
        #pragma unroll
        for (int j = 0; j < 12; ++j) s += att[n * 12 + j] * hs[j * 512 + c];
        gb[idx] = s;
    }
}

// ---------------- temporal conv, register sliding window, + BN stats ----------------
__global__ void tconv_kernel(const float* __restrict__ W, const float* __restrict__ bias) {
    const int b = blockIdx.x, n = blockIdx.y;
    const int c = threadIdx.x;
    float in[32];
    #pragma unroll
    for (int t = 0; t < 32; ++t)
        in[t] = g_gat[(((size_t)(b * 32 + t)) * 12 + n) * 512 + c];
    const float* wp = W + ((size_t)n * 512 + c) * 5;
    float w0 = wp[0], w1 = wp[1], w2 = wp[2], w3 = wp[3], w4 = wp[4];
    const float bv = bias[n * 512 + c];
    float s = 0.f, s2 = 0.f;
    #pragma unroll
    for (int t = 0; t < 32; ++t) {
        float v = bv;
        if (t >= 2)      v = fmaf(in[t - 2], w0, v);
        if (t >= 1)      v = fmaf(in[t - 1], w1, v);
        v = fmaf(in[t], w2, v);
        if (t + 1 < 32)  v = fmaf(in[t + 1], w3, v);
        if (t + 2 < 32)  v = fmaf(in[t + 2], w4, v);
        g_v[(((size_t)(b * 32 + t)) * 12 + n) * 512 + c] = v;
        s += v;
        s2 = fmaf(v, v, s2);
    }
    #pragma unroll
    for (int o = 16; o; o >>= 1) {
        s  += __shfl_xor_sync(0xFFFFFFFFu, s, o);
        s2 += __shfl_xor_sync(0xFFFFFFFFu, s2, o);
    }
    __shared__ float wsum[16], wsq[16];
    const int lane = c & 31, wrp = c >> 5;
    if (lane == 0) { wsum[wrp] = s; wsq[wrp] = s2; }
    __syncthreads();
    if (c == 0) {
        float a = 0.f, b2 = 0.f;
        #pragma unroll
        for (int i = 0; i < 16; ++i) { a += wsum[i]; b2 += wsq[i]; }
        atomicAdd(&g_tstats[n * 2],     a);
        atomicAdd(&g_tstats[n * 2 + 1], b2);
    }
}

// ---------------- final per-class BN + ReLU (float4) ----------------
__global__ void tbn_kernel(const float* __restrict__ gamma, const float* __restrict__ beta,
                           float* __restrict__ out) {
    const int bt = blockIdx.x, n = blockIdx.y;
    const int c = threadIdx.x * 4;
    const float cnt = 1.f / (1024.f * 512.f);
    const float mean = g_tstats[n * 2] * cnt;
    const float var  = g_tstats[n * 2 + 1] * cnt - mean * mean;
    const float rstd = rsqrtf(var + EPSF);
    const float sc = gamma[n] * rstd;
    const float sh = beta[n] - mean * sc;
    size_t idx = ((size_t)bt * 12 + n) * 512 + c;
    float4 v = *(const float4*)(g_v + idx);
    v.x = fmaxf(fmaf(v.x, sc, sh), 0.f);
    v.y = fmaxf(fmaf(v.y, sc, sh), 0.f);
    v.z = fmaxf(fmaf(v.z, sc, sh), 0.f);
    v.w = fmaxf(fmaf(v.w, sc, sh), 0.f);
    *(float4*)(out + 43008 + idx) = v;
}

// ---------------- launch ----------------
extern "C" void kernel_launch(void* const* d_in, const int* in_sizes, int n_in,
                              void* d_out, int out_size)
{
    const float* x            = (const float*)d_in[0];
    const float* adj_mask     = (const float*)d_in[1];
    const float* region_W     = (const float*)d_in[2];
    const float* region_b     = (const float*)d_in[3];
    const float* region_gamma = (const float*)d_in[4];
    const float* region_beta  = (const float*)d_in[5];
    const float* upfc_W  = (const float*)d_in[6];
    const float* upfc_b  = (const float*)d_in[7];
    const float* midfc_W = (const float*)d_in[8];
    const float* midfc_b = (const float*)d_in[9];
    const float* d1fc_W  = (const float*)d_in[10];
    const float* d1fc_b  = (const float*)d_in[11];
    const float* d2fc_W  = (const float*)d_in[12];
    const float* d2fc_b  = (const float*)d_in[13];
    const float* class_W     = (const float*)d_in[14];
    const float* class_b     = (const float*)d_in[15];
    const float* class_gamma = (const float*)d_in[16];
    const float* class_beta  = (const float*)d_in[17];
    const float* gat_W  = (const float*)d_in[18];
    const float* gat_al = (const float*)d_in[19];
    const float* gat_ar = (const float*)d_in[20];
    const float* tconv_W   = (const float*)d_in[21];
    const float* tconv_b   = (const float*)d_in[22];
    const float* tbn_gamma = (const float*)d_in[23];
    const float* tbn_beta  = (const float*)d_in[24];
    float* out = (float*)d_out;

    cudaFuncSetAttribute(gemm_s, cudaFuncAttributeMaxDynamicSharedMemorySize, SMEM_DYN);

    zero_stats_kernel<<<48, 256>>>();
    transpose_wt<<<dim3(16, 16, 17), dim3(32, 8)>>>(region_W, class_W, gat_W);
    gemm_s<<<dim3(4, 168, 4), 128, SMEM_DYN>>>(x, region_b, 21504, 0);
    finalize_rs<<<4, 512>>>(region_gamma, region_beta);
    hmean_kernel<<<dim3(1024, 4), 128>>>();
    preds_kernel<<<1024, 256>>>(upfc_W, upfc_b, midfc_W, midfc_b,
                                d1fc_W, d1fc_b, d2fc_W, d2fc_b, out);
    gemm_s<<<dim3(4, 168, 12), 128, SMEM_DYN>>>(nullptr, class_b, 21504, 1);
    bn_y_kernel<<<dim3(1024, 12), 128>>>(class_gamma, class_beta);
    gemm_s<<<dim3(4, 96, 1), 128, SMEM_DYN>>>(nullptr, nullptr, 12288, 2);
    gat_kernel<<<1024, 256>>>(adj_mask, gat_al, gat_ar);
    tconv_kernel<<<dim3(32, 12), 512>>>(tconv_W, tconv_b);
    tbn_kernel<<<dim3(1024, 12), 128>>>(tbn_gamma, tbn_beta, out);
}

// round 8
// speedup vs baseline: 3.0865x; 1.4061x over previous
#include <cuda_runtime.h>
#include <cuda_fp16.h>
#include <cstdint>

#define EPSF 1e-5f

// ---------------- scratch (static device globals; no allocation) ----------------
__device__ float g_h[(size_t)4 * 21504 * 512];      // region GEMM out (raw pre-BN)
__device__ float g_y[(size_t)12 * 21504 * 512];     // class GEMM out (pre-BN)
__device__ __half g_wt[(size_t)17 * 512 * 512];     // fragment-packed fp16 weights
__device__ float g_hmean[(size_t)4 * 1024 * 512];   // seq-mean of activated h
__device__ float g_fv[(size_t)1024 * 12 * 512];     // f_v
__device__ float g_hg[(size_t)1024 * 12 * 512];     // GAT projection
__device__ float g_gat[(size_t)1024 * 12 * 512];    // GAT output
__device__ float g_v[(size_t)1024 * 12 * 512];      // temporal conv out (pre-BN)
__device__ float g_rstats[4 * 512 * 2];
__device__ float g_cstats[12 * 512 * 2];
__device__ float g_tstats[24];
__device__ float g_rsc[4 * 512], g_rsh[4 * 512];

__constant__ int c_sel[12]  = {0, 0, 0, 1, 0, 3, 2, 2, 2, 3, 3, 3};
__constant__ int c_start[4] = {0, 14, 28, 28};
__constant__ float c_adj[144] = {
    0,0,0,1,0,1,1,1,1,1,1,1,
    0,0,0,1,0,1,1,1,1,1,1,1,
    0,0,0,1,0,1,1,1,1,1,1,1,
    1,1,1,0,1,1,1,1,1,1,1,1,
    0,0,0,1,0,1,1,1,1,1,1,1,
    1,1,1,1,1,0,1,1,1,0,0,0,
    1,1,1,1,1,1,0,0,0,1,1,1,
    1,1,1,1,1,1,0,0,0,1,1,1,
    1,1,1,1,1,1,0,0,0,1,1,1,
    1,1,1,1,1,0,1,1,1,0,0,0,
    1,1,1,1,1,0,1,1,1,0,0,0,
    1,1,1,1,1,0,1,1,1,0,0,0
};

// ---------------- helpers ----------------
__device__ __forceinline__ uint32_t smem_u32(const void* p) {
    uint32_t a;
    asm("{ .reg .u64 t; cvta.to.shared.u64 t, %1; cvt.u32.u64 %0, t; }" : "=r"(a) : "l"(p));
    return a;
}
__device__ __forceinline__ uint32_t f2h2(float a, float b) {
    __half2 h = __floats2half2_rn(a, b);
    return *(uint32_t*)&h;
}
#define CP_ASYNC16(dst, src) \
    asm volatile("cp.async.ca.shared.global [%0], [%1], 16;" :: "r"(dst), "l"(src) : "memory")
#define CP_COMMIT() asm volatile("cp.async.commit_group;" ::: "memory")
#define CP_WAIT0()  asm volatile("cp.async.wait_group 0;" ::: "memory")

#define MMA_F16(D, A, B0, B1) \
    asm volatile("mma.sync.aligned.m16n8k16.row.col.f32.f16.f16.f32 " \
        "{%0,%1,%2,%3}, {%4,%5,%6,%7}, {%8,%9}, {%0,%1,%2,%3};" \
        : "+f"((D)[0]), "+f"((D)[1]), "+f"((D)[2]), "+f"((D)[3]) \
        : "r"((A)[0]), "r"((A)[1]), "r"((A)[2]), "r"((A)[3]), \
          "r"(B0), "r"(B1))

// ---------------- stats zeroing ----------------
__global__ void zero_stats_kernel() {
    int i = blockIdx.x * blockDim.x + threadIdx.x;
    if (i < 4 * 512 * 2)  g_rstats[i] = 0.f;
    if (i < 12 * 512 * 2) g_cstats[i] = 0.f;
    if (i < 24)           g_tstats[i] = 0.f;
}

// ---------------- weight fragment-pack to fp16 ----------------
// g_wt layout per z: [ntile 2][kbg 32][p 16][block of 256 halfs in m16n8k16-B fragment order]
// block half index i: l = i>>3 (lane), rem = i&7: sub = rem>>2 (n 8-group), reg = (rem>>1)&1, hi = rem&1
//   lane l = g*4 + t  (g = n&7, t = (k&7)>>1);  k_l = reg*8 + t*2 + hi; n_l = sub*8 + g
__global__ void pack_wt(const float* __restrict__ rW,
                        const float* __restrict__ cW,
                        const float* __restrict__ gW) {
    __shared__ float tile[16][17];
    const int z = blockIdx.z;
    const int npg = blockIdx.y;     // global npair 0..31 (n = npg*16 + n_l)
    const int kbg = blockIdx.x;     // k block 0..31
    const float* src = (z < 4) ? rW + (size_t)z * 262144
                     : (z < 16) ? cW + (size_t)(z - 4) * 262144 : gW;
    const int i = threadIdx.x;
    {
        int k_l = i >> 4, n_l = i & 15;
        tile[k_l][n_l] = src[(size_t)(kbg * 16 + k_l) * 512 + npg * 16 + n_l];
    }
    __syncthreads();
    const int l = i >> 3, rem = i & 7;
    const int sub = rem >> 2, reg = (rem >> 1) & 1, hi = rem & 1;
    const int g = l >> 2, t = l & 3;
    const int k_l = reg * 8 + t * 2 + hi;
    const int n_l = sub * 8 + g;
    const int ntile = npg >> 4, p = npg & 15;
    size_t dst = ((((size_t)z * 2 + ntile) * 32 + kbg) * 16 + p) * 256 + i;
    g_wt[dst] = __float2half_rn(tile[k_l][n_l]);
}

// ================= fp16 mma.sync GEMM: block 128x256, 8 warps x (64x64), KC=32 =================
// mode 0: A = x (region gather),  Y = g_h,  stats = g_rstats
// mode 1: A = relu(affine(g_h)),  Y = g_y,  stats = g_cstats
// mode 2: A = g_fv,               Y = g_hg, no stats/bias
// SMEM: A halfs [2][128 rows][pitch 80B] at 0 (20480B); B [2][16384B] at 20480; epilogue stage reuses.
#define SMEM_DYN 67584
__global__ void __launch_bounds__(256) gemm_h(const float* __restrict__ A_ext,
                                              const float* __restrict__ bias, int M, int mode)
{
    extern __shared__ char smc[];
    float* stage = (float*)smc;
    __shared__ float s_bias[256], s_cs1[256], s_cs2[256];
    __shared__ float s_sc[512], s_sh[512];

    const int tid = threadIdx.x;
    const int w = tid >> 5, l = tid & 31;
    const int wm = w >> 2, wn = w & 3;      // warp tile: rows wm*64, cols wn*64
    const int g = l >> 2, t = l & 3;
    const int z = blockIdx.z;
    const int ntile = blockIdx.x;
    const int n0 = ntile * 256;
    const int m0 = blockIdx.y * 128;

    const float* A;
    float* Y;
    int sel = 0;
    if (mode == 0)      { A = A_ext; Y = g_h; }
    else if (mode == 1) { A = g_h;   Y = g_y; sel = c_sel[z]; }
    else                { A = g_fv;  Y = g_hg; }

    s_bias[tid] = bias ? bias[(size_t)z * 512 + n0 + tid] : 0.f;
    s_cs1[tid] = 0.f;
    s_cs2[tid] = 0.f;
    if (mode == 1 && tid < 128) {
        *(float4*)&s_sc[tid * 4] = *(const float4*)&g_rsc[sel * 512 + tid * 4];
        *(float4*)&s_sh[tid * 4] = *(const float4*)&g_rsh[sel * 512 + tid * 4];
    }

    // A loader: thread = (row lrow 0..127, k-half hk): 16 floats per stage
    const int lrow = tid >> 1, hk = tid & 1;
    const float* arow;
    {
        int m = m0 + lrow;
        if (mode == 0) {
            int bt = m / 21, s = m - bt * 21;
            arow = A + ((size_t)bt * 49 + c_start[z] + s) * 512;
        } else if (mode == 1) {
            arow = A + ((size_t)sel * 21504 + m) * 512;
        } else {
            arow = A + (size_t)m * 512;
        }
    }
    const int zw = (mode == 0) ? z : (mode == 1) ? 4 + z : 16;
    const char* gB = (const char*)g_wt + (size_t)zw * 524288 + (size_t)ntile * 262144;
    const uint32_t sB = smem_u32(smc);
    const int aoffB = lrow * 80 + hk * 32;     // byte offset in A buffer

    float d[4][8][4];
    #pragma unroll
    for (int mf = 0; mf < 4; ++mf)
        #pragma unroll
        for (int nf = 0; nf < 8; ++nf)
            #pragma unroll
            for (int q = 0; q < 4; ++q) d[mf][nf][q] = 0.f;

    __syncthreads();   // s_sc/s_sh ready

    // transform one float (mode-1 affine+relu), channel k
    auto xf = [&](float v, int k) -> float {
        if (mode == 1) v = fmaxf(fmaf(v, s_sc[k], s_sh[k]), 0.f);
        return v;
    };
    // load+transform+pack A chunk for stage kt into buffer bf
    auto loadA = [&](int kt, int bf, float4& q0, float4& q1, float4& q2, float4& q3) {
        const float4* a4 = (const float4*)arow;
        int base = kt * 8 + hk * 4;
        q0 = a4[base]; q1 = a4[base + 1]; q2 = a4[base + 2]; q3 = a4[base + 3];
    };
    auto storeA = [&](int kt, int bf, float4 q0, float4 q1, float4 q2, float4 q3) {
        int kb = kt * 32 + hk * 16;
        uint4 u0, u1;
        u0.x = f2h2(xf(q0.x, kb + 0),  xf(q0.y, kb + 1));
        u0.y = f2h2(xf(q0.z, kb + 2),  xf(q0.w, kb + 3));
        u0.z = f2h2(xf(q1.x, kb + 4),  xf(q1.y, kb + 5));
        u0.w = f2h2(xf(q1.z, kb + 6),  xf(q1.w, kb + 7));
        u1.x = f2h2(xf(q2.x, kb + 8),  xf(q2.y, kb + 9));
        u1.y = f2h2(xf(q2.z, kb + 10), xf(q2.w, kb + 11));
        u1.z = f2h2(xf(q3.x, kb + 12), xf(q3.y, kb + 13));
        u1.w = f2h2(xf(q3.z, kb + 14), xf(q3.w, kb + 15));
        char* dst = smc + bf * 10240 + aoffB;
        *(uint4*)dst = u0;
        *(uint4*)(dst + 16) = u1;
    };
    auto loadB = [&](int kt, int bf) {
        const char* src = gB + (size_t)kt * 16384;
        uint32_t dst = sB + 20480 + bf * 16384 + tid * 16;
        #pragma unroll
        for (int i = 0; i < 4; ++i)
            CP_ASYNC16(dst + i * 4096, src + tid * 16 + i * 4096);
        CP_COMMIT();
    };

    // prologue: stage 0
    {
        float4 q0, q1, q2, q3;
        loadB(0, 0);
        loadA(0, 0, q0, q1, q2, q3);
        storeA(0, 0, q0, q1, q2, q3);
        CP_WAIT0();
    }
    __syncthreads();

    for (int kt = 0; kt < 16; ++kt) {
        const int buf = kt & 1;
        float4 q0, q1, q2, q3;
        if (kt < 15) {
            loadB(kt + 1, buf ^ 1);
            loadA(kt + 1, buf ^ 1, q0, q1, q2, q3);
        }
        const char* Ab = smc + buf * 10240;
        const char* Bb = smc + 20480 + buf * 16384;
        #pragma unroll
        for (int kb2 = 0; kb2 < 2; ++kb2) {
            uint32_t af[4][4];
            uint4 bv[4];
            #pragma unroll
            for (int mf = 0; mf < 4; ++mf) {
                int off = (wm * 64 + mf * 16 + g) * 80 + kb2 * 32 + t * 4;
                af[mf][0] = *(const uint32_t*)(Ab + off);
                af[mf][1] = *(const uint32_t*)(Ab + off + 640);
                af[mf][2] = *(const uint32_t*)(Ab + off + 16);
                af[mf][3] = *(const uint32_t*)(Ab + off + 656);
            }
            #pragma unroll
            for (int j = 0; j < 4; ++j)
                bv[j] = *(const uint4*)(Bb + ((kb2 * 16 + wn * 4 + j) * 32 + l) * 16);
            #pragma unroll
            for (int mf = 0; mf < 4; ++mf) {
                #pragma unroll
                for (int j = 0; j < 4; ++j) {
                    MMA_F16(d[mf][j * 2],     af[mf], bv[j].x, bv[j].y);
                    MMA_F16(d[mf][j * 2 + 1], af[mf], bv[j].z, bv[j].w);
                }
            }
        }
        if (kt < 15) {
            storeA(kt + 1, buf ^ 1, q0, q1, q2, q3);
            CP_WAIT0();
        }
        __syncthreads();
    }

    // ---- epilogue: two 128-col passes through the stage buffer ----
    #pragma unroll
    for (int ph = 0; ph < 2; ++ph) {
        if ((wn >> 1) == ph) {
            float cs[16], cq[16];
            #pragma unroll
            for (int i = 0; i < 16; ++i) { cs[i] = 0.f; cq[i] = 0.f; }
            #pragma unroll
            for (int mf = 0; mf < 4; ++mf) {
                #pragma unroll
                for (int nf = 0; nf < 8; ++nf) {
                    int colL = (wn & 1) * 64 + nf * 8 + 2 * t;
                    int colG = wn * 64 + nf * 8 + 2 * t;
                    float b0 = s_bias[colG], b1 = s_bias[colG + 1];
                    int r0 = wm * 64 + mf * 16 + g;
                    float v00 = d[mf][nf][0] + b0;
                    float v01 = d[mf][nf][1] + b1;
                    float v10 = d[mf][nf][2] + b0;
                    float v11 = d[mf][nf][3] + b1;
                    stage[r0 * 132 + colL]           = v00;
                    stage[r0 * 132 + colL + 1]       = v01;
                    stage[(r0 + 8) * 132 + colL]     = v10;
                    stage[(r0 + 8) * 132 + colL + 1] = v11;
                    cs[nf * 2]     += v00 + v10;
                    cq[nf * 2]     += v00 * v00 + v10 * v10;
                    cs[nf * 2 + 1] += v01 + v11;
                    cq[nf * 2 + 1] += v01 * v01 + v11 * v11;
                }
            }
            if (mode != 2) {
                #pragma unroll
                for (int i = 0; i < 16; ++i) {
                    #pragma unroll
                    for (int msk = 4; msk <= 16; msk <<= 1) {
                        cs[i] += __shfl_xor_sync(0xFFFFFFFFu, cs[i], msk);
                        cq[i] += __shfl_xor_sync(0xFFFFFFFFu, cq[i], msk);
                    }
                }
                if (l < 4) {
                    #pragma unroll
                    for (int nf = 0; nf < 8; ++nf) {
                        int col = wn * 64 + nf * 8 + 2 * l;
                        atomicAdd(&s_cs1[col],     cs[nf * 2]);
                        atomicAdd(&s_cs2[col],     cq[nf * 2]);
                        atomicAdd(&s_cs1[col + 1], cs[nf * 2 + 1]);
                        atomicAdd(&s_cs2[col + 1], cq[nf * 2 + 1]);
                    }
                }
            }
        }
        __syncthreads();
        {
            int r = tid >> 1, hh = tid & 1;
            float* yrow = Y + ((size_t)z * M + m0 + r) * 512 + n0 + ph * 128 + hh * 64;
            const float* srow = stage + r * 132 + hh * 64;
            #pragma unroll
            for (int q = 0; q < 16; ++q)
                *(float4*)(yrow + q * 4) = *(const float4*)(srow + q * 4);
        }
        __syncthreads();
    }
    if (mode != 2) {
        float* stats = (mode == 0) ? g_rstats : g_cstats;
        atomicAdd(&stats[((size_t)z * 512 + n0 + tid) * 2],     s_cs1[tid]);
        atomicAdd(&stats[((size_t)z * 512 + n0 + tid) * 2 + 1], s_cs2[tid]);
    }
}

// ---------------- region BN finalize ----------------
__global__ void finalize_rs(const float* __restrict__ gamma, const float* __restrict__ beta) {
    int i = blockIdx.x * 512 + threadIdx.x;
    float s1 = g_rstats[i * 2], s2 = g_rstats[i * 2 + 1];
    float mean = s1 * (1.f / 21504.f);
    float var  = s2 * (1.f / 21504.f) - mean * mean;
    float rstd = rsqrtf(var + EPSF);
    float sc = gamma[i] * rstd;
    g_rsc[i] = sc;
    g_rsh[i] = beta[i] - mean * sc;
}

// ---------------- seq-mean of activated h (read-only, float4) ----------------
__global__ void hmean_kernel() {
    const int bt = blockIdx.x, r = blockIdx.y;
    const int c = threadIdx.x * 4;
    const float4 sc = *(const float4*)&g_rsc[r * 512 + c];
    const float4 sh = *(const float4*)&g_rsh[r * 512 + c];
    size_t base = ((size_t)r * 21504 + (size_t)bt * 21) * 512 + c;
    float4 acc = make_float4(0.f, 0.f, 0.f, 0.f);
    #pragma unroll
    for (int s = 0; s < 21; ++s) {
        float4 v = *(const float4*)(g_h + base + (size_t)s * 512);
        acc.x += fmaxf(fmaf(v.x, sc.x, sh.x), 0.f);
        acc.y += fmaxf(fmaf(v.y, sc.y, sh.y), 0.f);
        acc.z += fmaxf(fmaf(v.z, sc.z, sh.z), 0.f);
        acc.w += fmaxf(fmaf(v.w, sc.w, sh.w), 0.f);
    }
    const float inv = 1.f / 21.f;
    acc.x *= inv; acc.y *= inv; acc.z *= inv; acc.w *= inv;
    *(float4*)(g_hmean + ((size_t)r * 1024 + bt) * 512 + c) = acc;
}

// ---------------- BN+ReLU on y + seq-mean -> f_v (float4) ----------------
__global__ void bn_y_kernel(const float* __restrict__ gamma, const float* __restrict__ beta) {
    const int bt = blockIdx.x, n = blockIdx.y;
    const int c = threadIdx.x * 4;
    float4 sc, sh;
    {
        float* pc = &sc.x;
        float* ph = &sh.x;
        #pragma unroll
        for (int j = 0; j < 4; ++j) {
            int i = n * 512 + c + j;
            float mean = g_cstats[i * 2] * (1.f / 21504.f);
            float var  = g_cstats[i * 2 + 1] * (1.f / 21504.f) - mean * mean;
            float rstd = rsqrtf(var + EPSF);
            pc[j] = gamma[i] * rstd;
            ph[j] = beta[i] - mean * pc[j];
        }
    }
    size_t base = ((size_t)n * 21504 + (size_t)bt * 21) * 512 + c;
    float4 acc = make_float4(0.f, 0.f, 0.f, 0.f);
    #pragma unroll
    for (int s = 0; s < 21; ++s) {
        float4 v = *(const float4*)(g_y + base + (size_t)s * 512);
        acc.x += fmaxf(fmaf(v.x, sc.x, sh.x), 0.f);
        acc.y += fmaxf(fmaf(v.y, sc.y, sh.y), 0.f);
        acc.z += fmaxf(fmaf(v.z, sc.z, sh.z), 0.f);
        acc.w += fmaxf(fmaf(v.w, sc.w, sh.w), 0.f);
    }
    const float inv = 1.f / 21.f;
    acc.x *= inv; acc.y *= inv; acc.z *= inv; acc.w *= inv;
    *(float4*)(g_fv + ((size_t)bt * 12 + n) * 512 + c) = acc;
}

// ---------------- prediction heads ----------------
__global__ void preds_kernel(const float* __restrict__ upW,  const float* __restrict__ upb,
                             const float* __restrict__ midW, const float* __restrict__ midb,
                             const float* __restrict__ d1W,  const float* __restrict__ d1b,
                             const float* __restrict__ d2W,  const float* __restrict__ d2b,
                             float* __restrict__ out)
{
    __shared__ float smh[2048];
    const int bt = blockIdx.x;
    for (int i = threadIdx.x; i < 2048; i += 256)
        smh[i] = g_hmean[((size_t)(i >> 9) * 1024 + bt) * 512 + (i & 511)];
    __syncthreads();
    const int w = threadIdx.x >> 5, l = threadIdx.x & 31;
    for (int o = w; o < 42; o += 8) {
        int r, j, nout;
        const float* Wp;
        const float* bp;
        float* op;
        if (o < 16)      { r = 0; j = o;      Wp = upW;  bp = upb;  op = out + (size_t)bt * 16;         nout = 16; }
        else if (o < 18) { r = 1; j = o - 16; Wp = midW; bp = midb; op = out + 16384 + (size_t)bt * 2;  nout = 2;  }
        else if (o < 26) { r = 2; j = o - 18; Wp = d1W;  bp = d1b;  op = out + 18432 + (size_t)bt * 8;  nout = 8;  }
        else             { r = 3; j = o - 26; Wp = d2W;  bp = d2b;  op = out + 26624 + (size_t)bt * 16; nout = 16; }
        float a = 0.f;
        for (int c = l; c < 512; c += 32) a += smh[r * 512 + c] * Wp[c * nout + j];
        #pragma unroll
        for (int off = 16; off; off >>= 1) a += __shfl_xor_sync(0xFFFFFFFFu, a, off);
        if (l == 0) op[j] = a + bp[j];
    }
}

// ---------------- GAT ----------------
__global__ void gat_kernel(const float* __restrict__ adj_mask,
                           const float* __restrict__ al,
                           const float* __restrict__ ar)
{
    __shared__ float hs[12 * 512];
    __shared__ float alp[12], arp[12];
    __shared__ float att[144];
    const int bt = blockIdx.x;
    const float* hgb = g_hg + (size_t)bt * 12 * 512;
    for (int i = threadIdx.x; i < 6144; i += 256) hs[i] = hgb[i];
    __syncthreads();
    const int w = threadIdx.x >> 5, lane = threadIdx.x & 31;
    for (int dd = w; dd < 24; dd += 8) {
        int node = dd >> 1;
        const float* vec = (dd & 1) ? ar : al;
        float s = 0.f;
        for (int c = lane; c < 512; c += 32) s += hs[node * 512 + c] * vec[c];
        #pragma unroll
        for (int o = 16; o; o >>= 1) s += __shfl_xor_sync(0xFFFFFFFFu, s, o);
        if (lane == 0) { if (dd & 1) arp[node] = s; else alp[node] = s; }
    }
    __syncthreads();
    if (threadIdx.x < 144) {
        int i = threadIdx.x / 12, j = threadIdx.x % 12;
        float a = c_adj[threadIdx.x] * adj_mask[(size_t)bt * 144 + threadIdx.x] + (i == j ? 1.f : 0.f);
        float e = alp[i] + arp[j];
        e = (e > 0.f) ? e : 0.2f * e;
        att[threadIdx.x] = (a > 0.1f) ? e : -1e9f;
    }
    __syncthreads();
    if (threadIdx.x < 12) {
        int i = threadIdx.x;
        float mx = -1e30f;
        for (int j = 0; j < 12; ++j) mx = fmaxf(mx, att[i * 12 + j]);
        float tmp[12];
        float sum = 0.f;
        for (int j = 0; j < 12; ++j) { float ev = expf(att[i * 12 + j] - mx); tmp[j] = ev; sum += ev; }
        float invs = 1.f / sum;
        for (int j = 0; j < 12; ++j) att[i * 12 + j] = tmp[j] * invs;
    }
    __syncthreads();
    const float* fvb = g_fv + (size_t)bt * 12 * 512;
    float* gb = g_gat + (size_t)bt * 12 * 512;
    for (int idx = threadIdx.x; idx < 6144; idx += 256) {
        int n = idx >> 9, c = idx & 511;
        float s = fvb[idx];
        #pragma unroll
        for (int j = 0; j < 12; ++j) s += att[n * 12 + j] * hs[j * 512 + c];
        gb[idx] = s;
    }
}

// ---------------- temporal conv, register sliding window, + BN stats ----------------
__global__ void tconv_kernel(const float* __restrict__ W, const float* __restrict__ bias) {
    const int b = blockIdx.x, n = blockIdx.y;
    const int c = threadIdx.x;
    float in[32];
    #pragma unroll
    for (int t = 0; t < 32; ++t)
        in[t] = g_gat[(((size_t)(b * 32 + t)) * 12 + n) * 512 + c];
    const float* wp = W + ((size_t)n * 512 + c) * 5;
    float w0 = wp[0], w1 = wp[1], w2 = wp[2], w3 = wp[3], w4 = wp[4];
    const float bv = bias[n * 512 + c];
    float s = 0.f, s2 = 0.f;
    #pragma unroll
    for (int t = 0; t < 32; ++t) {
        float v = bv;
        if (t >= 2)      v = fmaf(in[t - 2], w0, v);
        if (t >= 1)      v = fmaf(in[t - 1], w1, v);
        v = fmaf(in[t], w2, v);
        if (t + 1 < 32)  v = fmaf(in[t + 1], w3, v);
        if (t + 2 < 32)  v = fmaf(in[t + 2], w4, v);
        g_v[(((size_t)(b * 32 + t)) * 12 + n) * 512 + c] = v;
        s += v;
        s2 = fmaf(v, v, s2);
    }
    #pragma unroll
    for (int o = 16; o; o >>= 1) {
        s  += __shfl_xor_sync(0xFFFFFFFFu, s, o);
        s2 += __shfl_xor_sync(0xFFFFFFFFu, s2, o);
    }
    __shared__ float wsum[16], wsq[16];
    const int lane = c & 31, wrp = c >> 5;
    if (lane == 0) { wsum[wrp] = s; wsq[wrp] = s2; }
    __syncthreads();
    if (c == 0) {
        float a = 0.f, b2 = 0.f;
        #pragma unroll
        for (int i = 0; i < 16; ++i) { a += wsum[i]; b2 += wsq[i]; }
        atomicAdd(&g_tstats[n * 2],     a);
        atomicAdd(&g_tstats[n * 2 + 1], b2);
    }
}

// ---------------- final per-class BN + ReLU (float4) ----------------
__global__ void tbn_kernel(const float* __restrict__ gamma, const float* __restrict__ beta,
                           float* __restrict__ out) {
    const int bt = blockIdx.x, n = blockIdx.y;
    const int c = threadIdx.x * 4;
    const float cnt = 1.f / (1024.f * 512.f);
    const float mean = g_tstats[n * 2] * cnt;
    const float var  = g_tstats[n * 2 + 1] * cnt - mean * mean;
    const float rstd = rsqrtf(var + EPSF);
    const float sc = gamma[n] * rstd;
    const float sh = beta[n] - mean * sc;
    size_t idx = ((size_t)bt * 12 + n) * 512 + c;
    float4 v = *(const float4*)(g_v + idx);
    v.x = fmaxf(fmaf(v.x, sc, sh), 0.f);
    v.y = fmaxf(fmaf(v.y, sc, sh), 0.f);
    v.z = fmaxf(fmaf(v.z, sc, sh), 0.f);
    v.w = fmaxf(fmaf(v.w, sc, sh), 0.f);
    *(float4*)(out + 43008 + idx) = v;
}

// ---------------- launch ----------------
extern "C" void kernel_launch(void* const* d_in, const int* in_sizes, int n_in,
                              void* d_out, int out_size)
{
    const float* x            = (const float*)d_in[0];
    const float* adj_mask     = (const float*)d_in[1];
    const float* region_W     = (const float*)d_in[2];
    const float* region_b     = (const float*)d_in[3];
    const float* region_gamma = (const float*)d_in[4];
    const float* region_beta  = (const float*)d_in[5];
    const float* upfc_W  = (const float*)d_in[6];
    const float* upfc_b  = (const float*)d_in[7];
    const float* midfc_W = (const float*)d_in[8];
    const float* midfc_b = (const float*)d_in[9];
    const float* d1fc_W  = (const float*)d_in[10];
    const float* d1fc_b  = (const float*)d_in[11];
    const float* d2fc_W  = (const float*)d_in[12];
    const float* d2fc_b  = (const float*)d_in[13];
    const float* class_W     = (const float*)d_in[14];
    const float* class_b     = (const float*)d_in[15];
    const float* class_gamma = (const float*)d_in[16];
    const float* class_beta  = (const float*)d_in[17];
    const float* gat_W  = (const float*)d_in[18];
    const float* gat_al = (const float*)d_in[19];
    const float* gat_ar = (const float*)d_in[20];
    const float* tconv_W   = (const float*)d_in[21];
    const float* tconv_b   = (const float*)d_in[22];
    const float* tbn_gamma = (const float*)d_in[23];
    const float* tbn_beta  = (const float*)d_in[24];
    float* out = (float*)d_out;

    cudaFuncSetAttribute(gemm_h, cudaFuncAttributeMaxDynamicSharedMemorySize, SMEM_DYN);

    zero_stats_kernel<<<48, 256>>>();
    pack_wt<<<dim3(32, 32, 17), 256>>>(region_W, class_W, gat_W);
    gemm_h<<<dim3(2, 168, 4), 256, SMEM_DYN>>>(x, region_b, 21504, 0);
    finalize_rs<<<4, 512>>>(region_gamma, region_beta);
    hmean_kernel<<<dim3(1024, 4), 128>>>();
    preds_kernel<<<1024, 256>>>(upfc_W, upfc_b, midfc_W, midfc_b,
                                d1fc_W, d1fc_b, d2fc_W, d2fc_b, out);
    gemm_h<<<dim3(2, 168, 12), 256, SMEM_DYN>>>(nullptr, class_b, 21504, 1);
    bn_y_kernel<<<dim3(1024, 12), 128>>>(class_gamma, class_beta);
    gemm_h<<<dim3(2, 96, 1), 256, SMEM_DYN>>>(nullptr, nullptr, 12288, 2);
    gat_kernel<<<1024, 256>>>(adj_mask, gat_al, gat_ar);
    tconv_kernel<<<dim3(32, 12), 512>>>(tconv_W, tconv_b);
    tbn_kernel<<<dim3(1024, 12), 128>>>(tbn_gamma, tbn_beta, out);
}

// round 9
// speedup vs baseline: 3.4710x; 1.1246x over previous
#include <cuda_runtime.h>
#include <cuda_fp16.h>
#include <cstdint>

#define EPSF 1e-5f

// ---------------- scratch (static device globals; no allocation) ----------------
__device__ __half g_h[(size_t)4 * 21504 * 512];     // region GEMM out (pre-BN, fp16)
__device__ __half g_y[(size_t)12 * 21504 * 512];    // class GEMM out (pre-BN, fp16)
__device__ __half g_wt[(size_t)17 * 512 * 512];     // fragment-packed fp16 weights
__device__ __half g_hg[(size_t)1024 * 12 * 512];    // GAT projection (fp16)
__device__ float g_hmean[(size_t)4 * 1024 * 512];   // seq-mean of activated h
__device__ float g_fv[(size_t)1024 * 12 * 512];     // f_v
__device__ float g_gat[(size_t)1024 * 12 * 512];    // GAT output
__device__ float g_v[(size_t)1024 * 12 * 512];      // temporal conv out (pre-BN)
__device__ float g_rstats[4 * 512 * 2];
__device__ float g_cstats[12 * 512 * 2];
__device__ float g_tstats[24];
__device__ float g_rsc[4 * 512], g_rsh[4 * 512];

__constant__ int c_sel[12]  = {0, 0, 0, 1, 0, 3, 2, 2, 2, 3, 3, 3};
__constant__ int c_start[4] = {0, 14, 28, 28};
__constant__ float c_adj[144] = {
    0,0,0,1,0,1,1,1,1,1,1,1,
    0,0,0,1,0,1,1,1,1,1,1,1,
    0,0,0,1,0,1,1,1,1,1,1,1,
    1,1,1,0,1,1,1,1,1,1,1,1,
    0,0,0,1,0,1,1,1,1,1,1,1,
    1,1,1,1,1,0,1,1,1,0,0,0,
    1,1,1,1,1,1,0,0,0,1,1,1,
    1,1,1,1,1,1,0,0,0,1,1,1,
    1,1,1,1,1,1,0,0,0,1,1,1,
    1,1,1,1,1,0,1,1,1,0,0,0,
    1,1,1,1,1,0,1,1,1,0,0,0,
    1,1,1,1,1,0,1,1,1,0,0,0
};

// ---------------- helpers ----------------
__device__ __forceinline__ uint32_t smem_u32(const void* p) {
    uint32_t a;
    asm("{ .reg .u64 t; cvta.to.shared.u64 t, %1; cvt.u32.u64 %0, t; }" : "=r"(a) : "l"(p));
    return a;
}
__device__ __forceinline__ uint32_t f2h2(float a, float b) {
    __half2 h = __floats2half2_rn(a, b);
    return *(uint32_t*)&h;
}
#define CP_ASYNC16(dst, src) \
    asm volatile("cp.async.ca.shared.global [%0], [%1], 16;" :: "r"(dst), "l"(src) : "memory")
#define CP_COMMIT() asm volatile("cp.async.commit_group;" ::: "memory")
#define CP_WAIT0()  asm volatile("cp.async.wait_group 0;" ::: "memory")

#define MMA_F16(D, A, B0, B1) \
    asm volatile("mma.sync.aligned.m16n8k16.row.col.f32.f16.f16.f32 " \
        "{%0,%1,%2,%3}, {%4,%5,%6,%7}, {%8,%9}, {%0,%1,%2,%3};" \
        : "+f"((D)[0]), "+f"((D)[1]), "+f"((D)[2]), "+f"((D)[3]) \
        : "r"((A)[0]), "r"((A)[1]), "r"((A)[2]), "r"((A)[3]), \
          "r"(B0), "r"(B1))

// ---------------- stats zeroing ----------------
__global__ void zero_stats_kernel() {
    int i = blockIdx.x * blockDim.x + threadIdx.x;
    if (i < 4 * 512 * 2)  g_rstats[i] = 0.f;
    if (i < 12 * 512 * 2) g_cstats[i] = 0.f;
    if (i < 24)           g_tstats[i] = 0.f;
}

// ---------------- weight fragment-pack to fp16 ----------------
__global__ void pack_wt(const float* __restrict__ rW,
                        const float* __restrict__ cW,
                        const float* __restrict__ gW) {
    __shared__ float tile[16][17];
    const int z = blockIdx.z;
    const int npg = blockIdx.y;
    const int kbg = blockIdx.x;
    const float* src = (z < 4) ? rW + (size_t)z * 262144
                     : (z < 16) ? cW + (size_t)(z - 4) * 262144 : gW;
    const int i = threadIdx.x;
    {
        int k_l = i >> 4, n_l = i & 15;
        tile[k_l][n_l] = src[(size_t)(kbg * 16 + k_l) * 512 + npg * 16 + n_l];
    }
    __syncthreads();
    const int l = i >> 3, rem = i & 7;
    const int sub = rem >> 2, reg = (rem >> 1) & 1, hi = rem & 1;
    const int g = l >> 2, t = l & 3;
    const int k_l = reg * 8 + t * 2 + hi;
    const int n_l = sub * 8 + g;
    const int ntile = npg >> 4, p = npg & 15;
    size_t dst = ((((size_t)z * 2 + ntile) * 32 + kbg) * 16 + p) * 256 + i;
    g_wt[dst] = __float2half_rn(tile[k_l][n_l]);
}

// ================= fp16 mma.sync GEMM: block 128x256, 8 warps x (64x64), KC=32 =================
// mode 0: A = x fp32 (region gather),      Y = g_h (half),  stats = g_rstats
// mode 1: A = relu(affine(g_h half)),      Y = g_y (half),  stats = g_cstats
// mode 2: A = g_fv fp32,                   Y = g_hg (half), no stats/bias
#define SMEM_DYN 53248
__global__ void __launch_bounds__(256) gemm_h(const float* __restrict__ A_ext,
                                              const float* __restrict__ bias, int M, int mode)
{
    extern __shared__ char smc[];
    __half* stg = (__half*)smc;     // epilogue stage reuse: [128][136] halfs
    __shared__ float s_bias[256], s_cs1[256], s_cs2[256];
    __shared__ float s_sc[512], s_sh[512];

    const int tid = threadIdx.x;
    const int w = tid >> 5, l = tid & 31;
    const int wm = w >> 2, wn = w & 3;
    const int g = l >> 2, t = l & 3;
    const int z = blockIdx.z;
    const int ntile = blockIdx.x;
    const int n0 = ntile * 256;
    const int m0 = blockIdx.y * 128;

    __half* Y;
    int sel = 0;
    if (mode == 0)      { Y = g_h; }
    else if (mode == 1) { Y = g_y; sel = c_sel[z]; }
    else                { Y = g_hg; }

    s_bias[tid] = bias ? bias[(size_t)z * 512 + n0 + tid] : 0.f;
    s_cs1[tid] = 0.f;
    s_cs2[tid] = 0.f;
    if (mode == 1 && tid < 128) {
        *(float4*)&s_sc[tid * 4] = *(const float4*)&g_rsc[sel * 512 + tid * 4];
        *(float4*)&s_sh[tid * 4] = *(const float4*)&g_rsh[sel * 512 + tid * 4];
    }

    // A loader: thread = (row lrow 0..127, k-half hk covering 16 channels)
    const int lrow = tid >> 1, hk = tid & 1;
    const float* arow32 = nullptr;
    const __half* arow16 = nullptr;
    {
        int m = m0 + lrow;
        if (mode == 0) {
            int bt = m / 21, s = m - bt * 21;
            arow32 = A_ext + ((size_t)bt * 49 + c_start[z] + s) * 512;
        } else if (mode == 1) {
            arow16 = g_h + ((size_t)sel * 21504 + m) * 512;
        } else {
            arow32 = g_fv + (size_t)m * 512;
        }
    }
    const int zw = (mode == 0) ? z : (mode == 1) ? 4 + z : 16;
    const char* gB = (const char*)g_wt + (size_t)zw * 524288 + (size_t)ntile * 262144;
    const uint32_t sB = smem_u32(smc);
    const int aoffB = lrow * 80 + hk * 32;

    float d[4][8][4];
    #pragma unroll
    for (int mf = 0; mf < 4; ++mf)
        #pragma unroll
        for (int nf = 0; nf < 8; ++nf)
            #pragma unroll
            for (int q = 0; q < 4; ++q) d[mf][nf][q] = 0.f;

    __syncthreads();   // s_sc/s_sh ready

    // mode-1 fp16-in transform: half2 -> affine+relu -> half2 (channel k, k+1)
    auto tr2 = [&](uint32_t h2, int k) -> uint32_t {
        float2 f = __half22float2(*(__half2*)&h2);
        f.x = fmaxf(fmaf(f.x, s_sc[k],     s_sh[k]),     0.f);
        f.y = fmaxf(fmaf(f.y, s_sc[k + 1], s_sh[k + 1]), 0.f);
        return f2h2(f.x, f.y);
    };
    auto storeA32 = [&](int kt, int bf, float4 q0, float4 q1, float4 q2, float4 q3) {
        uint4 u0, u1;
        u0.x = f2h2(q0.x, q0.y); u0.y = f2h2(q0.z, q0.w);
        u0.z = f2h2(q1.x, q1.y); u0.w = f2h2(q1.z, q1.w);
        u1.x = f2h2(q2.x, q2.y); u1.y = f2h2(q2.z, q2.w);
        u1.z = f2h2(q3.x, q3.y); u1.w = f2h2(q3.z, q3.w);
        char* dst = smc + bf * 10240 + aoffB;
        *(uint4*)dst = u0;
        *(uint4*)(dst + 16) = u1;
    };
    auto storeA16 = [&](int kt, int bf, uint4 p0, uint4 p1) {
        int kb = kt * 32 + hk * 16;
        uint4 u0, u1;
        u0.x = tr2(p0.x, kb + 0);  u0.y = tr2(p0.y, kb + 2);
        u0.z = tr2(p0.z, kb + 4);  u0.w = tr2(p0.w, kb + 6);
        u1.x = tr2(p1.x, kb + 8);  u1.y = tr2(p1.y, kb + 10);
        u1.z = tr2(p1.z, kb + 12); u1.w = tr2(p1.w, kb + 14);
        char* dst = smc + bf * 10240 + aoffB;
        *(uint4*)dst = u0;
        *(uint4*)(dst + 16) = u1;
    };
    auto loadB = [&](int kt, int bf) {
        const char* src = gB + (size_t)kt * 16384;
        uint32_t dst = sB + 20480 + bf * 16384 + tid * 16;
        #pragma unroll
        for (int i = 0; i < 4; ++i)
            CP_ASYNC16(dst + i * 4096, src + tid * 16 + i * 4096);
        CP_COMMIT();
    };

    // prologue: stage 0
    {
        loadB(0, 0);
        if (mode == 1) {
            const uint4* a16 = (const uint4*)(arow16 + hk * 16);
            storeA16(0, 0, a16[0], a16[1]);
        } else {
            const float4* a4 = (const float4*)arow32 + hk * 4;
            storeA32(0, 0, a4[0], a4[1], a4[2], a4[3]);
        }
        CP_WAIT0();
    }
    __syncthreads();

    for (int kt = 0; kt < 16; ++kt) {
        const int buf = kt & 1;
        float4 q0, q1, q2, q3;
        uint4 p0, p1;
        if (kt < 15) {
            loadB(kt + 1, buf ^ 1);
            if (mode == 1) {
                const uint4* a16 = (const uint4*)(arow16 + (kt + 1) * 32 + hk * 16);
                p0 = a16[0]; p1 = a16[1];
            } else {
                const float4* a4 = (const float4*)arow32 + (kt + 1) * 8 + hk * 4;
                q0 = a4[0]; q1 = a4[1]; q2 = a4[2]; q3 = a4[3];
            }
        }
        const char* Ab = smc + buf * 10240;
        const char* Bb = smc + 20480 + buf * 16384;
        #pragma unroll
        for (int kb2 = 0; kb2 < 2; ++kb2) {
            uint32_t af[4][4];
            uint4 bv[4];
            #pragma unroll
            for (int mf = 0; mf < 4; ++mf) {
                int off = (wm * 64 + mf * 16 + g) * 80 + kb2 * 32 + t * 4;
                af[mf][0] = *(const uint32_t*)(Ab + off);
                af[mf][1] = *(const uint32_t*)(Ab + off + 640);
                af[mf][2] = *(const uint32_t*)(Ab + off + 16);
                af[mf][3] = *(const uint32_t*)(Ab + off + 656);
            }
            #pragma unroll
            for (int j = 0; j < 4; ++j)
                bv[j] = *(const uint4*)(Bb + ((kb2 * 16 + wn * 4 + j) * 32 + l) * 16);
            #pragma unroll
            for (int mf = 0; mf < 4; ++mf) {
                #pragma unroll
                for (int j = 0; j < 4; ++j) {
                    MMA_F16(d[mf][j * 2],     af[mf], bv[j].x, bv[j].y);
                    MMA_F16(d[mf][j * 2 + 1], af[mf], bv[j].z, bv[j].w);
                }
            }
        }
        if (kt < 15) {
            if (mode == 1) storeA16(kt + 1, buf ^ 1, p0, p1);
            else           storeA32(kt + 1, buf ^ 1, q0, q1, q2, q3);
            CP_WAIT0();
        }
        __syncthreads();
    }

    // ---- epilogue: two 128-col passes, half stage, fp32 stats ----
    #pragma unroll
    for (int ph = 0; ph < 2; ++ph) {
        if ((wn >> 1) == ph) {
            float cs[16], cq[16];
            #pragma unroll
            for (int i = 0; i < 16; ++i) { cs[i] = 0.f; cq[i] = 0.f; }
            #pragma unroll
            for (int mf = 0; mf < 4; ++mf) {
                #pragma unroll
                for (int nf = 0; nf < 8; ++nf) {
                    int colL = (wn & 1) * 64 + nf * 8 + 2 * t;
                    int colG = wn * 64 + nf * 8 + 2 * t;
                    float b0 = s_bias[colG], b1 = s_bias[colG + 1];
                    int r0 = wm * 64 + mf * 16 + g;
                    float v00 = d[mf][nf][0] + b0;
                    float v01 = d[mf][nf][1] + b1;
                    float v10 = d[mf][nf][2] + b0;
                    float v11 = d[mf][nf][3] + b1;
                    *(__half2*)&stg[r0 * 136 + colL]       = __floats2half2_rn(v00, v01);
                    *(__half2*)&stg[(r0 + 8) * 136 + colL] = __floats2half2_rn(v10, v11);
                    cs[nf * 2]     += v00 + v10;
                    cq[nf * 2]     += v00 * v00 + v10 * v10;
                    cs[nf * 2 + 1] += v01 + v11;
                    cq[nf * 2 + 1] += v01 * v01 + v11 * v11;
                }
            }
            if (mode != 2) {
                #pragma unroll
                for (int i = 0; i < 16; ++i) {
                    #pragma unroll
                    for (int msk = 4; msk <= 16; msk <<= 1) {
                        cs[i] += __shfl_xor_sync(0xFFFFFFFFu, cs[i], msk);
                        cq[i] += __shfl_xor_sync(0xFFFFFFFFu, cq[i], msk);
                    }
                }
                if (l < 4) {
                    #pragma unroll
                    for (int nf = 0; nf < 8; ++nf) {
                        int col = wn * 64 + nf * 8 + 2 * l;
                        atomicAdd(&s_cs1[col],     cs[nf * 2]);
                        atomicAdd(&s_cs2[col],     cq[nf * 2]);
                        atomicAdd(&s_cs1[col + 1], cs[nf * 2 + 1]);
                        atomicAdd(&s_cs2[col + 1], cq[nf * 2 + 1]);
                    }
                }
            }
        }
        __syncthreads();
        {
            int r = tid >> 1, hh = tid & 1;
            __half* yrow = Y + ((size_t)z * M + m0 + r) * 512 + n0 + ph * 128 + hh * 64;
            const __half* srow = stg + r * 136 + hh * 64;
            #pragma unroll
            for (int q = 0; q < 8; ++q)
                *(uint4*)(yrow + q * 8) = *(const uint4*)(srow + q * 8);
        }
        __syncthreads();
    }
    if (mode != 2) {
        float* stats = (mode == 0) ? g_rstats : g_cstats;
        atomicAdd(&stats[((size_t)z * 512 + n0 + tid) * 2],     s_cs1[tid]);
        atomicAdd(&stats[((size_t)z * 512 + n0 + tid) * 2 + 1], s_cs2[tid]);
    }
}

// ---------------- region BN finalize ----------------
__global__ void finalize_rs(const float* __restrict__ gamma, const float* __restrict__ beta) {
    int i = blockIdx.x * 512 + threadIdx.x;
    float s1 = g_rstats[i * 2], s2 = g_rstats[i * 2 + 1];
    float mean = s1 * (1.f / 21504.f);
    float var  = s2 * (1.f / 21504.f) - mean * mean;
    float rstd = rsqrtf(var + EPSF);
    float sc = gamma[i] * rstd;
    g_rsc[i] = sc;
    g_rsh[i] = beta[i] - mean * sc;
}

// ---------------- seq-mean of activated h (fp16 read) ----------------
__global__ void hmean_kernel() {
    const int bt = blockIdx.x, r = blockIdx.y;
    const int c = threadIdx.x * 8;    // 64 threads
    float sc[8], sh[8];
    #pragma unroll
    for (int j = 0; j < 8; ++j) {
        sc[j] = g_rsc[r * 512 + c + j];
        sh[j] = g_rsh[r * 512 + c + j];
    }
    size_t base = ((size_t)r * 21504 + (size_t)bt * 21) * 512 + c;
    float acc[8] = {0.f, 0.f, 0.f, 0.f, 0.f, 0.f, 0.f, 0.f};
    #pragma unroll
    for (int s = 0; s < 21; ++s) {
        uint4 u = *(const uint4*)(g_h + base + (size_t)s * 512);
        const __half2* hp = (const __half2*)&u;
        #pragma unroll
        for (int p = 0; p < 4; ++p) {
            float2 f = __half22float2(hp[p]);
            acc[p * 2]     += fmaxf(fmaf(f.x, sc[p * 2],     sh[p * 2]),     0.f);
            acc[p * 2 + 1] += fmaxf(fmaf(f.y, sc[p * 2 + 1], sh[p * 2 + 1]), 0.f);
        }
    }
    float* dst = g_hmean + ((size_t)r * 1024 + bt) * 512 + c;
    #pragma unroll
    for (int j = 0; j < 8; ++j) dst[j] = acc[j] * (1.f / 21.f);
}

// ---------------- BN+ReLU on y + seq-mean -> f_v (fp16 read) ----------------
__global__ void bn_y_kernel(const float* __restrict__ gamma, const float* __restrict__ beta) {
    const int bt = blockIdx.x, n = blockIdx.y;
    const int c = threadIdx.x * 8;    // 64 threads
    float sc[8], sh[8];
    #pragma unroll
    for (int j = 0; j < 8; ++j) {
        int i = n * 512 + c + j;
        float mean = g_cstats[i * 2] * (1.f / 21504.f);
        float var  = g_cstats[i * 2 + 1] * (1.f / 21504.f) - mean * mean;
        float rstd = rsqrtf(var + EPSF);
        sc[j] = gamma[i] * rstd;
        sh[j] = beta[i] - mean * sc[j];
    }
    size_t base = ((size_t)n * 21504 + (size_t)bt * 21) * 512 + c;
    float acc[8] = {0.f, 0.f, 0.f, 0.f, 0.f, 0.f, 0.f, 0.f};
    #pragma unroll
    for (int s = 0; s < 21; ++s) {
        uint4 u = *(const uint4*)(g_y + base + (size_t)s * 512);
        const __half2* hp = (const __half2*)&u;
        #pragma unroll
        for (int p = 0; p < 4; ++p) {
            float2 f = __half22float2(hp[p]);
            acc[p * 2]     += fmaxf(fmaf(f.x, sc[p * 2],     sh[p * 2]),     0.f);
            acc[p * 2 + 1] += fmaxf(fmaf(f.y, sc[p * 2 + 1], sh[p * 2 + 1]), 0.f);
        }
    }
    float* dst = g_fv + ((size_t)bt * 12 + n) * 512 + c;
    #pragma unroll
    for (int j = 0; j < 8; ++j) dst[j] = acc[j] * (1.f / 21.f);
}

// ---------------- prediction heads ----------------
__global__ void preds_kernel(const float* __restrict__ upW,  const float* __restrict__ upb,
                             const float* __restrict__ midW, const float* __restrict__ midb,
                             const float* __restrict__ d1W,  const float* __restrict__ d1b,
                             const float* __restrict__ d2W,  const float* __restrict__ d2b,
                             float* __restrict__ out)
{
    __shared__ float smh[2048];
    const int bt = blockIdx.x;
    for (int i = threadIdx.x; i < 2048; i += 256)
        smh[i] = g_hmean[((size_t)(i >> 9) * 1024 + bt) * 512 + (i & 511)];
    __syncthreads();
    const int w = threadIdx.x >> 5, l = threadIdx.x & 31;
    for (int o = w; o < 42; o += 8) {
        int r, j, nout;
        const float* Wp;
        const float* bp;
        float* op;
        if (o < 16)      { r = 0; j = o;      Wp = upW;  bp = upb;  op = out + (size_t)bt * 16;         nout = 16; }
        else if (o < 18) { r = 1; j = o - 16; Wp = midW; bp = midb; op = out + 16384 + (size_t)bt * 2;  nout = 2;  }
        else if (o < 26) { r = 2; j = o - 18; Wp = d1W;  bp = d1b;  op = out + 18432 + (size_t)bt * 8;  nout = 8;  }
        else             { r = 3; j = o - 26; Wp = d2W;  bp = d2b;  op = out + 26624 + (size_t)bt * 16; nout = 16; }
        float a = 0.f;
        for (int c = l; c < 512; c += 32) a += smh[r * 512 + c] * Wp[c * nout + j];
        #pragma unroll
        for (int off = 16; off; off >>= 1) a += __shfl_xor_sync(0xFFFFFFFFu, a, off);
        if (l == 0) op[j] = a + bp[j];
    }
}

// ---------------- GAT (fp16 hg read) ----------------
__global__ void gat_kernel(const float* __restrict__ adj_mask,
                           const float* __restrict__ al,
                           const float* __restrict__ ar)
{
    __shared__ float hs[12 * 512];
    __shared__ float alp[12], arp[12];
    __shared__ float att[144];
    const int bt = blockIdx.x;
    const __half* hgb = g_hg + (size_t)bt * 12 * 512;
    for (int i = threadIdx.x; i < 6144; i += 256) hs[i] = __half2float(hgb[i]);
    __syncthreads();
    const int w = threadIdx.x >> 5, lane = threadIdx.x & 31;
    for (int dd = w; dd < 24; dd += 8) {
        int node = dd >> 1;
        const float* vec = (dd & 1) ? ar : al;
        float s = 0.f;
        for (int c = lane; c < 512; c += 32) s += hs[node * 512 + c] * vec[c];
        #pragma unroll
        for (int o = 16; o; o >>= 1) s += __shfl_xor_sync(0xFFFFFFFFu, s, o);
        if (lane == 0) { if (dd & 1) arp[node] = s; else alp[node] = s; }
    }
    __syncthreads();
    if (threadIdx.x < 144) {
        int i = threadIdx.x / 12, j = threadIdx.x % 12;
        float a = c_adj[threadIdx.x] * adj_mask[(size_t)bt * 144 + threadIdx.x] + (i == j ? 1.f : 0.f);
        float e = alp[i] + arp[j];
        e = (e > 0.f) ? e : 0.2f * e;
        att[threadIdx.x] = (a > 0.1f) ? e : -1e9f;
    }
    __syncthreads();
    if (threadIdx.x < 12) {
        int i = threadIdx.x;
        float mx = -1e30f;
        for (int j = 0; j < 12; ++j) mx = fmaxf(mx, att[i * 12 + j]);
        float tmp[12];
        float sum = 0.f;
        for (int j = 0; j < 12; ++j) { float ev = expf(att[i * 12 + j] - mx); tmp[j] = ev; sum += ev; }
        float invs = 1.f / sum;
        for (int j = 0; j < 12; ++j) att[i * 12 + j] = tmp[j] * invs;
    }
    __syncthreads();
    const float* fvb = g_fv + (size_t)bt * 12 * 512;
    float* gb = g_gat + (size_t)bt * 12 * 512;
    for (int idx = threadIdx.x; idx < 6144; idx += 256) {
        int n = idx >> 9, c = idx & 511;
        float s = fvb[idx];
        #pragma unroll
        for (int j = 0; j < 12; ++j) s += att[n * 12 + j] * hs[j * 512 + c];
        gb[idx] = s;
    }
}

// ---------------- temporal conv, register sliding window, + BN stats ----------------
__global__ void tconv_kernel(const float* __restrict__ W, const float* __restrict__ bias) {
    const int b = blockIdx.x, n = blockIdx.y;
    const int c = threadIdx.x;
    float in[32];
    #pragma unroll
    for (int t = 0; t < 32; ++t)
        in[t] = g_gat[(((size_t)(b * 32 + t)) * 12 + n) * 512 + c];
    const float* wp = W + ((size_t)n * 512 + c) * 5;
    float w0 = wp[0], w1 = wp[1], w2 = wp[2], w3 = wp[3], w4 = wp[4];
    const float bv = bias[n * 512 + c];
    float s = 0.f, s2 = 0.f;
    #pragma unroll
    for (int t = 0; t < 32; ++t) {
        float v = bv;
        if (t >= 2)      v = fmaf(in[t - 2], w0, v);
        if (t >= 1)      v = fmaf(in[t - 1], w1, v);
        v = fmaf(in[t], w2, v);
        if (t + 1 < 32)  v = fmaf(in[t + 1], w3, v);
        if (t + 2 < 32)  v = fmaf(in[t + 2], w4, v);
        g_v[(((size_t)(b * 32 + t)) * 12 + n) * 512 + c] = v;
        s += v;
        s2 = fmaf(v, v, s2);
    }
    #pragma unroll
    for (int o = 16; o; o >>= 1) {
        s  += __shfl_xor_sync(0xFFFFFFFFu, s, o);
        s2 += __shfl_xor_sync(0xFFFFFFFFu, s2, o);
    }
    __shared__ float wsum[16], wsq[16];
    const int lane = c & 31, wrp = c >> 5;
    if (lane == 0) { wsum[wrp] = s; wsq[wrp] = s2; }
    __syncthreads();
    if (c == 0) {
        float a = 0.f, b2 = 0.f;
        #pragma unroll
        for (int i = 0; i < 16; ++i) { a += wsum[i]; b2 += wsq[i]; }
        atomicAdd(&g_tstats[n * 2],     a);
        atomicAdd(&g_tstats[n * 2 + 1], b2);
    }
}

// ---------------- final per-class BN + ReLU (float4) ----------------
__global__ void tbn_kernel(const float* __restrict__ gamma, const float* __restrict__ beta,
                           float* __restrict__ out) {
    const int bt = blockIdx.x, n = blockIdx.y;
    const int c = threadIdx.x * 4;
    const float cnt = 1.f / (1024.f * 512.f);
    const float mean = g_tstats[n * 2] * cnt;
    const float var  = g_tstats[n * 2 + 1] * cnt - mean * mean;
    const float rstd = rsqrtf(var + EPSF);
    const float sc = gamma[n] * rstd;
    const float sh = beta[n] - mean * sc;
    size_t idx = ((size_t)bt * 12 + n) * 512 + c;
    float4 v = *(const float4*)(g_v + idx);
    v.x = fmaxf(fmaf(v.x, sc, sh), 0.f);
    v.y = fmaxf(fmaf(v.y, sc, sh), 0.f);
    v.z = fmaxf(fmaf(v.z, sc, sh), 0.f);
    v.w = fmaxf(fmaf(v.w, sc, sh), 0.f);
    *(float4*)(out + 43008 + idx) = v;
}

// ---------------- launch ----------------
extern "C" void kernel_launch(void* const* d_in, const int* in_sizes, int n_in,
                              void* d_out, int out_size)
{
    const float* x            = (const float*)d_in[0];
    const float* adj_mask     = (const float*)d_in[1];
    const float* region_W     = (const float*)d_in[2];
    const float* region_b     = (const float*)d_in[3];
    const float* region_gamma = (const float*)d_in[4];
    const float* region_beta  = (const float*)d_in[5];
    const float* upfc_W  = (const float*)d_in[6];
    const float* upfc_b  = (const float*)d_in[7];
    const float* midfc_W = (const float*)d_in[8];
    const float* midfc_b = (const float*)d_in[9];
    const float* d1fc_W  = (const float*)d_in[10];
    const float* d1fc_b  = (const float*)d_in[11];
    const float* d2fc_W  = (const float*)d_in[12];
    const float* d2fc_b  = (const float*)d_in[13];
    const float* class_W     = (const float*)d_in[14];
    const float* class_b     = (const float*)d_in[15];
    const float* class_gamma = (const float*)d_in[16];
    const float* class_beta  = (const float*)d_in[17];
    const float* gat_W  = (const float*)d_in[18];
    const float* gat_al = (const float*)d_in[19];
    const float* gat_ar = (const float*)d_in[20];
    const float* tconv_W   = (const float*)d_in[21];
    const float* tconv_b   = (const float*)d_in[22];
    const float* tbn_gamma = (const float*)d_in[23];
    const float* tbn_beta  = (const float*)d_in[24];
    float* out = (float*)d_out;

    cudaFuncSetAttribute(gemm_h, cudaFuncAttributeMaxDynamicSharedMemorySize, SMEM_DYN);

    zero_stats_kernel<<<48, 256>>>();
    pack_wt<<<dim3(32, 32, 17), 256>>>(region_W, class_W, gat_W);
    gemm_h<<<dim3(2, 168, 4), 256, SMEM_DYN>>>(x, region_b, 21504, 0);
    finalize_rs<<<4, 512>>>(region_gamma, region_beta);
    hmean_kernel<<<dim3(1024, 4), 64>>>();
    preds_kernel<<<1024, 256>>>(upfc_W, upfc_b, midfc_W, midfc_b,
                                d1fc_W, d1fc_b, d2fc_W, d2fc_b, out);
    gemm_h<<<dim3(2, 168, 12), 256, SMEM_DYN>>>(nullptr, class_b, 21504, 1);
    bn_y_kernel<<<dim3(1024, 12), 64>>>(class_gamma, class_beta);
    gemm_h<<<dim3(2, 96, 1), 256, SMEM_DYN>>>(nullptr, nullptr, 12288, 2);
    gat_kernel<<<1024, 256>>>(adj_mask, gat_al, gat_ar);
    tconv_kernel<<<dim3(32, 12), 512>>>(tconv_W, tconv_b);
    tbn_kernel<<<dim3(1024, 12), 128>>>(tbn_gamma, tbn_beta, out);
}

// round 10
// speedup vs baseline: 3.6720x; 1.0579x over previous
#include <cuda_runtime.h>
#include <cuda_fp16.h>
#include <cstdint>

#define EPSF 1e-5f

// ---------------- scratch (static device globals; no allocation) ----------------
__device__ __half g_xh[(size_t)1024 * 49 * 512];    // fp16 input
__device__ __half g_h[(size_t)4 * 21504 * 512];     // region GEMM out; activated fp16 in place
__device__ __half g_y[(size_t)12 * 21504 * 512];    // class GEMM out (pre-BN, fp16)
__device__ __half g_wt[(size_t)17 * 512 * 512];     // fragment-packed fp16 weights
__device__ __half g_hg[(size_t)1024 * 12 * 512];    // GAT projection (fp16)
__device__ __half g_fvh[(size_t)1024 * 12 * 512];   // f_v fp16 (GEMM operand)
__device__ float g_hmean[(size_t)4 * 1024 * 512];   // seq-mean of activated h
__device__ float g_fv[(size_t)1024 * 12 * 512];     // f_v fp32 (GAT residual)
__device__ float g_gat[(size_t)1024 * 12 * 512];    // GAT output
__device__ float g_v[(size_t)1024 * 12 * 512];      // temporal conv out (pre-BN)
__device__ float g_rstats[4 * 512 * 2];
__device__ float g_cstats[12 * 512 * 2];
__device__ float g_tstats[24];

__constant__ int c_sel[12]  = {0, 0, 0, 1, 0, 3, 2, 2, 2, 3, 3, 3};
__constant__ int c_start[4] = {0, 14, 28, 28};
__constant__ float c_adj[144] = {
    0,0,0,1,0,1,1,1,1,1,1,1,
    0,0,0,1,0,1,1,1,1,1,1,1,
    0,0,0,1,0,1,1,1,1,1,1,1,
    1,1,1,0,1,1,1,1,1,1,1,1,
    0,0,0,1,0,1,1,1,1,1,1,1,
    1,1,1,1,1,0,1,1,1,0,0,0,
    1,1,1,1,1,1,0,0,0,1,1,1,
    1,1,1,1,1,1,0,0,0,1,1,1,
    1,1,1,1,1,1,0,0,0,1,1,1,
    1,1,1,1,1,0,1,1,1,0,0,0,
    1,1,1,1,1,0,1,1,1,0,0,0,
    1,1,1,1,1,0,1,1,1,0,0,0
};

// ---------------- helpers ----------------
__device__ __forceinline__ uint32_t smem_u32(const void* p) {
    uint32_t a;
    asm("{ .reg .u64 t; cvta.to.shared.u64 t, %1; cvt.u32.u64 %0, t; }" : "=r"(a) : "l"(p));
    return a;
}
__device__ __forceinline__ uint32_t f2h2(float a, float b) {
    __half2 h = __floats2half2_rn(a, b);
    return *(uint32_t*)&h;
}
#define CP_ASYNC16(dst, src) \
    asm volatile("cp.async.ca.shared.global [%0], [%1], 16;" :: "r"(dst), "l"(src) : "memory")
#define CP_COMMIT() asm volatile("cp.async.commit_group;" ::: "memory")
#define CP_WAIT0()  asm volatile("cp.async.wait_group 0;" ::: "memory")

#define MMA_F16(D, A, B0, B1) \
    asm volatile("mma.sync.aligned.m16n8k16.row.col.f32.f16.f16.f32 " \
        "{%0,%1,%2,%3}, {%4,%5,%6,%7}, {%8,%9}, {%0,%1,%2,%3};" \
        : "+f"((D)[0]), "+f"((D)[1]), "+f"((D)[2]), "+f"((D)[3]) \
        : "r"((A)[0]), "r"((A)[1]), "r"((A)[2]), "r"((A)[3]), \
          "r"(B0), "r"(B1))

// ---------------- prep: x -> fp16, zero stats ----------------
__global__ void prep_kernel(const float* __restrict__ x) {
    size_t base = ((size_t)blockIdx.x * 256 + threadIdx.x) * 8;
    float4 f0 = *(const float4*)(x + base);
    float4 f1 = *(const float4*)(x + base + 4);
    uint4 u;
    u.x = f2h2(f0.x, f0.y); u.y = f2h2(f0.z, f0.w);
    u.z = f2h2(f1.x, f1.y); u.w = f2h2(f1.z, f1.w);
    *(uint4*)(g_xh + base) = u;
    if (blockIdx.x == 0) {
        for (int j = threadIdx.x; j < 4 * 512 * 2; j += 256)  g_rstats[j] = 0.f;
        for (int j = threadIdx.x; j < 12 * 512 * 2; j += 256) g_cstats[j] = 0.f;
        if (threadIdx.x < 24) g_tstats[threadIdx.x] = 0.f;
    }
}

// ---------------- weight fragment-pack to fp16 ----------------
__global__ void pack_wt(const float* __restrict__ rW,
                        const float* __restrict__ cW,
                        const float* __restrict__ gW) {
    __shared__ float tile[16][17];
    const int z = blockIdx.z;
    const int npg = blockIdx.y;
    const int kbg = blockIdx.x;
    const float* src = (z < 4) ? rW + (size_t)z * 262144
                     : (z < 16) ? cW + (size_t)(z - 4) * 262144 : gW;
    const int i = threadIdx.x;
    {
        int k_l = i >> 4, n_l = i & 15;
        tile[k_l][n_l] = src[(size_t)(kbg * 16 + k_l) * 512 + npg * 16 + n_l];
    }
    __syncthreads();
    const int l = i >> 3, rem = i & 7;
    const int sub = rem >> 2, reg = (rem >> 1) & 1, hi = rem & 1;
    const int g = l >> 2, t = l & 3;
    const int k_l = reg * 8 + t * 2 + hi;
    const int n_l = sub * 8 + g;
    const int ntile = npg >> 4, p = npg & 15;
    size_t dst = ((((size_t)z * 2 + ntile) * 32 + kbg) * 16 + p) * 256 + i;
    g_wt[dst] = __float2half_rn(tile[k_l][n_l]);
}

// ================= fp16 mma.sync GEMM: block 128x256, 8 warps x (64x64), KC=32 =================
// All A sources fp16, loaded with cp.async (no register staging):
// mode 0: A = g_xh (region gather),  Y = g_h (half),  stats = g_rstats
// mode 1: A = g_h (pre-activated),   Y = g_y (half),  stats = g_cstats
// mode 2: A = g_fvh,                 Y = g_hg (half), no stats/bias
#define SMEM_DYN 53248
__global__ void __launch_bounds__(256) gemm_h(const float* __restrict__ bias, int M, int mode)
{
    extern __shared__ char smc[];
    __half* stg = (__half*)smc;     // epilogue stage reuse: [128][136] halfs
    __shared__ float s_bias[256], s_cs1[256], s_cs2[256];

    const int tid = threadIdx.x;
    const int w = tid >> 5, l = tid & 31;
    const int wm = w >> 2, wn = w & 3;
    const int g = l >> 2, t = l & 3;
    const int z = blockIdx.z;
    const int ntile = blockIdx.x;
    const int n0 = ntile * 256;
    const int m0 = blockIdx.y * 128;

    __half* Y;
    int sel = 0;
    if (mode == 0)      { Y = g_h; }
    else if (mode == 1) { Y = g_y; sel = c_sel[z]; }
    else                { Y = g_hg; }

    s_bias[tid] = bias ? bias[(size_t)z * 512 + n0 + tid] : 0.f;
    s_cs1[tid] = 0.f;
    s_cs2[tid] = 0.f;

    // A loader: thread = (row lrow 0..127, k-half hk covering 16 channels = 32B)
    const int lrow = tid >> 1, hk = tid & 1;
    const __half* arow;
    {
        int m = m0 + lrow;
        if (mode == 0) {
            int bt = m / 21, s = m - bt * 21;
            arow = g_xh + ((size_t)bt * 49 + c_start[z] + s) * 512;
        } else if (mode == 1) {
            arow = g_h + ((size_t)sel * 21504 + m) * 512;
        } else {
            arow = g_fvh + (size_t)m * 512;
        }
    }
    const int zw = (mode == 0) ? z : (mode == 1) ? 4 + z : 16;
    const char* gB = (const char*)g_wt + (size_t)zw * 524288 + (size_t)ntile * 262144;
    const uint32_t sBase = smem_u32(smc);
    const uint32_t adst = sBase + lrow * 80 + hk * 32;
    const uint32_t bdst = sBase + 20480 + tid * 16;

    float d[4][8][4];
    #pragma unroll
    for (int mf = 0; mf < 4; ++mf)
        #pragma unroll
        for (int nf = 0; nf < 8; ++nf)
            #pragma unroll
            for (int q = 0; q < 4; ++q) d[mf][nf][q] = 0.f;

    auto loadAB = [&](int kt, int bf) {
        const char* as = (const char*)(arow + kt * 32 + hk * 16);
        uint32_t ad = adst + bf * 10240;
        CP_ASYNC16(ad, as);
        CP_ASYNC16(ad + 16, as + 16);
        const char* bs = gB + (size_t)kt * 16384 + tid * 16;
        uint32_t bd = bdst + bf * 16384;
        #pragma unroll
        for (int i = 0; i < 4; ++i)
            CP_ASYNC16(bd + i * 4096, bs + i * 4096);
        CP_COMMIT();
    };

    // prologue
    loadAB(0, 0);
    CP_WAIT0();
    __syncthreads();

    for (int kt = 0; kt < 16; ++kt) {
        const int buf = kt & 1;
        if (kt < 15) loadAB(kt + 1, buf ^ 1);
        const char* Ab = smc + buf * 10240;
        const char* Bb = smc + 20480 + buf * 16384;
        #pragma unroll
        for (int kb2 = 0; kb2 < 2; ++kb2) {
            uint32_t af[4][4];
            uint4 bv[4];
            #pragma unroll
            for (int mf = 0; mf < 4; ++mf) {
                int off = (wm * 64 + mf * 16 + g) * 80 + kb2 * 32 + t * 4;
                af[mf][0] = *(const uint32_t*)(Ab + off);
                af[mf][1] = *(const uint32_t*)(Ab + off + 640);
                af[mf][2] = *(const uint32_t*)(Ab + off + 16);
                af[mf][3] = *(const uint32_t*)(Ab + off + 656);
            }
            #pragma unroll
            for (int j = 0; j < 4; ++j)
                bv[j] = *(const uint4*)(Bb + ((kb2 * 16 + wn * 4 + j) * 32 + l) * 16);
            #pragma unroll
            for (int mf = 0; mf < 4; ++mf) {
                #pragma unroll
                for (int j = 0; j < 4; ++j) {
                    MMA_F16(d[mf][j * 2],     af[mf], bv[j].x, bv[j].y);
                    MMA_F16(d[mf][j * 2 + 1], af[mf], bv[j].z, bv[j].w);
                }
            }
        }
        if (kt < 15) CP_WAIT0();
        __syncthreads();
    }

    // ---- epilogue: two 128-col passes, half stage, fp32 stats ----
    #pragma unroll
    for (int ph = 0; ph < 2; ++ph) {
        if ((wn >> 1) == ph) {
            float cs[16], cq[16];
            #pragma unroll
            for (int i = 0; i < 16; ++i) { cs[i] = 0.f; cq[i] = 0.f; }
            #pragma unroll
            for (int mf = 0; mf < 4; ++mf) {
                #pragma unroll
                for (int nf = 0; nf < 8; ++nf) {
                    int colL = (wn & 1) * 64 + nf * 8 + 2 * t;
                    int colG = wn * 64 + nf * 8 + 2 * t;
                    float b0 = s_bias[colG], b1 = s_bias[colG + 1];
                    int r0 = wm * 64 + mf * 16 + g;
                    float v00 = d[mf][nf][0] + b0;
                    float v01 = d[mf][nf][1] + b1;
                    float v10 = d[mf][nf][2] + b0;
                    float v11 = d[mf][nf][3] + b1;
                    *(__half2*)&stg[r0 * 136 + colL]       = __floats2half2_rn(v00, v01);
                    *(__half2*)&stg[(r0 + 8) * 136 + colL] = __floats2half2_rn(v10, v11);
                    cs[nf * 2]     += v00 + v10;
                    cq[nf * 2]     += v00 * v00 + v10 * v10;
                    cs[nf * 2 + 1] += v01 + v11;
                    cq[nf * 2 + 1] += v01 * v01 + v11 * v11;
                }
            }
            if (mode != 2) {
                #pragma unroll
                for (int i = 0; i < 16; ++i) {
                    #pragma unroll
                    for (int msk = 4; msk <= 16; msk <<= 1) {
                        cs[i] += __shfl_xor_sync(0xFFFFFFFFu, cs[i], msk);
                        cq[i] += __shfl_xor_sync(0xFFFFFFFFu, cq[i], msk);
                    }
                }
                if (l < 4) {
                    #pragma unroll
                    for (int nf = 0; nf < 8; ++nf) {
                        int col = wn * 64 + nf * 8 + 2 * l;
                        atomicAdd(&s_cs1[col],     cs[nf * 2]);
                        atomicAdd(&s_cs2[col],     cq[nf * 2]);
                        atomicAdd(&s_cs1[col + 1], cs[nf * 2 + 1]);
                        atomicAdd(&s_cs2[col + 1], cq[nf * 2 + 1]);
                    }
                }
            }
        }
        __syncthreads();
        {
            int r = tid >> 1, hh = tid & 1;
            __half* yrow = Y + ((size_t)z * M + m0 + r) * 512 + n0 + ph * 128 + hh * 64;
            const __half* srow = stg + r * 136 + hh * 64;
            #pragma unroll
            for (int q = 0; q < 8; ++q)
                *(uint4*)(yrow + q * 8) = *(const uint4*)(srow + q * 8);
        }
        __syncthreads();
    }
    if (mode != 2) {
        float* stats = (mode == 0) ? g_rstats : g_cstats;
        atomicAdd(&stats[((size_t)z * 512 + n0 + tid) * 2],     s_cs1[tid]);
        atomicAdd(&stats[((size_t)z * 512 + n0 + tid) * 2 + 1], s_cs2[tid]);
    }
}

// ---------------- hmean: finalize region BN, activate g_h IN PLACE (fp16), seq-mean ----------------
__global__ void hmean_kernel(const float* __restrict__ gamma, const float* __restrict__ beta) {
    const int bt = blockIdx.x, r = blockIdx.y;
    const int c = threadIdx.x * 8;    // 64 threads
    float sc[8], sh[8];
    #pragma unroll
    for (int j = 0; j < 8; ++j) {
        int i = r * 512 + c + j;
        float mean = g_rstats[i * 2] * (1.f / 21504.f);
        float var  = g_rstats[i * 2 + 1] * (1.f / 21504.f) - mean * mean;
        float rstd = rsqrtf(var + EPSF);
        sc[j] = gamma[i] * rstd;
        sh[j] = beta[i] - mean * sc[j];
    }
    size_t base = ((size_t)r * 21504 + (size_t)bt * 21) * 512 + c;
    float acc[8] = {0.f, 0.f, 0.f, 0.f, 0.f, 0.f, 0.f, 0.f};
    #pragma unroll
    for (int s = 0; s < 21; ++s) {
        uint4 u = *(const uint4*)(g_h + base + (size_t)s * 512);
        const __half2* hp = (const __half2*)&u;
        float av[8];
        #pragma unroll
        for (int p = 0; p < 4; ++p) {
            float2 f = __half22float2(hp[p]);
            av[p * 2]     = fmaxf(fmaf(f.x, sc[p * 2],     sh[p * 2]),     0.f);
            av[p * 2 + 1] = fmaxf(fmaf(f.y, sc[p * 2 + 1], sh[p * 2 + 1]), 0.f);
            acc[p * 2]     += av[p * 2];
            acc[p * 2 + 1] += av[p * 2 + 1];
        }
        uint4 o;
        o.x = f2h2(av[0], av[1]); o.y = f2h2(av[2], av[3]);
        o.z = f2h2(av[4], av[5]); o.w = f2h2(av[6], av[7]);
        *(uint4*)(g_h + base + (size_t)s * 512) = o;
    }
    float* dst = g_hmean + ((size_t)r * 1024 + bt) * 512 + c;
    #pragma unroll
    for (int j = 0; j < 8; ++j) dst[j] = acc[j] * (1.f / 21.f);
}

// ---------------- BN+ReLU on y + seq-mean -> f_v (fp32 + fp16) ----------------
__global__ void bn_y_kernel(const float* __restrict__ gamma, const float* __restrict__ beta) {
    const int bt = blockIdx.x, n = blockIdx.y;
    const int c = threadIdx.x * 8;    // 64 threads
    float sc[8], sh[8];
    #pragma unroll
    for (int j = 0; j < 8; ++j) {
        int i = n * 512 + c + j;
        float mean = g_cstats[i * 2] * (1.f / 21504.f);
        float var  = g_cstats[i * 2 + 1] * (1.f / 21504.f) - mean * mean;
        float rstd = rsqrtf(var + EPSF);
        sc[j] = gamma[i] * rstd;
        sh[j] = beta[i] - mean * sc[j];
    }
    size_t base = ((size_t)n * 21504 + (size_t)bt * 21) * 512 + c;
    float acc[8] = {0.f, 0.f, 0.f, 0.f, 0.f, 0.f, 0.f, 0.f};
    #pragma unroll
    for (int s = 0; s < 21; ++s) {
        uint4 u = *(const uint4*)(g_y + base + (size_t)s * 512);
        const __half2* hp = (const __half2*)&u;
        #pragma unroll
        for (int p = 0; p < 4; ++p) {
            float2 f = __half22float2(hp[p]);
            acc[p * 2]     += fmaxf(fmaf(f.x, sc[p * 2],     sh[p * 2]),     0.f);
            acc[p * 2 + 1] += fmaxf(fmaf(f.y, sc[p * 2 + 1], sh[p * 2 + 1]), 0.f);
        }
    }
    size_t didx = ((size_t)bt * 12 + n) * 512 + c;
    float* dst = g_fv + didx;
    #pragma unroll
    for (int j = 0; j < 8; ++j) {
        acc[j] *= (1.f / 21.f);
        dst[j] = acc[j];
    }
    uint4 o;
    o.x = f2h2(acc[0], acc[1]); o.y = f2h2(acc[2], acc[3]);
    o.z = f2h2(acc[4], acc[5]); o.w = f2h2(acc[6], acc[7]);
    *(uint4*)(g_fvh + didx) = o;
}

// ---------------- prediction heads ----------------
__global__ void preds_kernel(const float* __restrict__ upW,  const float* __restrict__ upb,
                             const float* __restrict__ midW, const float* __restrict__ midb,
                             const float* __restrict__ d1W,  const float* __restrict__ d1b,
                             const float* __restrict__ d2W,  const float* __restrict__ d2b,
                             float* __restrict__ out)
{
    __shared__ float smh[2048];
    const int bt = blockIdx.x;
    for (int i = threadIdx.x; i < 2048; i += 256)
        smh[i] = g_hmean[((size_t)(i >> 9) * 1024 + bt) * 512 + (i & 511)];
    __syncthreads();
    const int w = threadIdx.x >> 5, l = threadIdx.x & 31;
    for (int o = w; o < 42; o += 8) {
        int r, j, nout;
        const float* Wp;
        const float* bp;
        float* op;
        if (o < 16)      { r = 0; j = o;      Wp = upW;  bp = upb;  op = out + (size_t)bt * 16;         nout = 16; }
        else if (o < 18) { r = 1; j = o - 16; Wp = midW; bp = midb; op = out + 16384 + (size_t)bt * 2;  nout = 2;  }
        else if (o < 26) { r = 2; j = o - 18; Wp = d1W;  bp = d1b;  op = out + 18432 + (size_t)bt * 8;  nout = 8;  }
        else             { r = 3; j = o - 26; Wp = d2W;  bp = d2b;  op = out + 26624 + (size_t)bt * 16; nout = 16; }
        float a = 0.f;
        for (int c = l; c < 512; c += 32) a += smh[r * 512 + c] * Wp[c * nout + j];
        #pragma unroll
        for (int off = 16; off; off >>= 1) a += __shfl_xor_sync(0xFFFFFFFFu, a, off);
        if (l == 0) op[j] = a + bp[j];
    }
}

// ---------------- GAT (fp16 hg read) ----------------
__global__ void gat_kernel(const float* __restrict__ adj_mask,
                           const float* __restrict__ al,
                           const float* __restrict__ ar)
{
    __shared__ float hs[12 * 512];
    __shared__ float alp[12], arp[12];
    __shared__ float att[144];
    const int bt = blockIdx.x;
    const __half* hgb = g_hg + (size_t)bt * 12 * 512;
    for (int i = threadIdx.x; i < 6144; i += 256) hs[i] = __half2float(hgb[i]);
    __syncthreads();
    const int w = threadIdx.x >> 5, lane = threadIdx.x & 31;
    for (int dd = w; dd < 24; dd += 8) {
        int node = dd >> 1;
        const float* vec = (dd & 1) ? ar : al;
        float s = 0.f;
        for (int c = lane; c < 512; c += 32) s += hs[node * 512 + c] * vec[c];
        #pragma unroll
        for (int o = 16; o; o >>= 1) s += __shfl_xor_sync(0xFFFFFFFFu, s, o);
        if (lane == 0) { if (dd & 1) arp[node] = s; else alp[node] = s; }
    }
    __syncthreads();
    if (threadIdx.x < 144) {
        int i = threadIdx.x / 12, j = threadIdx.x % 12;
        float a = c_adj[threadIdx.x] * adj_mask[(size_t)bt * 144 + threadIdx.x] + (i == j ? 1.f : 0.f);
        float e = alp[i] + arp[j];
        e = (e > 0.f) ? e : 0.2f * e;
        att[threadIdx.x] = (a > 0.1f) ? e : -1e9f;
    }
    __syncthreads();
    if (threadIdx.x < 12) {
        int i = threadIdx.x;
        float mx = -1e30f;
        for (int j = 0; j < 12; ++j) mx = fmaxf(mx, att[i * 12 + j]);
        float tmp[12];
        float sum = 0.f;
        for (int j = 0; j < 12; ++j) { float ev = expf(att[i * 12 + j] - mx); tmp[j] = ev; sum += ev; }
        float invs = 1.f / sum;
        for (int j = 0; j < 12; ++j) att[i * 12 + j] = tmp[j] * invs;
    }
    __syncthreads();
    const float* fvb = g_fv + (size_t)bt * 12 * 512;
    float* gb = g_gat + (size_t)bt * 12 * 512;
    for (int idx = threadIdx.x; idx < 6144; idx += 256) {
        int n = idx >> 9, c = idx & 511;
        float s = fvb[idx];
        #pragma unroll
        for (int j = 0; j < 12; ++j) s += att[n * 12 + j] * hs[j * 512 + c];
        gb[idx] = s;
    }
}

// ---------------- temporal conv, register sliding window, + BN stats ----------------
__global__ void tconv_kernel(const float* __restrict__ W, const float* __restrict__ bias) {
    const int b = blockIdx.x, n = blockIdx.y;
    const int c = threadIdx.x;
    float in[32];
    #pragma unroll
    for (int t = 0; t < 32; ++t)
        in[t] = g_gat[(((size_t)(b * 32 + t)) * 12 + n) * 512 + c];
    const float* wp = W + ((size_t)n * 512 + c) * 5;
    float w0 = wp[0], w1 = wp[1], w2 = wp[2], w3 = wp[3], w4 = wp[4];
    const float bv = bias[n * 512 + c];
    float s = 0.f, s2 = 0.f;
    #pragma unroll
    for (int t = 0; t < 32; ++t) {
        float v = bv;
        if (t >= 2)      v = fmaf(in[t - 2], w0, v);
        if (t >= 1)      v = fmaf(in[t - 1], w1, v);
        v = fmaf(in[t], w2, v);
        if (t + 1 < 32)  v = fmaf(in[t + 1], w3, v);
        if (t + 2 < 32)  v = fmaf(in[t + 2], w4, v);
        g_v[(((size_t)(b * 32 + t)) * 12 + n) * 512 + c] = v;
        s += v;
        s2 = fmaf(v, v, s2);
    }
    #pragma unroll
    for (int o = 16; o; o >>= 1) {
        s  += __shfl_xor_sync(0xFFFFFFFFu, s, o);
        s2 += __shfl_xor_sync(0xFFFFFFFFu, s2, o);
    }
    __shared__ float wsum[16], wsq[16];
    const int lane = c & 31, wrp = c >> 5;
    if (lane == 0) { wsum[wrp] = s; wsq[wrp] = s2; }
    __syncthreads();
    if (c == 0) {
        float a = 0.f, b2 = 0.f;
        #pragma unroll
        for (int i = 0; i < 16; ++i) { a += wsum[i]; b2 += wsq[i]; }
        atomicAdd(&g_tstats[n * 2],     a);
        atomicAdd(&g_tstats[n * 2 + 1], b2);
    }
}

// ---------------- final per-class BN + ReLU (float4) ----------------
__global__ void tbn_kernel(const float* __restrict__ gamma, const float* __restrict__ beta,
                           float* __restrict__ out) {
    const int bt = blockIdx.x, n = blockIdx.y;
    const int c = threadIdx.x * 4;
    const float cnt = 1.f / (1024.f * 512.f);
    const float mean = g_tstats[n * 2] * cnt;
    const float var  = g_tstats[n * 2 + 1] * cnt - mean * mean;
    const float rstd = rsqrtf(var + EPSF);
    const float sc = gamma[n] * rstd;
    const float sh = beta[n] - mean * sc;
    size_t idx = ((size_t)bt * 12 + n) * 512 + c;
    float4 v = *(const float4*)(g_v + idx);
    v.x = fmaxf(fmaf(v.x, sc, sh), 0.f);
    v.y = fmaxf(fmaf(v.y, sc, sh), 0.f);
    v.z = fmaxf(fmaf(v.z, sc, sh), 0.f);
    v.w = fmaxf(fmaf(v.w, sc, sh), 0.f);
    *(float4*)(out + 43008 + idx) = v;
}

// ---------------- launch ----------------
extern "C" void kernel_launch(void* const* d_in, const int* in_sizes, int n_in,
                              void* d_out, int out_size)
{
    const float* x            = (const float*)d_in[0];
    const float* adj_mask     = (const float*)d_in[1];
    const float* region_W     = (const float*)d_in[2];
    const float* region_b     = (const float*)d_in[3];
    const float* region_gamma = (const float*)d_in[4];
    const float* region_beta  = (const float*)d_in[5];
    const float* upfc_W  = (const float*)d_in[6];
    const float* upfc_b  = (const float*)d_in[7];
    const float* midfc_W = (const float*)d_in[8];
    const float* midfc_b = (const float*)d_in[9];
    const float* d1fc_W  = (const float*)d_in[10];
    const float* d1fc_b  = (const float*)d_in[11];
    const float* d2fc_W  = (const float*)d_in[12];
    const float* d2fc_b  = (const float*)d_in[13];
    const float* class_W     = (const float*)d_in[14];
    const float* class_b     = (const float*)d_in[15];
    const float* class_gamma = (const float*)d_in[16];
    const float* class_beta  = (const float*)d_in[17];
    const float* gat_W  = (const float*)d_in[18];
    const float* gat_al = (const float*)d_in[19];
    const float* gat_ar = (const float*)d_in[20];
    const float* tconv_W   = (const float*)d_in[21];
    const float* tconv_b   = (const float*)d_in[22];
    const float* tbn_gamma = (const float*)d_in[23];
    const float* tbn_beta  = (const float*)d_in[24];
    float* out = (float*)d_out;

    cudaFuncSetAttribute(gemm_h, cudaFuncAttributeMaxDynamicSharedMemorySize, SMEM_DYN);

    prep_kernel<<<12544, 256>>>(x);
    pack_wt<<<dim3(32, 32, 17), 256>>>(region_W, class_W, gat_W);
    gemm_h<<<dim3(2, 168, 4), 256, SMEM_DYN>>>(region_b, 21504, 0);
    hmean_kernel<<<dim3(1024, 4), 64>>>(region_gamma, region_beta);
    gemm_h<<<dim3(2, 168, 12), 256, SMEM_DYN>>>(class_b, 21504, 1);
    preds_kernel<<<1024, 256>>>(upfc_W, upfc_b, midfc_W, midfc_b,
                                d1fc_W, d1fc_b, d2fc_W, d2fc_b, out);
    bn_y_kernel<<<dim3(1024, 12), 64>>>(class_gamma, class_beta);
    gemm_h<<<dim3(2, 96, 1), 256, SMEM_DYN>>>(nullptr, 12288, 2);
    gat_kernel<<<1024, 256>>>(adj_mask, gat_al, gat_ar);
    tconv_kernel<<<dim3(32, 12), 512>>>(tconv_W, tconv_b);
    tbn_kernel<<<dim3(1024, 12), 128>>>(tbn_gamma, tbn_beta, out);
}

// round 11
// speedup vs baseline: 3.6871x; 1.0041x over previous
#include <cuda_runtime.h>
#include <cuda_fp16.h>
#include <cstdint>

#define EPSF 1e-5f

// ---------------- scratch (static device globals; no allocation) ----------------
__device__ __half g_xh[(size_t)1024 * 49 * 512];    // fp16 input
__device__ __half g_h[(size_t)4 * 21504 * 512];     // region GEMM out; activated fp16 in place
__device__ __half g_y[(size_t)12 * 21504 * 512];    // class GEMM out (pre-BN, fp16)
__device__ __half g_wt[(size_t)17 * 512 * 512];     // fragment-packed fp16 weights
__device__ __half g_hg[(size_t)1024 * 12 * 512];    // GAT projection (fp16)
__device__ __half g_fvh[(size_t)1024 * 12 * 512];   // f_v fp16 (GEMM operand)
__device__ float g_hmean[(size_t)4 * 1024 * 512];   // seq-mean of activated h
__device__ float g_fv[(size_t)1024 * 12 * 512];     // f_v fp32 (GAT residual)
__device__ float g_gat[(size_t)1024 * 12 * 512];    // GAT output
__device__ float g_v[(size_t)1024 * 12 * 512];      // temporal conv out (pre-BN)
__device__ float g_rstats[4 * 512 * 2];
__device__ float g_cstats[12 * 512 * 2];
__device__ float g_tstats[24];

__constant__ int c_sel[12]  = {0, 0, 0, 1, 0, 3, 2, 2, 2, 3, 3, 3};
__constant__ int c_start[4] = {0, 14, 28, 28};
__constant__ float c_adj[144] = {
    0,0,0,1,0,1,1,1,1,1,1,1,
    0,0,0,1,0,1,1,1,1,1,1,1,
    0,0,0,1,0,1,1,1,1,1,1,1,
    1,1,1,0,1,1,1,1,1,1,1,1,
    0,0,0,1,0,1,1,1,1,1,1,1,
    1,1,1,1,1,0,1,1,1,0,0,0,
    1,1,1,1,1,1,0,0,0,1,1,1,
    1,1,1,1,1,1,0,0,0,1,1,1,
    1,1,1,1,1,1,0,0,0,1,1,1,
    1,1,1,1,1,0,1,1,1,0,0,0,
    1,1,1,1,1,0,1,1,1,0,0,0,
    1,1,1,1,1,0,1,1,1,0,0,0
};

// ---------------- helpers ----------------
__device__ __forceinline__ uint32_t smem_u32(const void* p) {
    uint32_t a;
    asm("{ .reg .u64 t; cvta.to.shared.u64 t, %1; cvt.u32.u64 %0, t; }" : "=r"(a) : "l"(p));
    return a;
}
__device__ __forceinline__ uint32_t f2h2(float a, float b) {
    __half2 h = __floats2half2_rn(a, b);
    return *(uint32_t*)&h;
}
#define CP_ASYNC16(dst, src) \
    asm volatile("cp.async.ca.shared.global [%0], [%1], 16;" :: "r"(dst), "l"(src) : "memory")
#define CP_COMMIT() asm volatile("cp.async.commit_group;" ::: "memory")
#define CP_WAIT0()  asm volatile("cp.async.wait_group 0;" ::: "memory")

#define MMA_F16(D, A, B0, B1) \
    asm volatile("mma.sync.aligned.m16n8k16.row.col.f32.f16.f16.f32 " \
        "{%0,%1,%2,%3}, {%4,%5,%6,%7}, {%8,%9}, {%0,%1,%2,%3};" \
        : "+f"((D)[0]), "+f"((D)[1]), "+f"((D)[2]), "+f"((D)[3]) \
        : "r"((A)[0]), "r"((A)[1]), "r"((A)[2]), "r"((A)[3]), \
          "r"(B0), "r"(B1))

// ---------------- prep: x -> fp16, zero stats ----------------
__global__ void prep_kernel(const float* __restrict__ x) {
    size_t base = ((size_t)blockIdx.x * 256 + threadIdx.x) * 8;
    float4 f0 = *(const float4*)(x + base);
    float4 f1 = *(const float4*)(x + base + 4);
    uint4 u;
    u.x = f2h2(f0.x, f0.y); u.y = f2h2(f0.z, f0.w);
    u.z = f2h2(f1.x, f1.y); u.w = f2h2(f1.z, f1.w);
    *(uint4*)(g_xh + base) = u;
    if (blockIdx.x == 0) {
        for (int j = threadIdx.x; j < 4 * 512 * 2; j += 256)  g_rstats[j] = 0.f;
        for (int j = threadIdx.x; j < 12 * 512 * 2; j += 256) g_cstats[j] = 0.f;
        if (threadIdx.x < 24) g_tstats[threadIdx.x] = 0.f;
    }
}

// ---------------- weight fragment-pack to fp16 (z range via z0) ----------------
__global__ void pack_wt(const float* __restrict__ rW,
                        const float* __restrict__ cW,
                        const float* __restrict__ gW, int z0) {
    __shared__ float tile[16][17];
    const int z = blockIdx.z + z0;
    const int npg = blockIdx.y;
    const int kbg = blockIdx.x;
    const float* src = (z < 4) ? rW + (size_t)z * 262144
                     : (z < 16) ? cW + (size_t)(z - 4) * 262144 : gW;
    const int i = threadIdx.x;
    {
        int k_l = i >> 4, n_l = i & 15;
        tile[k_l][n_l] = src[(size_t)(kbg * 16 + k_l) * 512 + npg * 16 + n_l];
    }
    __syncthreads();
    const int l = i >> 3, rem = i & 7;
    const int sub = rem >> 2, reg = (rem >> 1) & 1, hi = rem & 1;
    const int g = l >> 2, t = l & 3;
    const int k_l = reg * 8 + t * 2 + hi;
    const int n_l = sub * 8 + g;
    const int ntile = npg >> 4, p = npg & 15;
    size_t dst = ((((size_t)z * 2 + ntile) * 32 + kbg) * 16 + p) * 256 + i;
    g_wt[dst] = __float2half_rn(tile[k_l][n_l]);
}

// ================= fp16 mma.sync GEMM: block 128x256, 8 warps x (64x64), KC=32 =================
#define SMEM_DYN 53248
__global__ void __launch_bounds__(256) gemm_h(const float* __restrict__ bias, int M, int mode)
{
    extern __shared__ char smc[];
    __half* stg = (__half*)smc;
    __shared__ float s_bias[256], s_cs1[256], s_cs2[256];

    const int tid = threadIdx.x;
    const int w = tid >> 5, l = tid & 31;
    const int wm = w >> 2, wn = w & 3;
    const int g = l >> 2, t = l & 3;
    const int z = blockIdx.z;
    const int ntile = blockIdx.x;
    const int n0 = ntile * 256;
    const int m0 = blockIdx.y * 128;

    __half* Y;
    int sel = 0;
    if (mode == 0)      { Y = g_h; }
    else if (mode == 1) { Y = g_y; sel = c_sel[z]; }
    else                { Y = g_hg; }

    s_bias[tid] = bias ? bias[(size_t)z * 512 + n0 + tid] : 0.f;
    s_cs1[tid] = 0.f;
    s_cs2[tid] = 0.f;

    const int lrow = tid >> 1, hk = tid & 1;
    const __half* arow;
    {
        int m = m0 + lrow;
        if (mode == 0) {
            int bt = m / 21, s = m - bt * 21;
            arow = g_xh + ((size_t)bt * 49 + c_start[z] + s) * 512;
        } else if (mode == 1) {
            arow = g_h + ((size_t)sel * 21504 + m) * 512;
        } else {
            arow = g_fvh + (size_t)m * 512;
        }
    }
    const int zw = (mode == 0) ? z : (mode == 1) ? 4 + z : 16;
    const char* gB = (const char*)g_wt + (size_t)zw * 524288 + (size_t)ntile * 262144;
    const uint32_t sBase = smem_u32(smc);
    const uint32_t adst = sBase + lrow * 80 + hk * 32;
    const uint32_t bdst = sBase + 20480 + tid * 16;

    float d[4][8][4];
    #pragma unroll
    for (int mf = 0; mf < 4; ++mf)
        #pragma unroll
        for (int nf = 0; nf < 8; ++nf)
            #pragma unroll
            for (int q = 0; q < 4; ++q) d[mf][nf][q] = 0.f;

    auto loadAB = [&](int kt, int bf) {
        const char* as = (const char*)(arow + kt * 32 + hk * 16);
        uint32_t ad = adst + bf * 10240;
        CP_ASYNC16(ad, as);
        CP_ASYNC16(ad + 16, as + 16);
        const char* bs = gB + (size_t)kt * 16384 + tid * 16;
        uint32_t bd = bdst + bf * 16384;
        #pragma unroll
        for (int i = 0; i < 4; ++i)
            CP_ASYNC16(bd + i * 4096, bs + i * 4096);
        CP_COMMIT();
    };

    loadAB(0, 0);
    CP_WAIT0();
    __syncthreads();

    for (int kt = 0; kt < 16; ++kt) {
        const int buf = kt & 1;
        if (kt < 15) loadAB(kt + 1, buf ^ 1);
        const char* Ab = smc + buf * 10240;
        const char* Bb = smc + 20480 + buf * 16384;
        #pragma unroll
        for (int kb2 = 0; kb2 < 2; ++kb2) {
            uint32_t af[4][4];
            uint4 bv[4];
            #pragma unroll
            for (int mf = 0; mf < 4; ++mf) {
                int off = (wm * 64 + mf * 16 + g) * 80 + kb2 * 32 + t * 4;
                af[mf][0] = *(const uint32_t*)(Ab + off);
                af[mf][1] = *(const uint32_t*)(Ab + off + 640);
                af[mf][2] = *(const uint32_t*)(Ab + off + 16);
                af[mf][3] = *(const uint32_t*)(Ab + off + 656);
            }
            #pragma unroll
            for (int j = 0; j < 4; ++j)
                bv[j] = *(const uint4*)(Bb + ((kb2 * 16 + wn * 4 + j) * 32 + l) * 16);
            #pragma unroll
            for (int mf = 0; mf < 4; ++mf) {
                #pragma unroll
                for (int j = 0; j < 4; ++j) {
                    MMA_F16(d[mf][j * 2],     af[mf], bv[j].x, bv[j].y);
                    MMA_F16(d[mf][j * 2 + 1], af[mf], bv[j].z, bv[j].w);
                }
            }
        }
        if (kt < 15) CP_WAIT0();
        __syncthreads();
    }

    #pragma unroll
    for (int ph = 0; ph < 2; ++ph) {
        if ((wn >> 1) == ph) {
            float cs[16], cq[16];
            #pragma unroll
            for (int i = 0; i < 16; ++i) { cs[i] = 0.f; cq[i] = 0.f; }
            #pragma unroll
            for (int mf = 0; mf < 4; ++mf) {
                #pragma unroll
                for (int nf = 0; nf < 8; ++nf) {
                    int colL = (wn & 1) * 64 + nf * 8 + 2 * t;
                    int colG = wn * 64 + nf * 8 + 2 * t;
                    float b0 = s_bias[colG], b1 = s_bias[colG + 1];
                    int r0 = wm * 64 + mf * 16 + g;
                    float v00 = d[mf][nf][0] + b0;
                    float v01 = d[mf][nf][1] + b1;
                    float v10 = d[mf][nf][2] + b0;
                    float v11 = d[mf][nf][3] + b1;
                    *(__half2*)&stg[r0 * 136 + colL]       = __floats2half2_rn(v00, v01);
                    *(__half2*)&stg[(r0 + 8) * 136 + colL] = __floats2half2_rn(v10, v11);
                    cs[nf * 2]     += v00 + v10;
                    cq[nf * 2]     += v00 * v00 + v10 * v10;
                    cs[nf * 2 + 1] += v01 + v11;
                    cq[nf * 2 + 1] += v01 * v01 + v11 * v11;
                }
            }
            if (mode != 2) {
                #pragma unroll
                for (int i = 0; i < 16; ++i) {
                    #pragma unroll
                    for (int msk = 4; msk <= 16; msk <<= 1) {
                        cs[i] += __shfl_xor_sync(0xFFFFFFFFu, cs[i], msk);
                        cq[i] += __shfl_xor_sync(0xFFFFFFFFu, cq[i], msk);
                    }
                }
                if (l < 4) {
                    #pragma unroll
                    for (int nf = 0; nf < 8; ++nf) {
                        int col = wn * 64 + nf * 8 + 2 * l;
                        atomicAdd(&s_cs1[col],     cs[nf * 2]);
                        atomicAdd(&s_cs2[col],     cq[nf * 2]);
                        atomicAdd(&s_cs1[col + 1], cs[nf * 2 + 1]);
                        atomicAdd(&s_cs2[col + 1], cq[nf * 2 + 1]);
                    }
                }
            }
        }
        __syncthreads();
        {
            int r = tid >> 1, hh = tid & 1;
            __half* yrow = Y + ((size_t)z * M + m0 + r) * 512 + n0 + ph * 128 + hh * 64;
            const __half* srow = stg + r * 136 + hh * 64;
            #pragma unroll
            for (int q = 0; q < 8; ++q)
                *(uint4*)(yrow + q * 8) = *(const uint4*)(srow + q * 8);
        }
        __syncthreads();
    }
    if (mode != 2) {
        float* stats = (mode == 0) ? g_rstats : g_cstats;
        atomicAdd(&stats[((size_t)z * 512 + n0 + tid) * 2],     s_cs1[tid]);
        atomicAdd(&stats[((size_t)z * 512 + n0 + tid) * 2 + 1], s_cs2[tid]);
    }
}

// ---------------- hmean: finalize region BN, activate g_h IN PLACE (fp16), seq-mean ----------------
__global__ void hmean_kernel(const float* __restrict__ gamma, const float* __restrict__ beta) {
    const int bt = blockIdx.x, r = blockIdx.y;
    const int c = threadIdx.x * 8;
    float sc[8], sh[8];
    #pragma unroll
    for (int j = 0; j < 8; ++j) {
        int i = r * 512 + c + j;
        float mean = g_rstats[i * 2] * (1.f / 21504.f);
        float var  = g_rstats[i * 2 + 1] * (1.f / 21504.f) - mean * mean;
        float rstd = rsqrtf(var + EPSF);
        sc[j] = gamma[i] * rstd;
        sh[j] = beta[i] - mean * sc[j];
    }
    size_t base = ((size_t)r * 21504 + (size_t)bt * 21) * 512 + c;
    float acc[8] = {0.f, 0.f, 0.f, 0.f, 0.f, 0.f, 0.f, 0.f};
    #pragma unroll
    for (int s = 0; s < 21; ++s) {
        uint4 u = *(const uint4*)(g_h + base + (size_t)s * 512);
        const __half2* hp = (const __half2*)&u;
        float av[8];
        #pragma unroll
        for (int p = 0; p < 4; ++p) {
            float2 f = __half22float2(hp[p]);
            av[p * 2]     = fmaxf(fmaf(f.x, sc[p * 2],     sh[p * 2]),     0.f);
            av[p * 2 + 1] = fmaxf(fmaf(f.y, sc[p * 2 + 1], sh[p * 2 + 1]), 0.f);
            acc[p * 2]     += av[p * 2];
            acc[p * 2 + 1] += av[p * 2 + 1];
        }
        uint4 o;
        o.x = f2h2(av[0], av[1]); o.y = f2h2(av[2], av[3]);
        o.z = f2h2(av[4], av[5]); o.w = f2h2(av[6], av[7]);
        *(uint4*)(g_h + base + (size_t)s * 512) = o;
    }
    float* dst = g_hmean + ((size_t)r * 1024 + bt) * 512 + c;
    #pragma unroll
    for (int j = 0; j < 8; ++j) dst[j] = acc[j] * (1.f / 21.f);
}

// ---------------- BN+ReLU on y + seq-mean -> f_v (fp32 + fp16) ----------------
__global__ void bn_y_kernel(const float* __restrict__ gamma, const float* __restrict__ beta) {
    const int bt = blockIdx.x, n = blockIdx.y;
    const int c = threadIdx.x * 8;
    float sc[8], sh[8];
    #pragma unroll
    for (int j = 0; j < 8; ++j) {
        int i = n * 512 + c + j;
        float mean = g_cstats[i * 2] * (1.f / 21504.f);
        float var  = g_cstats[i * 2 + 1] * (1.f / 21504.f) - mean * mean;
        float rstd = rsqrtf(var + EPSF);
        sc[j] = gamma[i] * rstd;
        sh[j] = beta[i] - mean * sc[j];
    }
    size_t base = ((size_t)n * 21504 + (size_t)bt * 21) * 512 + c;
    float acc[8] = {0.f, 0.f, 0.f, 0.f, 0.f, 0.f, 0.f, 0.f};
    #pragma unroll
    for (int s = 0; s < 21; ++s) {
        uint4 u = *(const uint4*)(g_y + base + (size_t)s * 512);
        const __half2* hp = (const __half2*)&u;
        #pragma unroll
        for (int p = 0; p < 4; ++p) {
            float2 f = __half22float2(hp[p]);
            acc[p * 2]     += fmaxf(fmaf(f.x, sc[p * 2],     sh[p * 2]),     0.f);
            acc[p * 2 + 1] += fmaxf(fmaf(f.y, sc[p * 2 + 1], sh[p * 2 + 1]), 0.f);
        }
    }
    size_t didx = ((size_t)bt * 12 + n) * 512 + c;
    float* dst = g_fv + didx;
    #pragma unroll
    for (int j = 0; j < 8; ++j) {
        acc[j] *= (1.f / 21.f);
        dst[j] = acc[j];
    }
    uint4 o;
    o.x = f2h2(acc[0], acc[1]); o.y = f2h2(acc[2], acc[3]);
    o.z = f2h2(acc[4], acc[5]); o.w = f2h2(acc[6], acc[7]);
    *(uint4*)(g_fvh + didx) = o;
}

// ---------------- prediction heads ----------------
__global__ void preds_kernel(const float* __restrict__ upW,  const float* __restrict__ upb,
                             const float* __restrict__ midW, const float* __restrict__ midb,
                             const float* __restrict__ d1W,  const float* __restrict__ d1b,
                             const float* __restrict__ d2W,  const float* __restrict__ d2b,
                             float* __restrict__ out)
{
    __shared__ float smh[2048];
    const int bt = blockIdx.x;
    for (int i = threadIdx.x; i < 2048; i += 256)
        smh[i] = g_hmean[((size_t)(i >> 9) * 1024 + bt) * 512 + (i & 511)];
    __syncthreads();
    const int w = threadIdx.x >> 5, l = threadIdx.x & 31;
    for (int o = w; o < 42; o += 8) {
        int r, j, nout;
        const float* Wp;
        const float* bp;
        float* op;
        if (o < 16)      { r = 0; j = o;      Wp = upW;  bp = upb;  op = out + (size_t)bt * 16;         nout = 16; }
        else if (o < 18) { r = 1; j = o - 16; Wp = midW; bp = midb; op = out + 16384 + (size_t)bt * 2;  nout = 2;  }
        else if (o < 26) { r = 2; j = o - 18; Wp = d1W;  bp = d1b;  op = out + 18432 + (size_t)bt * 8;  nout = 8;  }
        else             { r = 3; j = o - 26; Wp = d2W;  bp = d2b;  op = out + 26624 + (size_t)bt * 16; nout = 16; }
        float a = 0.f;
        for (int c = l; c < 512; c += 32) a += smh[r * 512 + c] * Wp[c * nout + j];
        #pragma unroll
        for (int off = 16; off; off >>= 1) a += __shfl_xor_sync(0xFFFFFFFFu, a, off);
        if (l == 0) op[j] = a + bp[j];
    }
}

// ---------------- GAT (fp16 hg read, half2 loads) ----------------
__global__ void gat_kernel(const float* __restrict__ adj_mask,
                           const float* __restrict__ al,
                           const float* __restrict__ ar)
{
    __shared__ float hs[12 * 512];
    __shared__ float alp[12], arp[12];
    __shared__ float att[144];
    const int bt = blockIdx.x;
    const __half2* hgb = (const __half2*)(g_hg + (size_t)bt * 12 * 512);
    for (int i = threadIdx.x; i < 3072; i += 256) {
        float2 f = __half22float2(hgb[i]);
        hs[i * 2] = f.x;
        hs[i * 2 + 1] = f.y;
    }
    __syncthreads();
    const int w = threadIdx.x >> 5, lane = threadIdx.x & 31;
    for (int dd = w; dd < 24; dd += 8) {
        int node = dd >> 1;
        const float* vec = (dd & 1) ? ar : al;
        float s = 0.f;
        for (int c = lane; c < 512; c += 32) s += hs[node * 512 + c] * vec[c];
        #pragma unroll
        for (int o = 16; o; o >>= 1) s += __shfl_xor_sync(0xFFFFFFFFu, s, o);
        if (lane == 0) { if (dd & 1) arp[node] = s; else alp[node] = s; }
    }
    __syncthreads();
    if (threadIdx.x < 144) {
        int i = threadIdx.x / 12, j = threadIdx.x % 12;
        float a = c_adj[threadIdx.x] * adj_mask[(size_t)bt * 144 + threadIdx.x] + (i == j ? 1.f : 0.f);
        float e = alp[i] + arp[j];
        e = (e > 0.f) ? e : 0.2f * e;
        att[threadIdx.x] = (a > 0.1f) ? e : -1e9f;
    }
    __syncthreads();
    if (threadIdx.x < 12) {
        int i = threadIdx.x;
        float mx = -1e30f;
        for (int j = 0; j < 12; ++j) mx = fmaxf(mx, att[i * 12 + j]);
        float tmp[12];
        float sum = 0.f;
        for (int j = 0; j < 12; ++j) { float ev = expf(att[i * 12 + j] - mx); tmp[j] = ev; sum += ev; }
        float invs = 1.f / sum;
        for (int j = 0; j < 12; ++j) att[i * 12 + j] = tmp[j] * invs;
    }
    __syncthreads();
    const float* fvb = g_fv + (size_t)bt * 12 * 512;
    float* gb = g_gat + (size_t)bt * 12 * 512;
    for (int idx = threadIdx.x; idx < 6144; idx += 256) {
        int n = idx >> 9, c = idx & 511;
        float s = fvb[idx];
        #pragma unroll
        for (int j = 0; j < 12; ++j) s += att[n * 12 + j] * hs[j * 512 + c];
        gb[idx] = s;
    }
}

// ---------------- temporal conv, register sliding window, + BN stats ----------------
__global__ void tconv_kernel(const float* __restrict__ W, const float* __restrict__ bias) {
    const int b = blockIdx.x, n = blockIdx.y;
    const int c = threadIdx.x;
    float in[32];
    #pragma unroll
    for (int t = 0; t < 32; ++t)
        in[t] = g_gat[(((size_t)(b * 32 + t)) * 12 + n) * 512 + c];
    const float* wp = W + ((size_t)n * 512 + c) * 5;
    float w0 = wp[0], w1 = wp[1], w2 = wp[2], w3 = wp[3], w4 = wp[4];
    const float bv = bias[n * 512 + c];
    float s = 0.f, s2 = 0.f;
    #pragma unroll
    for (int t = 0; t < 32; ++t) {
        float v = bv;
        if (t >= 2)      v = fmaf(in[t - 2], w0, v);
        if (t >= 1)      v = fmaf(in[t - 1], w1, v);
        v = fmaf(in[t], w2, v);
        if (t + 1 < 32)  v = fmaf(in[t + 1], w3, v);
        if (t + 2 < 32)  v = fmaf(in[t + 2], w4, v);
        g_v[(((size_t)(b * 32 + t)) * 12 + n) * 512 + c] = v;
        s += v;
        s2 = fmaf(v, v, s2);
    }
    #pragma unroll
    for (int o = 16; o; o >>= 1) {
        s  += __shfl_xor_sync(0xFFFFFFFFu, s, o);
        s2 += __shfl_xor_sync(0xFFFFFFFFu, s2, o);
    }
    __shared__ float wsum[16], wsq[16];
    const int lane = c & 31, wrp = c >> 5;
    if (lane == 0) { wsum[wrp] = s; wsq[wrp] = s2; }
    __syncthreads();
    if (c == 0) {
        float a = 0.f, b2 = 0.f;
        #pragma unroll
        for (int i = 0; i < 16; ++i) { a += wsum[i]; b2 += wsq[i]; }
        atomicAdd(&g_tstats[n * 2],     a);
        atomicAdd(&g_tstats[n * 2 + 1], b2);
    }
}

// ---------------- final per-class BN + ReLU (float4) ----------------
__global__ void tbn_kernel(const float* __restrict__ gamma, const float* __restrict__ beta,
                           float* __restrict__ out) {
    const int bt = blockIdx.x, n = blockIdx.y;
    const int c = threadIdx.x * 4;
    const float cnt = 1.f / (1024.f * 512.f);
    const float mean = g_tstats[n * 2] * cnt;
    const float var  = g_tstats[n * 2 + 1] * cnt - mean * mean;
    const float rstd = rsqrtf(var + EPSF);
    const float sc = gamma[n] * rstd;
    const float sh = beta[n] - mean * sc;
    size_t idx = ((size_t)bt * 12 + n) * 512 + c;
    float4 v = *(const float4*)(g_v + idx);
    v.x = fmaxf(fmaf(v.x, sc, sh), 0.f);
    v.y = fmaxf(fmaf(v.y, sc, sh), 0.f);
    v.z = fmaxf(fmaf(v.z, sc, sh), 0.f);
    v.w = fmaxf(fmaf(v.w, sc, sh), 0.f);
    *(float4*)(out + 43008 + idx) = v;
}

// ---------------- launch (fork/join on side streams) ----------------
extern "C" void kernel_launch(void* const* d_in, const int* in_sizes, int n_in,
                              void* d_out, int out_size)
{
    const float* x            = (const float*)d_in[0];
    const float* adj_mask     = (const float*)d_in[1];
    const float* region_W     = (const float*)d_in[2];
    const float* region_b     = (const float*)d_in[3];
    const float* region_gamma = (const float*)d_in[4];
    const float* region_beta  = (const float*)d_in[5];
    const float* upfc_W  = (const float*)d_in[6];
    const float* upfc_b  = (const float*)d_in[7];
    const float* midfc_W = (const float*)d_in[8];
    const float* midfc_b = (const float*)d_in[9];
    const float* d1fc_W  = (const float*)d_in[10];
    const float* d1fc_b  = (const float*)d_in[11];
    const float* d2fc_W  = (const float*)d_in[12];
    const float* d2fc_b  = (const float*)d_in[13];
    const float* class_W     = (const float*)d_in[14];
    const float* class_b     = (const float*)d_in[15];
    const float* class_gamma = (const float*)d_in[16];
    const float* class_beta  = (const float*)d_in[17];
    const float* gat_W  = (const float*)d_in[18];
    const float* gat_al = (const float*)d_in[19];
    const float* gat_ar = (const float*)d_in[20];
    const float* tconv_W   = (const float*)d_in[21];
    const float* tconv_b   = (const float*)d_in[22];
    const float* tbn_gamma = (const float*)d_in[23];
    const float* tbn_beta  = (const float*)d_in[24];
    float* out = (float*)d_out;

    cudaFuncSetAttribute(gemm_h, cudaFuncAttributeMaxDynamicSharedMemorySize, SMEM_DYN);

    cudaStream_t sd1, sd2;
    cudaStreamCreateWithFlags(&sd1, cudaStreamNonBlocking);
    cudaStreamCreateWithFlags(&sd2, cudaStreamNonBlocking);
    cudaEvent_t e0, e1, e2, e3, e4;
    cudaEventCreateWithFlags(&e0, cudaEventDisableTiming);
    cudaEventCreateWithFlags(&e1, cudaEventDisableTiming);
    cudaEventCreateWithFlags(&e2, cudaEventDisableTiming);
    cudaEventCreateWithFlags(&e3, cudaEventDisableTiming);
    cudaEventCreateWithFlags(&e4, cudaEventDisableTiming);

    // fork sd1 from main at the top
    cudaEventRecord(e0, 0);
    cudaStreamWaitEvent(sd1, e0, 0);

    // main: region weight pack + prep (both needed by region GEMM)
    prep_kernel<<<12544, 256>>>(x);
    pack_wt<<<dim3(32, 32, 4), 256>>>(region_W, class_W, gat_W, 0);
    // sd1: class + gat weight pack (needed only by class/gat GEMMs)
    pack_wt<<<dim3(32, 32, 13), 256, 0, sd1>>>(region_W, class_W, gat_W, 4);
    cudaEventRecord(e3, sd1);

    // main: region GEMM -> hmean
    gemm_h<<<dim3(2, 168, 4), 256, SMEM_DYN>>>(region_b, 21504, 0);
    hmean_kernel<<<dim3(1024, 4), 64>>>(region_gamma, region_beta);
    cudaEventRecord(e2, 0);

    // sd2: prediction heads (depends only on hmean), overlaps class GEMM
    cudaStreamWaitEvent(sd2, e2, 0);
    preds_kernel<<<1024, 256, 0, sd2>>>(upfc_W, upfc_b, midfc_W, midfc_b,
                                        d1fc_W, d1fc_b, d2fc_W, d2fc_b, out);
    cudaEventRecord(e4, sd2);

    // main: wait class/gat weights, then class GEMM onward
    cudaStreamWaitEvent(0, e3, 0);
    gemm_h<<<dim3(2, 168, 12), 256, SMEM_DYN>>>(class_b, 21504, 1);
    bn_y_kernel<<<dim3(1024, 12), 64>>>(class_gamma, class_beta);
    gemm_h<<<dim3(2, 96, 1), 256, SMEM_DYN>>>(nullptr, 12288, 2);
    gat_kernel<<<1024, 256>>>(adj_mask, gat_al, gat_ar);
    tconv_kernel<<<dim3(32, 12), 512>>>(tconv_W, tconv_b);
    tbn_kernel<<<dim3(1024, 12), 128>>>(tbn_gamma, tbn_beta, out);

    // join preds before returning
    cudaStreamWaitEvent(0, e4, 0);

    cudaEventDestroy(e0);
    cudaEventDestroy(e1);
    cudaEventDestroy(e2);
    cudaEventDestroy(e3);
    cudaEventDestroy(e4);
    cudaStreamDestroy(sd1);
    cudaStreamDestroy(sd2);
}

// round 13
// speedup vs baseline: 3.9640x; 1.0751x over previous
#include <cuda_runtime.h>
#include <cuda_fp16.h>
#include <cstdint>

#define EPSF 1e-5f

// ---------------- scratch (static device globals; no allocation) ----------------
__device__ __half g_xh[(size_t)1024 * 49 * 512];    // fp16 input
__device__ __half g_h[(size_t)4 * 21504 * 512];     // region GEMM out; activated fp16 in place
__device__ __half g_y[(size_t)12 * 21504 * 512];    // class GEMM out (pre-BN, fp16)
__device__ __half g_wt[(size_t)17 * 512 * 512];     // fragment-packed fp16 weights
__device__ __half g_hg[(size_t)1024 * 12 * 512];    // GAT projection (fp16)
__device__ __half g_fvh[(size_t)1024 * 12 * 512];   // f_v fp16 (GEMM operand)
__device__ float g_hmean[(size_t)4 * 1024 * 512];   // seq-mean of activated h
__device__ float g_fv[(size_t)1024 * 12 * 512];     // f_v fp32 (GAT residual)
__device__ float g_gat[(size_t)1024 * 12 * 512];    // GAT output
__device__ float g_v[(size_t)1024 * 12 * 512];      // temporal conv out (pre-BN)
__device__ float g_rstats[4 * 512 * 2];
__device__ float g_cstats[12 * 512 * 2];
__device__ float g_tstats[24];

__constant__ int c_sel[12]  = {0, 0, 0, 1, 0, 3, 2, 2, 2, 3, 3, 3};
__constant__ int c_start[4] = {0, 14, 28, 28};
__constant__ float c_adj[144] = {
    0,0,0,1,0,1,1,1,1,1,1,1,
    0,0,0,1,0,1,1,1,1,1,1,1,
    0,0,0,1,0,1,1,1,1,1,1,1,
    1,1,1,0,1,1,1,1,1,1,1,1,
    0,0,0,1,0,1,1,1,1,1,1,1,
    1,1,1,1,1,0,1,1,1,0,0,0,
    1,1,1,1,1,1,0,0,0,1,1,1,
    1,1,1,1,1,1,0,0,0,1,1,1,
    1,1,1,1,1,1,0,0,0,1,1,1,
    1,1,1,1,1,0,1,1,1,0,0,0,
    1,1,1,1,1,0,1,1,1,0,0,0,
    1,1,1,1,1,0,1,1,1,0,0,0
};

// ---------------- helpers ----------------
__device__ __forceinline__ uint32_t smem_u32(const void* p) {
    uint32_t a;
    asm("{ .reg .u64 t; cvta.to.shared.u64 t, %1; cvt.u32.u64 %0, t; }" : "=r"(a) : "l"(p));
    return a;
}
__device__ __forceinline__ uint32_t f2h2(float a, float b) {
    __half2 h = __floats2half2_rn(a, b);
    return *(uint32_t*)&h;
}
#define CP_ASYNC16(dst, src) \
    asm volatile("cp.async.ca.shared.global [%0], [%1], 16;" :: "r"(dst), "l"(src) : "memory")
#define CP_COMMIT() asm volatile("cp.async.commit_group;" ::: "memory")
#define CP_WAIT0()  asm volatile("cp.async.wait_group 0;" ::: "memory")

#define MMA_F16(D, A, B0, B1) \
    asm volatile("mma.sync.aligned.m16n8k16.row.col.f32.f16.f16.f32 " \
        "{%0,%1,%2,%3}, {%4,%5,%6,%7}, {%8,%9}, {%0,%1,%2,%3};" \
        : "+f"((D)[0]), "+f"((D)[1]), "+f"((D)[2]), "+f"((D)[3]) \
        : "r"((A)[0]), "r"((A)[1]), "r"((A)[2]), "r"((A)[3]), \
          "r"(B0), "r"(B1))

// ---------------- prep: x -> fp16, zero stats ----------------
__global__ void prep_kernel(const float* __restrict__ x) {
    size_t base = ((size_t)blockIdx.x * 256 + threadIdx.x) * 8;
    float4 f0 = *(const float4*)(x + base);
    float4 f1 = *(const float4*)(x + base + 4);
    uint4 u;
    u.x = f2h2(f0.x, f0.y); u.y = f2h2(f0.z, f0.w);
    u.z = f2h2(f1.x, f1.y); u.w = f2h2(f1.z, f1.w);
    *(uint4*)(g_xh + base) = u;
    if (blockIdx.x == 0) {
        for (int j = threadIdx.x; j < 4 * 512 * 2; j += 256)  g_rstats[j] = 0.f;
        for (int j = threadIdx.x; j < 12 * 512 * 2; j += 256) g_cstats[j] = 0.f;
        if (threadIdx.x < 24) g_tstats[threadIdx.x] = 0.f;
    }
}

// ---------------- weight fragment-pack to fp16 ----------------
// layout per z: [ntile 4][kbg 32][p 8][256 halfs in m16n8k16-B fragment order]
__global__ void pack_wt(const float* __restrict__ rW,
                        const float* __restrict__ cW,
                        const float* __restrict__ gW, int z0) {
    __shared__ float tile[16][17];
    const int z = blockIdx.z + z0;
    const int npg = blockIdx.y;     // global 16-col group 0..31
    const int kbg = blockIdx.x;     // k16 block 0..31
    const float* src = (z < 4) ? rW + (size_t)z * 262144
                     : (z < 16) ? cW + (size_t)(z - 4) * 262144 : gW;
    const int i = threadIdx.x;
    {
        int k_l = i >> 4, n_l = i & 15;
        tile[k_l][n_l] = src[(size_t)(kbg * 16 + k_l) * 512 + npg * 16 + n_l];
    }
    __syncthreads();
    const int l = i >> 3, rem = i & 7;
    const int sub = rem >> 2, reg = (rem >> 1) & 1, hi = rem & 1;
    const int g = l >> 2, t = l & 3;
    const int k_l = reg * 8 + t * 2 + hi;
    const int n_l = sub * 8 + g;
    const int ntile = npg >> 3, p = npg & 7;    // 128-col tiles
    size_t dst = ((((size_t)z * 4 + ntile) * 32 + kbg) * 8 + p) * 256 + i;
    g_wt[dst] = __float2half_rn(tile[k_l][n_l]);
}

// ================= fp16 mma.sync GEMM: block 128x128, 8 warps x (32x64), KC=32, 2 CTA/SM ======
// mode 0: A = g_xh (region gather),  Y = g_h,  stats = g_rstats
// mode 1: A = g_h (pre-activated),   Y = g_y,  stats = g_cstats
// mode 2: A = g_fvh,                 Y = g_hg, no stats/bias
#define SMEM_DYN 36864
__global__ void __launch_bounds__(256, 2) gemm_h(const float* __restrict__ bias, int M, int mode)
{
    extern __shared__ char smc[];
    __half* stg = (__half*)smc;     // epilogue stage reuse: [128][136] halfs (34816 B)
    __shared__ float s_bias[128], s_cs1[128], s_cs2[128];

    const int tid = threadIdx.x;
    const int w = tid >> 5, l = tid & 31;
    const int wm = w >> 1, wn = w & 1;      // warp tile: rows wm*32, cols wn*64
    const int g = l >> 2, t = l & 3;
    const int z = blockIdx.z;
    const int ntile = blockIdx.x;
    const int n0 = ntile * 128;
    const int m0 = blockIdx.y * 128;

    __half* Y;
    int sel = 0;
    if (mode == 0)      { Y = g_h; }
    else if (mode == 1) { Y = g_y; sel = c_sel[z]; }
    else                { Y = g_hg; }

    if (tid < 128) {
        s_bias[tid] = bias ? bias[(size_t)z * 512 + n0 + tid] : 0.f;
        s_cs1[tid] = 0.f;
        s_cs2[tid] = 0.f;
    }

    // A loader: thread = (row lrow 0..127, k-half hk covering 16 channels = 32B)
    const int lrow = tid >> 1, hk = tid & 1;
    const __half* arow;
    {
        int m = m0 + lrow;
        if (mode == 0) {
            int bt = m / 21, s = m - bt * 21;
            arow = g_xh + ((size_t)bt * 49 + c_start[z] + s) * 512;
        } else if (mode == 1) {
            arow = g_h + ((size_t)sel * 21504 + m) * 512;
        } else {
            arow = g_fvh + (size_t)m * 512;
        }
    }
    const int zw = (mode == 0) ? z : (mode == 1) ? 4 + z : 16;
    // per z: 524288 bytes; per 128-col ntile: 131072 bytes; per kbg: 4096 bytes
    const char* gB = (const char*)g_wt + (size_t)zw * 524288 + (size_t)ntile * 131072;
    const uint32_t sBase = smem_u32(smc);
    const uint32_t adst = sBase + lrow * 80 + hk * 32;
    const uint32_t bdst = sBase + 20480 + tid * 16;

    float d[2][8][4];
    #pragma unroll
    for (int mf = 0; mf < 2; ++mf)
        #pragma unroll
        for (int nf = 0; nf < 8; ++nf)
            #pragma unroll
            for (int q = 0; q < 4; ++q) d[mf][nf][q] = 0.f;

    auto loadAB = [&](int kt, int bf) {
        const char* as = (const char*)(arow + kt * 32 + hk * 16);
        uint32_t ad = adst + bf * 10240;
        CP_ASYNC16(ad, as);
        CP_ASYNC16(ad + 16, as + 16);
        const char* bs = gB + (size_t)kt * 8192 + tid * 16;
        uint32_t bd = bdst + bf * 8192;
        CP_ASYNC16(bd, bs);
        CP_ASYNC16(bd + 4096, bs + 4096);
        CP_COMMIT();
    };

    loadAB(0, 0);
    CP_WAIT0();
    __syncthreads();

    for (int kt = 0; kt < 16; ++kt) {
        const int buf = kt & 1;
        if (kt < 15) loadAB(kt + 1, buf ^ 1);
        const char* Ab = smc + buf * 10240;
        const char* Bb = smc + 20480 + buf * 8192;
        #pragma unroll
        for (int kb2 = 0; kb2 < 2; ++kb2) {
            uint32_t af[2][4];
            uint4 bv[4];
            #pragma unroll
            for (int mf = 0; mf < 2; ++mf) {
                int off = (wm * 32 + mf * 16 + g) * 80 + kb2 * 32 + t * 4;
                af[mf][0] = *(const uint32_t*)(Ab + off);
                af[mf][1] = *(const uint32_t*)(Ab + off + 640);
                af[mf][2] = *(const uint32_t*)(Ab + off + 16);
                af[mf][3] = *(const uint32_t*)(Ab + off + 656);
            }
            #pragma unroll
            for (int j = 0; j < 4; ++j)
                bv[j] = *(const uint4*)(Bb + ((kb2 * 8 + wn * 4 + j) * 32 + l) * 16);
            #pragma unroll
            for (int mf = 0; mf < 2; ++mf) {
                #pragma unroll
                for (int j = 0; j < 4; ++j) {
                    MMA_F16(d[mf][j * 2],     af[mf], bv[j].x, bv[j].y);
                    MMA_F16(d[mf][j * 2 + 1], af[mf], bv[j].z, bv[j].w);
                }
            }
        }
        if (kt < 15) CP_WAIT0();
        __syncthreads();
    }

    // ---- epilogue: single pass (block is 128 cols), half stage, fp32 stats ----
    {
        float cs[16], cq[16];
        #pragma unroll
        for (int i = 0; i < 16; ++i) { cs[i] = 0.f; cq[i] = 0.f; }
        #pragma unroll
        for (int mf = 0; mf < 2; ++mf) {
            #pragma unroll
            for (int nf = 0; nf < 8; ++nf) {
                int col = wn * 64 + nf * 8 + 2 * t;
                float b0 = s_bias[col], b1 = s_bias[col + 1];
                int r0 = wm * 32 + mf * 16 + g;
                float v00 = d[mf][nf][0] + b0;
                float v01 = d[mf][nf][1] + b1;
                float v10 = d[mf][nf][2] + b0;
                float v11 = d[mf][nf][3] + b1;
                *(__half2*)&stg[r0 * 136 + col]       = __floats2half2_rn(v00, v01);
                *(__half2*)&stg[(r0 + 8) * 136 + col] = __floats2half2_rn(v10, v11);
                cs[nf * 2]     += v00 + v10;
                cq[nf * 2]     += v00 * v00 + v10 * v10;
                cs[nf * 2 + 1] += v01 + v11;
                cq[nf * 2 + 1] += v01 * v01 + v11 * v11;
            }
        }
        if (mode != 2) {
            #pragma unroll
            for (int i = 0; i < 16; ++i) {
                #pragma unroll
                for (int msk = 4; msk <= 16; msk <<= 1) {
                    cs[i] += __shfl_xor_sync(0xFFFFFFFFu, cs[i], msk);
                    cq[i] += __shfl_xor_sync(0xFFFFFFFFu, cq[i], msk);
                }
            }
            if (l < 4) {
                #pragma unroll
                for (int nf = 0; nf < 8; ++nf) {
                    int col = wn * 64 + nf * 8 + 2 * l;
                    atomicAdd(&s_cs1[col],     cs[nf * 2]);
                    atomicAdd(&s_cs2[col],     cq[nf * 2]);
                    atomicAdd(&s_cs1[col + 1], cs[nf * 2 + 1]);
                    atomicAdd(&s_cs2[col + 1], cq[nf * 2 + 1]);
                }
            }
        }
    }
    __syncthreads();
    {
        int r = tid >> 1, hh = tid & 1;
        __half* yrow = Y + ((size_t)z * M + m0 + r) * 512 + n0 + hh * 64;
        const __half* srow = stg + r * 136 + hh * 64;
        #pragma unroll
        for (int q = 0; q < 8; ++q)
            *(uint4*)(yrow + q * 8) = *(const uint4*)(srow + q * 8);
    }
    if (mode != 2 && tid < 128) {
        float* stats = (mode == 0) ? g_rstats : g_cstats;
        atomicAdd(&stats[((size_t)z * 512 + n0 + tid) * 2],     s_cs1[tid]);
        atomicAdd(&stats[((size_t)z * 512 + n0 + tid) * 2 + 1], s_cs2[tid]);
    }
}

// ---------------- hmean: finalize region BN, activate g_h IN PLACE (fp16), seq-mean ----------------
__global__ void hmean_kernel(const float* __restrict__ gamma, const float* __restrict__ beta) {
    const int bt = blockIdx.x, r = blockIdx.y;
    const int c = threadIdx.x * 8;
    float sc[8], sh[8];
    #pragma unroll
    for (int j = 0; j < 8; ++j) {
        int i = r * 512 + c + j;
        float mean = g_rstats[i * 2] * (1.f / 21504.f);
        float var  = g_rstats[i * 2 + 1] * (1.f / 21504.f) - mean * mean;
        float rstd = rsqrtf(var + EPSF);
        sc[j] = gamma[i] * rstd;
        sh[j] = beta[i] - mean * sc[j];
    }
    size_t base = ((size_t)r * 21504 + (size_t)bt * 21) * 512 + c;
    float acc[8] = {0.f, 0.f, 0.f, 0.f, 0.f, 0.f, 0.f, 0.f};
    #pragma unroll
    for (int s = 0; s < 21; ++s) {
        uint4 u = *(const uint4*)(g_h + base + (size_t)s * 512);
        const __half2* hp = (const __half2*)&u;
        float av[8];
        #pragma unroll
        for (int p = 0; p < 4; ++p) {
            float2 f = __half22float2(hp[p]);
            av[p * 2]     = fmaxf(fmaf(f.x, sc[p * 2],     sh[p * 2]),     0.f);
            av[p * 2 + 1] = fmaxf(fmaf(f.y, sc[p * 2 + 1], sh[p * 2 + 1]), 0.f);
            acc[p * 2]     += av[p * 2];
            acc[p * 2 + 1] += av[p * 2 + 1];
        }
        uint4 o;
        o.x = f2h2(av[0], av[1]); o.y = f2h2(av[2], av[3]);
        o.z = f2h2(av[4], av[5]); o.w = f2h2(av[6], av[7]);
        *(uint4*)(g_h + base + (size_t)s * 512) = o;
    }
    float* dst = g_hmean + ((size_t)r * 1024 + bt) * 512 + c;
    #pragma unroll
    for (int j = 0; j < 8; ++j) dst[j] = acc[j] * (1.f / 21.f);
}

// ---------------- BN+ReLU on y + seq-mean -> f_v (fp32 + fp16) ----------------
__global__ void bn_y_kernel(const float* __restrict__ gamma, const float* __restrict__ beta) {
    const int bt = blockIdx.x, n = blockIdx.y;
    const int c = threadIdx.x * 8;
    float sc[8], sh[8];
    #pragma unroll
    for (int j = 0; j < 8; ++j) {
        int i = n * 512 + c + j;
        float mean = g_cstats[i * 2] * (1.f / 21504.f);
        float var  = g_cstats[i * 2 + 1] * (1.f / 21504.f) - mean * mean;
        float rstd = rsqrtf(var + EPSF);
        sc[j] = gamma[i] * rstd;
        sh[j] = beta[i] - mean * sc[j];
    }
    size_t base = ((size_t)n * 21504 + (size_t)bt * 21) * 512 + c;
    float acc[8] = {0.f, 0.f, 0.f, 0.f, 0.f, 0.f, 0.f, 0.f};
    #pragma unroll
    for (int s = 0; s < 21; ++s) {
        uint4 u = *(const uint4*)(g_y + base + (size_t)s * 512);
        const __half2* hp = (const __half2*)&u;
        #pragma unroll
        for (int p = 0; p < 4; ++p) {
            float2 f = __half22float2(hp[p]);
            acc[p * 2]     += fmaxf(fmaf(f.x, sc[p * 2],     sh[p * 2]),     0.f);
            acc[p * 2 + 1] += fmaxf(fmaf(f.y, sc[p * 2 + 1], sh[p * 2 + 1]), 0.f);
        }
    }
    size_t didx = ((size_t)bt * 12 + n) * 512 + c;
    float* dst = g_fv + didx;
    #pragma unroll
    for (int j = 0; j < 8; ++j) {
        acc[j] *= (1.f / 21.f);
        dst[j] = acc[j];
    }
    uint4 o;
    o.x = f2h2(acc[0], acc[1]); o.y = f2h2(acc[2], acc[3]);
    o.z = f2h2(acc[4], acc[5]); o.w = f2h2(acc[6], acc[7]);
    *(uint4*)(g_fvh + didx) = o;
}

// ---------------- prediction heads ----------------
__global__ void preds_kernel(const float* __restrict__ upW,  const float* __restrict__ upb,
                             const float* __restrict__ midW, const float* __restrict__ midb,
                             const float* __restrict__ d1W,  const float* __restrict__ d1b,
                             const float* __restrict__ d2W,  const float* __restrict__ d2b,
                             float* __restrict__ out)
{
    __shared__ float smh[2048];
    const int bt = blockIdx.x;
    for (int i = threadIdx.x; i < 2048; i += 256)
        smh[i] = g_hmean[((size_t)(i >> 9) * 1024 + bt) * 512 + (i & 511)];
    __syncthreads();
    const int w = threadIdx.x >> 5, l = threadIdx.x & 31;
    for (int o = w; o < 42; o += 8) {
        int r, j, nout;
        const float* Wp;
        const float* bp;
        float* op;
        if (o < 16)      { r = 0; j = o;      Wp = upW;  bp = upb;  op = out + (size_t)bt * 16;         nout = 16; }
        else if (o < 18) { r = 1; j = o - 16; Wp = midW; bp = midb; op = out + 16384 + (size_t)bt * 2;  nout = 2;  }
        else if (o < 26) { r = 2; j = o - 18; Wp = d1W;  bp = d1b;  op = out + 18432 + (size_t)bt * 8;  nout = 8;  }
        else             { r = 3; j = o - 26; Wp = d2W;  bp = d2b;  op = out + 26624 + (size_t)bt * 16; nout = 16; }
        float a = 0.f;
        for (int c = l; c < 512; c += 32) a += smh[r * 512 + c] * Wp[c * nout + j];
        #pragma unroll
        for (int off = 16; off; off >>= 1) a += __shfl_xor_sync(0xFFFFFFFFu, a, off);
        if (l == 0) op[j] = a + bp[j];
    }
}

// ---------------- GAT (fp16 hg read, half2 loads) ----------------
__global__ void gat_kernel(const float* __restrict__ adj_mask,
                           const float* __restrict__ al,
                           const float* __restrict__ ar)
{
    __shared__ float hs[12 * 512];
    __shared__ float alp[12], arp[12];
    __shared__ float att[144];
    const int bt = blockIdx.x;
    const __half2* hgb = (const __half2*)(g_hg + (size_t)bt * 12 * 512);
    for (int i = threadIdx.x; i < 3072; i += 256) {
        float2 f = __half22float2(hgb[i]);
        hs[i * 2] = f.x;
        hs[i * 2 + 1] = f.y;
    }
    __syncthreads();
    const int w = threadIdx.x >> 5, lane = threadIdx.x & 31;
    for (int dd = w; dd < 24; dd += 8) {
        int node = dd >> 1;
        const float* vec = (dd & 1) ? ar : al;
        float s = 0.f;
        for (int c = lane; c < 512; c += 32) s += hs[node * 512 + c] * vec[c];
        #pragma unroll
        for (int o = 16; o; o >>= 1) s += __shfl_xor_sync(0xFFFFFFFFu, s, o);
        if (lane == 0) { if (dd & 1) arp[node] = s; else alp[node] = s; }
    }
    __syncthreads();
    if (threadIdx.x < 144) {
        int i = threadIdx.x / 12, j = threadIdx.x % 12;
        float a = c_adj[threadIdx.x] * adj_mask[(size_t)bt * 144 + threadIdx.x] + (i == j ? 1.f : 0.f);
        float e = alp[i] + arp[j];
        e = (e > 0.f) ? e : 0.2f * e;
        att[threadIdx.x] = (a > 0.1f) ? e : -1e9f;
    }
    __syncthreads();
    if (threadIdx.x < 12) {
        int i = threadIdx.x;
        float mx = -1e30f;
        for (int j = 0; j < 12; ++j) mx = fmaxf(mx, att[i * 12 + j]);
        float tmp[12];
        float sum = 0.f;
        for (int j = 0; j < 12; ++j) { float ev = expf(att[i * 12 + j] - mx); tmp[j] = ev; sum += ev; }
        float invs = 1.f / sum;
        for (int j = 0; j < 12; ++j) att[i * 12 + j] = tmp[j] * invs;
    }
    __syncthreads();
    const float* fvb = g_fv + (size_t)bt * 12 * 512;
    float* gb = g_gat + (size_t)bt * 12 * 512;
    for (int idx = threadIdx.x; idx < 6144; idx += 256) {
        int n = idx >> 9, c = idx & 511;
        float s = fvb[idx];
        #pragma unroll
        for (int j = 0; j < 12; ++j) s += att[n * 12 + j] * hs[j * 512 + c];
        gb[idx] = s;
    }
}

// ---------------- temporal conv, register sliding window, + BN stats ----------------
__global__ void tconv_kernel(const float* __restrict__ W, const float* __restrict__ bias) {
    const int b = blockIdx.x, n = blockIdx.y;
    const int c = threadIdx.x;
    float in[32];
    #pragma unroll
    for (int t = 0; t < 32; ++t)
        in[t] = g_gat[(((size_t)(b * 32 + t)) * 12 + n) * 512 + c];
    const float* wp = W + ((size_t)n * 512 + c) * 5;
    float w0 = wp[0], w1 = wp[1], w2 = wp[2], w3 = wp[3], w4 = wp[4];
    const float bv = bias[n * 512 + c];
    float s = 0.f, s2 = 0.f;
    #pragma unroll
    for (int t = 0; t < 32; ++t) {
        float v = bv;
        if (t >= 2)      v = fmaf(in[t - 2], w0, v);
        if (t >= 1)      v = fmaf(in[t - 1], w1, v);
        v = fmaf(in[t], w2, v);
        if (t + 1 < 32)  v = fmaf(in[t + 1], w3, v);
        if (t + 2 < 32)  v = fmaf(in[t + 2], w4, v);
        g_v[(((size_t)(b * 32 + t)) * 12 + n) * 512 + c] = v;
        s += v;
        s2 = fmaf(v, v, s2);
    }
    #pragma unroll
    for (int o = 16; o; o >>= 1) {
        s  += __shfl_xor_sync(0xFFFFFFFFu, s, o);
        s2 += __shfl_xor_sync(0xFFFFFFFFu, s2, o);
    }
    __shared__ float wsum[16], wsq[16];
    const int lane = c & 31, wrp = c >> 5;
    if (lane == 0) { wsum[wrp] = s; wsq[wrp] = s2; }
    __syncthreads();
    if (c == 0) {
        float a = 0.f, b2 = 0.f;
        #pragma unroll
        for (int i = 0; i < 16; ++i) { a += wsum[i]; b2 += wsq[i]; }
        atomicAdd(&g_tstats[n * 2],     a);
        atomicAdd(&g_tstats[n * 2 + 1], b2);
    }
}

// ---------------- final per-class BN + ReLU (float4) ----------------
__global__ void tbn_kernel(const float* __restrict__ gamma, const float* __restrict__ beta,
                           float* __restrict__ out) {
    const int bt = blockIdx.x, n = blockIdx.y;
    const int c = threadIdx.x * 4;
    const float cnt = 1.f / (1024.f * 512.f);
    const float mean = g_tstats[n * 2] * cnt;
    const float var  = g_tstats[n * 2 + 1] * cnt - mean * mean;
    const float rstd = rsqrtf(var + EPSF);
    const float sc = gamma[n] * rstd;
    const float sh = beta[n] - mean * sc;
    size_t idx = ((size_t)bt * 12 + n) * 512 + c;
    float4 v = *(const float4*)(g_v + idx);
    v.x = fmaxf(fmaf(v.x, sc, sh), 0.f);
    v.y = fmaxf(fmaf(v.y, sc, sh), 0.f);
    v.z = fmaxf(fmaf(v.z, sc, sh), 0.f);
    v.w = fmaxf(fmaf(v.w, sc, sh), 0.f);
    *(float4*)(out + 43008 + idx) = v;
}

// ---------------- launch (fork/join on side streams) ----------------
extern "C" void kernel_launch(void* const* d_in, const int* in_sizes, int n_in,
                              void* d_out, int out_size)
{
    const float* x            = (const float*)d_in[0];
    const float* adj_mask     = (const float*)d_in[1];
    const float* region_W     = (const float*)d_in[2];
    const float* region_b     = (const float*)d_in[3];
    const float* region_gamma = (const float*)d_in[4];
    const float* region_beta  = (const float*)d_in[5];
    const float* upfc_W  = (const float*)d_in[6];
    const float* upfc_b  = (const float*)d_in[7];
    const float* midfc_W = (const float*)d_in[8];
    const float* midfc_b = (const float*)d_in[9];
    const float* d1fc_W  = (const float*)d_in[10];
    const float* d1fc_b  = (const float*)d_in[11];
    const float* d2fc_W  = (const float*)d_in[12];
    const float* d2fc_b  = (const float*)d_in[13];
    const float* class_W     = (const float*)d_in[14];
    const float* class_b     = (const float*)d_in[15];
    const float* class_gamma = (const float*)d_in[16];
    const float* class_beta  = (const float*)d_in[17];
    const float* gat_W  = (const float*)d_in[18];
    const float* gat_al = (const float*)d_in[19];
    const float* gat_ar = (const float*)d_in[20];
    const float* tconv_W   = (const float*)d_in[21];
    const float* tconv_b   = (const float*)d_in[22];
    const float* tbn_gamma = (const float*)d_in[23];
    const float* tbn_beta  = (const float*)d_in[24];
    float* out = (float*)d_out;

    cudaFuncSetAttribute(gemm_h, cudaFuncAttributeMaxDynamicSharedMemorySize, SMEM_DYN);

    cudaStream_t sd1, sd2;
    cudaStreamCreateWithFlags(&sd1, cudaStreamNonBlocking);
    cudaStreamCreateWithFlags(&sd2, cudaStreamNonBlocking);
    cudaEvent_t e0, e2, e3, e4;
    cudaEventCreateWithFlags(&e0, cudaEventDisableTiming);
    cudaEventCreateWithFlags(&e2, cudaEventDisableTiming);
    cudaEventCreateWithFlags(&e3, cudaEventDisableTiming);
    cudaEventCreateWithFlags(&e4, cudaEventDisableTiming);

    cudaEventRecord(e0, 0);
    cudaStreamWaitEvent(sd1, e0, 0);

    prep_kernel<<<12544, 256>>>(x);
    pack_wt<<<dim3(32, 32, 4), 256>>>(region_W, class_W, gat_W, 0);
    pack_wt<<<dim3(32, 32, 13), 256, 0, sd1>>>(region_W, class_W, gat_W, 4);
    cudaEventRecord(e3, sd1);

    gemm_h<<<dim3(4, 168, 4), 256, SMEM_DYN>>>(region_b, 21504, 0);
    hmean_kernel<<<dim3(1024, 4), 64>>>(region_gamma, region_beta);
    cudaEventRecord(e2, 0);

    cudaStreamWaitEvent(sd2, e2, 0);
    preds_kernel<<<1024, 256, 0, sd2>>>(upfc_W, upfc_b, midfc_W, midfc_b,
                                        d1fc_W, d1fc_b, d2fc_W, d2fc_b, out);
    cudaEventRecord(e4, sd2);

    cudaStreamWaitEvent(0, e3, 0);
    gemm_h<<<dim3(4, 168, 12), 256, SMEM_DYN>>>(class_b, 21504, 1);
    bn_y_kernel<<<dim3(1024, 12), 64>>>(class_gamma, class_beta);
    gemm_h<<<dim3(4, 96, 1), 256, SMEM_DYN>>>(nullptr, 12288, 2);
    gat_kernel<<<1024, 256>>>(adj_mask, gat_al, gat_ar);
    tconv_kernel<<<dim3(32, 12), 512>>>(tconv_W, tconv_b);
    tbn_kernel<<<dim3(1024, 12), 128>>>(tbn_gamma, tbn_beta, out);

    cudaStreamWaitEvent(0, e4, 0);

    cudaEventDestroy(e0);
    cudaEventDestroy(e2);
    cudaEventDestroy(e3);
    cudaEventDestroy(e4);
    cudaStreamDestroy(sd1);
    cudaStreamDestroy(sd2);
}

// round 15
// speedup vs baseline: 4.5716x; 1.1533x over previous
#include <cuda_runtime.h>
#include <cuda_fp16.h>
#include <cstdint>

#define EPSF 1e-5f

// ---------------- scratch (static device globals; no allocation) ----------------
__device__ __half g_xh[(size_t)1024 * 49 * 512];    // fp16 input
__device__ __half g_h[(size_t)4 * 21504 * 512];     // region GEMM out; activated fp16 in place
__device__ __half g_y[(size_t)12 * 21504 * 512];    // class GEMM out (pre-BN, fp16)
__device__ __half g_wt[(size_t)17 * 512 * 512];     // fragment-packed fp16 weights
__device__ __half g_hg[(size_t)1024 * 12 * 512];    // GAT projection (fp16)
__device__ __half g_fvh[(size_t)1024 * 12 * 512];   // f_v fp16 (GEMM operand)
__device__ float g_hmean[(size_t)4 * 1024 * 512];   // seq-mean of activated h
__device__ float g_fv[(size_t)1024 * 12 * 512];     // f_v fp32 (GAT residual)
__device__ float g_gat[(size_t)1024 * 12 * 512];    // GAT output
__device__ float g_v[(size_t)1024 * 12 * 512];      // temporal conv out (pre-BN)
__device__ float g_rstats[4 * 512 * 2];
__device__ float g_cstats[12 * 512 * 2];
__device__ float g_tstats[24];

__constant__ int c_sel[12]  = {0, 0, 0, 1, 0, 3, 2, 2, 2, 3, 3, 3};
__constant__ int c_start[4] = {0, 14, 28, 28};
__constant__ float c_adj[144] = {
    0,0,0,1,0,1,1,1,1,1,1,1,
    0,0,0,1,0,1,1,1,1,1,1,1,
    0,0,0,1,0,1,1,1,1,1,1,1,
    1,1,1,0,1,1,1,1,1,1,1,1,
    0,0,0,1,0,1,1,1,1,1,1,1,
    1,1,1,1,1,0,1,1,1,0,0,0,
    1,1,1,1,1,1,0,0,0,1,1,1,
    1,1,1,1,1,1,0,0,0,1,1,1,
    1,1,1,1,1,1,0,0,0,1,1,1,
    1,1,1,1,1,0,1,1,1,0,0,0,
    1,1,1,1,1,0,1,1,1,0,0,0,
    1,1,1,1,1,0,1,1,1,0,0,0
};

// ---------------- helpers ----------------
__device__ __forceinline__ uint32_t smem_u32(const void* p) {
    uint32_t a;
    asm("{ .reg .u64 t; cvta.to.shared.u64 t, %1; cvt.u32.u64 %0, t; }" : "=r"(a) : "l"(p));
    return a;
}
__device__ __forceinline__ uint32_t f2h2(float a, float b) {
    __half2 h = __floats2half2_rn(a, b);
    return *(uint32_t*)&h;
}
#define CP_ASYNC16(dst, src) \
    asm volatile("cp.async.ca.shared.global [%0], [%1], 16;" :: "r"(dst), "l"(src) : "memory")
#define CP_COMMIT() asm volatile("cp.async.commit_group;" ::: "memory")
#define CP_WAIT0()  asm volatile("cp.async.wait_group 0;" ::: "memory")
#define CP_WAIT1()  asm volatile("cp.async.wait_group 1;" ::: "memory")

#define LDSM_X4(r0, r1, r2, r3, addr) \
    asm volatile("ldmatrix.sync.aligned.m8n8.x4.shared.b16 {%0,%1,%2,%3}, [%4];" \
        : "=r"(r0), "=r"(r1), "=r"(r2), "=r"(r3) : "r"(addr))

#define MMA_F16(D, A, B0, B1) \
    asm volatile("mma.sync.aligned.m16n8k16.row.col.f32.f16.f16.f32 " \
        "{%0,%1,%2,%3}, {%4,%5,%6,%7}, {%8,%9}, {%0,%1,%2,%3};" \
        : "+f"((D)[0]), "+f"((D)[1]), "+f"((D)[2]), "+f"((D)[3]) \
        : "r"((A)[0]), "r"((A)[1]), "r"((A)[2]), "r"((A)[3]), \
          "r"(B0), "r"(B1))

// ---------------- prep: x -> fp16, zero stats ----------------
__global__ void prep_kernel(const float* __restrict__ x) {
    size_t base = ((size_t)blockIdx.x * 256 + threadIdx.x) * 8;
    float4 f0 = *(const float4*)(x + base);
    float4 f1 = *(const float4*)(x + base + 4);
    uint4 u;
    u.x = f2h2(f0.x, f0.y); u.y = f2h2(f0.z, f0.w);
    u.z = f2h2(f1.x, f1.y); u.w = f2h2(f1.z, f1.w);
    *(uint4*)(g_xh + base) = u;
    if (blockIdx.x == 0) {
        for (int j = threadIdx.x; j < 4 * 512 * 2; j += 256)  g_rstats[j] = 0.f;
        for (int j = threadIdx.x; j < 12 * 512 * 2; j += 256) g_cstats[j] = 0.f;
        if (threadIdx.x < 24) g_tstats[threadIdx.x] = 0.f;
    }
}

// ---------------- weight fragment-pack to fp16 ----------------
// layout per z: [ntile 4][kbg 32][p 8][256 halfs in m16n8k16-B fragment order]
__global__ void pack_wt(const float* __restrict__ rW,
                        const float* __restrict__ cW,
                        const float* __restrict__ gW, int z0) {
    __shared__ float tile[16][17];
    const int z = blockIdx.z + z0;
    const int npg = blockIdx.y;
    const int kbg = blockIdx.x;
    const float* src = (z < 4) ? rW + (size_t)z * 262144
                     : (z < 16) ? cW + (size_t)(z - 4) * 262144 : gW;
    const int i = threadIdx.x;
    {
        int k_l = i >> 4, n_l = i & 15;
        tile[k_l][n_l] = src[(size_t)(kbg * 16 + k_l) * 512 + npg * 16 + n_l];
    }
    __syncthreads();
    const int l = i >> 3, rem = i & 7;
    const int sub = rem >> 2, reg = (rem >> 1) & 1, hi = rem & 1;
    const int g = l >> 2, t = l & 3;
    const int k_l = reg * 8 + t * 2 + hi;
    const int n_l = sub * 8 + g;
    const int ntile = npg >> 3, p = npg & 7;
    size_t dst = ((((size_t)z * 4 + ntile) * 32 + kbg) * 8 + p) * 256 + i;
    g_wt[dst] = __float2half_rn(tile[k_l][n_l]);
}

// ====== fp16 mma.sync GEMM: block 128x128, 8 warps x (32x64), KC=32, 3-stage, ldmatrix A ======
// SMEM: A 3x10240 at 0; B 3x8192 at 30720; epilogue stage [128][136] halfs reuses from 0.
#define SMEM_DYN 55296
__global__ void __launch_bounds__(256, 2) gemm_h(const float* __restrict__ bias, int M, int mode)
{
    extern __shared__ char smc[];
    __half* stg = (__half*)smc;
    __shared__ float s_bias[128], s_cs1[128], s_cs2[128];

    const int tid = threadIdx.x;
    const int w = tid >> 5, l = tid & 31;
    const int wm = w >> 1, wn = w & 1;      // warp tile: rows wm*32, cols wn*64
    const int g = l >> 2, t = l & 3;
    const int z = blockIdx.z;
    const int ntile = blockIdx.x;
    const int n0 = ntile * 128;
    const int m0 = blockIdx.y * 128;

    __half* Y;
    int sel = 0;
    if (mode == 0)      { Y = g_h; }
    else if (mode == 1) { Y = g_y; sel = c_sel[z]; }
    else                { Y = g_hg; }

    if (tid < 128) {
        s_bias[tid] = bias ? bias[(size_t)z * 512 + n0 + tid] : 0.f;
        s_cs1[tid] = 0.f;
        s_cs2[tid] = 0.f;
    }

    // A loader: thread = (row lrow 0..127, k-half hk covering 16 channels = 32B)
    const int lrow = tid >> 1, hk = tid & 1;
    const __half* arow;
    {
        int m = m0 + lrow;
        if (mode == 0) {
            int bt = m / 21, s = m - bt * 21;
            arow = g_xh + ((size_t)bt * 49 + c_start[z] + s) * 512;
        } else if (mode == 1) {
            arow = g_h + ((size_t)sel * 21504 + m) * 512;
        } else {
            arow = g_fvh + (size_t)m * 512;
        }
    }
    const int zw = (mode == 0) ? z : (mode == 1) ? 4 + z : 16;
    const char* gB = (const char*)g_wt + (size_t)zw * 524288 + (size_t)ntile * 131072;
    const uint32_t sBase = smem_u32(smc);
    const uint32_t adst = sBase + lrow * 80 + hk * 32;
    const uint32_t bdst = sBase + 30720 + tid * 16;
    // ldmatrix lane address for A fragments: row = warp row base + (l&15), k-byte = (l>>4)*16
    const uint32_t a_lm = sBase + (wm * 32 + (l & 15)) * 80 + (l >> 4) * 16;

    float d[2][8][4];
    #pragma unroll
    for (int mf = 0; mf < 2; ++mf)
        #pragma unroll
        for (int nf = 0; nf < 8; ++nf)
            #pragma unroll
            for (int q = 0; q < 4; ++q) d[mf][nf][q] = 0.f;

    auto loadAB = [&](int kt, int bf) {
        const char* as = (const char*)(arow + kt * 32 + hk * 16);
        uint32_t ad = adst + bf * 10240;
        CP_ASYNC16(ad, as);
        CP_ASYNC16(ad + 16, as + 16);
        const char* bs = gB + (size_t)kt * 8192 + tid * 16;
        uint32_t bd = bdst + bf * 8192;
        CP_ASYNC16(bd, bs);
        CP_ASYNC16(bd + 4096, bs + 4096);
        CP_COMMIT();
    };

    // prologue: stages 0,1 in flight
    loadAB(0, 0);
    loadAB(1, 1);
    CP_WAIT1();             // stage 0 complete
    __syncthreads();

    for (int kt = 0; kt < 16; ++kt) {
        const int buf = kt - (kt / 3) * 3;   // kt % 3
        if (kt + 2 < 16) {
            int nb = (kt + 2) - ((kt + 2) / 3) * 3;
            loadAB(kt + 2, nb);
        }
        const char* Bb = smc + 30720 + buf * 8192;
        const uint32_t ab = a_lm + buf * 10240;
        #pragma unroll
        for (int kb2 = 0; kb2 < 2; ++kb2) {
            uint32_t af[2][4];
            uint4 bv[4];
            LDSM_X4(af[0][0], af[0][1], af[0][2], af[0][3], ab + kb2 * 32);
            LDSM_X4(af[1][0], af[1][1], af[1][2], af[1][3], ab + 16 * 80 + kb2 * 32);
            #pragma unroll
            for (int j = 0; j < 4; ++j)
                bv[j] = *(const uint4*)(Bb + ((kb2 * 8 + wn * 4 + j) * 32 + l) * 16);
            #pragma unroll
            for (int mf = 0; mf < 2; ++mf) {
                #pragma unroll
                for (int j = 0; j < 4; ++j) {
                    MMA_F16(d[mf][j * 2],     af[mf], bv[j].x, bv[j].y);
                    MMA_F16(d[mf][j * 2 + 1], af[mf], bv[j].z, bv[j].w);
                }
            }
        }
        if (kt < 15) {
            if (kt + 2 < 16) { CP_WAIT1(); } else { CP_WAIT0(); }
        }
        __syncthreads();
    }

    // ---- epilogue: single pass, half stage, fp32 stats ----
    {
        float cs[16], cq[16];
        #pragma unroll
        for (int i = 0; i < 16; ++i) { cs[i] = 0.f; cq[i] = 0.f; }
        #pragma unroll
        for (int mf = 0; mf < 2; ++mf) {
            #pragma unroll
            for (int nf = 0; nf < 8; ++nf) {
                int col = wn * 64 + nf * 8 + 2 * t;
                float b0 = s_bias[col], b1 = s_bias[col + 1];
                int r0 = wm * 32 + mf * 16 + g;
                float v00 = d[mf][nf][0] + b0;
                float v01 = d[mf][nf][1] + b1;
                float v10 = d[mf][nf][2] + b0;
                float v11 = d[mf][nf][3] + b1;
                *(__half2*)&stg[r0 * 136 + col]       = __floats2half2_rn(v00, v01);
                *(__half2*)&stg[(r0 + 8) * 136 + col] = __floats2half2_rn(v10, v11);
                cs[nf * 2]     += v00 + v10;
                cq[nf * 2]     += v00 * v00 + v10 * v10;
                cs[nf * 2 + 1] += v01 + v11;
                cq[nf * 2 + 1] += v01 * v01 + v11 * v11;
            }
        }
        if (mode != 2) {
            #pragma unroll
            for (int i = 0; i < 16; ++i) {
                #pragma unroll
                for (int msk = 4; msk <= 16; msk <<= 1) {
                    cs[i] += __shfl_xor_sync(0xFFFFFFFFu, cs[i], msk);
                    cq[i] += __shfl_xor_sync(0xFFFFFFFFu, cq[i], msk);
                }
            }
            if (l < 4) {
                #pragma unroll
                for (int nf = 0; nf < 8; ++nf) {
                    int col = wn * 64 + nf * 8 + 2 * l;
                    atomicAdd(&s_cs1[col],     cs[nf * 2]);
                    atomicAdd(&s_cs2[col],     cq[nf * 2]);
                    atomicAdd(&s_cs1[col + 1], cs[nf * 2 + 1]);
                    atomicAdd(&s_cs2[col + 1], cq[nf * 2 + 1]);
                }
            }
        }
    }
    __syncthreads();
    {
        int r = tid >> 1, hh = tid & 1;
        __half* yrow = Y + ((size_t)z * M + m0 + r) * 512 + n0 + hh * 64;
        const __half* srow = stg + r * 136 + hh * 64;
        #pragma unroll
        for (int q = 0; q < 8; ++q)
            *(uint4*)(yrow + q * 8) = *(const uint4*)(srow + q * 8);
    }
    if (mode != 2 && tid < 128) {
        float* stats = (mode == 0) ? g_rstats : g_cstats;
        atomicAdd(&stats[((size_t)z * 512 + n0 + tid) * 2],     s_cs1[tid]);
        atomicAdd(&stats[((size_t)z * 512 + n0 + tid) * 2 + 1], s_cs2[tid]);
    }
}

// ---------------- hmean: finalize region BN, activate g_h IN PLACE (fp16), seq-mean ----------------
__global__ void hmean_kernel(const float* __restrict__ gamma, const float* __restrict__ beta) {
    const int bt = blockIdx.x, r = blockIdx.y;
    const int c = threadIdx.x * 8;
    float sc[8], sh[8];
    #pragma unroll
    for (int j = 0; j < 8; ++j) {
        int i = r * 512 + c + j;
        float mean = g_rstats[i * 2] * (1.f / 21504.f);
        float var  = g_rstats[i * 2 + 1] * (1.f / 21504.f) - mean * mean;
        float rstd = rsqrtf(var + EPSF);
        sc[j] = gamma[i] * rstd;
        sh[j] = beta[i] - mean * sc[j];
    }
    size_t base = ((size_t)r * 21504 + (size_t)bt * 21) * 512 + c;
    float acc[8] = {0.f, 0.f, 0.f, 0.f, 0.f, 0.f, 0.f, 0.f};
    #pragma unroll
    for (int s = 0; s < 21; ++s) {
        uint4 u = *(const uint4*)(g_h + base + (size_t)s * 512);
        const __half2* hp = (const __half2*)&u;
        float av[8];
        #pragma unroll
        for (int p = 0; p < 4; ++p) {
            float2 f = __half22float2(hp[p]);
            av[p * 2]     = fmaxf(fmaf(f.x, sc[p * 2],     sh[p * 2]),     0.f);
            av[p * 2 + 1] = fmaxf(fmaf(f.y, sc[p * 2 + 1], sh[p * 2 + 1]), 0.f);
            acc[p * 2]     += av[p * 2];
            acc[p * 2 + 1] += av[p * 2 + 1];
        }
        uint4 o;
        o.x = f2h2(av[0], av[1]); o.y = f2h2(av[2], av[3]);
        o.z = f2h2(av[4], av[5]); o.w = f2h2(av[6], av[7]);
        *(uint4*)(g_h + base + (size_t)s * 512) = o;
    }
    float* dst = g_hmean + ((size_t)r * 1024 + bt) * 512 + c;
    #pragma unroll
    for (int j = 0; j < 8; ++j) dst[j] = acc[j] * (1.f / 21.f);
}

// ---------------- BN+ReLU on y + seq-mean -> f_v (fp32 + fp16) ----------------
__global__ void bn_y_kernel(const float* __restrict__ gamma, const float* __restrict__ beta) {
    const int bt = blockIdx.x, n = blockIdx.y;
    const int c = threadIdx.x * 8;
    float sc[8], sh[8];
    #pragma unroll
    for (int j = 0; j < 8; ++j) {
        int i = n * 512 + c + j;
        float mean = g_cstats[i * 2] * (1.f / 21504.f);
        float var  = g_cstats[i * 2 + 1] * (1.f / 21504.f) - mean * mean;
        float rstd = rsqrtf(var + EPSF);
        sc[j] = gamma[i] * rstd;
        sh[j] = beta[i] - mean * sc[j];
    }
    size_t base = ((size_t)n * 21504 + (size_t)bt * 21) * 512 + c;
    float acc[8] = {0.f, 0.f, 0.f, 0.f, 0.f, 0.f, 0.f, 0.f};
    #pragma unroll
    for (int s = 0; s < 21; ++s) {
        uint4 u = *(const uint4*)(g_y + base + (size_t)s * 512);
        const __half2* hp = (const __half2*)&u;
        #pragma unroll
        for (int p = 0; p < 4; ++p) {
            float2 f = __half22float2(hp[p]);
            acc[p * 2]     += fmaxf(fmaf(f.x, sc[p * 2],     sh[p * 2]),     0.f);
            acc[p * 2 + 1] += fmaxf(fmaf(f.y, sc[p * 2 + 1], sh[p * 2 + 1]), 0.f);
        }
    }
    size_t didx = ((size_t)bt * 12 + n) * 512 + c;
    float* dst = g_fv + didx;
    #pragma unroll
    for (int j = 0; j < 8; ++j) {
        acc[j] *= (1.f / 21.f);
        dst[j] = acc[j];
    }
    uint4 o;
    o.x = f2h2(acc[0], acc[1]); o.y = f2h2(acc[2], acc[3]);
    o.z = f2h2(acc[4], acc[5]); o.w = f2h2(acc[6], acc[7]);
    *(uint4*)(g_fvh + didx) = o;
}

// ---------------- prediction heads ----------------
__global__ void preds_kernel(const float* __restrict__ upW,  const float* __restrict__ upb,
                             const float* __restrict__ midW, const float* __restrict__ midb,
                             const float* __restrict__ d1W,  const float* __restrict__ d1b,
                             const float* __restrict__ d2W,  const float* __restrict__ d2b,
                             float* __restrict__ out)
{
    __shared__ float smh[2048];
    const int bt = blockIdx.x;
    for (int i = threadIdx.x; i < 2048; i += 256)
        smh[i] = g_hmean[((size_t)(i >> 9) * 1024 + bt) * 512 + (i & 511)];
    __syncthreads();
    const int w = threadIdx.x >> 5, l = threadIdx.x & 31;
    for (int o = w; o < 42; o += 8) {
        int r, j, nout;
        const float* Wp;
        const float* bp;
        float* op;
        if (o < 16)      { r = 0; j = o;      Wp = upW;  bp = upb;  op = out + (size_t)bt * 16;         nout = 16; }
        else if (o < 18) { r = 1; j = o - 16; Wp = midW; bp = midb; op = out + 16384 + (size_t)bt * 2;  nout = 2;  }
        else if (o < 26) { r = 2; j = o - 18; Wp = d1W;  bp = d1b;  op = out + 18432 + (size_t)bt * 8;  nout = 8;  }
        else             { r = 3; j = o - 26; Wp = d2W;  bp = d2b;  op = out + 26624 + (size_t)bt * 16; nout = 16; }
        float a = 0.f;
        for (int c = l; c < 512; c += 32) a += smh[r * 512 + c] * Wp[c * nout + j];
        #pragma unroll
        for (int off = 16; off; off >>= 1) a += __shfl_xor_sync(0xFFFFFFFFu, a, off);
        if (l == 0) op[j] = a + bp[j];
    }
}

// ---------------- GAT (fp16 hg read, half2 loads) ----------------
__global__ void gat_kernel(const float* __restrict__ adj_mask,
                           const float* __restrict__ al,
                           const float* __restrict__ ar)
{
    __shared__ float hs[12 * 512];
    __shared__ float alp[12], arp[12];
    __shared__ float att[144];
    const int bt = blockIdx.x;
    const __half2* hgb = (const __half2*)(g_hg + (size_t)bt * 12 * 512);
    for (int i = threadIdx.x; i < 3072; i += 256) {
        float2 f = __half22float2(hgb[i]);
        hs[i * 2] = f.x;
        hs[i * 2 + 1] = f.y;
    }
    __syncthreads();
    const int w = threadIdx.x >> 5, lane = threadIdx.x & 31;
    for (int dd = w; dd < 24; dd += 8) {
        int node = dd >> 1;
        const float* vec = (dd & 1) ? ar : al;
        float s = 0.f;
        for (int c = lane; c < 512; c += 32) s += hs[node * 512 + c] * vec[c];
        #pragma unroll
        for (int o = 16; o; o >>= 1) s += __shfl_xor_sync(0xFFFFFFFFu, s, o);
        if (lane == 0) { if (dd & 1) arp[node] = s; else alp[node] = s; }
    }
    __syncthreads();
    if (threadIdx.x < 144) {
        int i = threadIdx.x / 12, j = threadIdx.x % 12;
        float a = c_adj[threadIdx.x] * adj_mask[(size_t)bt * 144 + threadIdx.x] + (i == j ? 1.f : 0.f);
        float e = alp[i] + arp[j];
        e = (e > 0.f) ? e : 0.2f * e;
        att[threadIdx.x] = (a > 0.1f) ? e : -1e9f;
    }
    __syncthreads();
    if (threadIdx.x < 12) {
        int i = threadIdx.x;
        float mx = -1e30f;
        for (int j = 0; j < 12; ++j) mx = fmaxf(mx, att[i * 12 + j]);
        float tmp[12];
        float sum = 0.f;
        for (int j = 0; j < 12; ++j) { float ev = expf(att[i * 12 + j] - mx); tmp[j] = ev; sum += ev; }
        float invs = 1.f / sum;
        for (int j = 0; j < 12; ++j) att[i * 12 + j] = tmp[j] * invs;
    }
    __syncthreads();
    const float* fvb = g_fv + (size_t)bt * 12 * 512;
    float* gb = g_gat + (size_t)bt * 12 * 512;
    for (int idx = threadIdx.x; idx < 6144; idx += 256) {
        int n = idx >> 9, c = idx & 511;
        float s = fvb[idx];
        #pragma unroll
        for (int j = 0; j < 12; ++j) s += att[n * 12 + j] * hs[j * 512 + c];
        gb[idx] = s;
    }
}

// ---------------- temporal conv, register sliding window, + BN stats ----------------
__global__ void tconv_kernel(const float* __restrict__ W, const float* __restrict__ bias) {
    const int b = blockIdx.x, n = blockIdx.y;
    const int c = threadIdx.x;
    float in[32];
    #pragma unroll
    for (int t = 0; t < 32; ++t)
        in[t] = g_gat[(((size_t)(b * 32 + t)) * 12 + n) * 512 + c];
    const float* wp = W + ((size_t)n * 512 + c) * 5;
    float w0 = wp[0], w1 = wp[1], w2 = wp[2], w3 = wp[3], w4 = wp[4];
    const float bv = bias[n * 512 + c];
    float s = 0.f, s2 = 0.f;
    #pragma unroll
    for (int t = 0; t < 32; ++t) {
        float v = bv;
        if (t >= 2)      v = fmaf(in[t - 2], w0, v);
        if (t >= 1)      v = fmaf(in[t - 1], w1, v);
        v = fmaf(in[t], w2, v);
        if (t + 1 < 32)  v = fmaf(in[t + 1], w3, v);
        if (t + 2 < 32)  v = fmaf(in[t + 2], w4, v);
        g_v[(((size_t)(b * 32 + t)) * 12 + n) * 512 + c] = v;
        s += v;
        s2 = fmaf(v, v, s2);
    }
    #pragma unroll
    for (int o = 16; o; o >>= 1) {
        s  += __shfl_xor_sync(0xFFFFFFFFu, s, o);
        s2 += __shfl_xor_sync(0xFFFFFFFFu, s2, o);
    }
    __shared__ float wsum[16], wsq[16];
    const int lane = c & 31, wrp = c >> 5;
    if (lane == 0) { wsum[wrp] = s; wsq[wrp] = s2; }
    __syncthreads();
    if (c == 0) {
        float a = 0.f, b2 = 0.f;
        #pragma unroll
        for (int i = 0; i < 16; ++i) { a += wsum[i]; b2 += wsq[i]; }
        atomicAdd(&g_tstats[n * 2],     a);
        atomicAdd(&g_tstats[n * 2 + 1], b2);
    }
}

// ---------------- final per-class BN + ReLU (float4) ----------------
__global__ void tbn_kernel(const float* __restrict__ gamma, const float* __restrict__ beta,
                           float* __restrict__ out) {
    const int bt = blockIdx.x, n = blockIdx.y;
    const int c = threadIdx.x * 4;
    const float cnt = 1.f / (1024.f * 512.f);
    const float mean = g_tstats[n * 2] * cnt;
    const float var  = g_tstats[n * 2 + 1] * cnt - mean * mean;
    const float rstd = rsqrtf(var + EPSF);
    const float sc = gamma[n] * rstd;
    const float sh = beta[n] - mean * sc;
    size_t idx = ((size_t)bt * 12 + n) * 512 + c;
    float4 v = *(const float4*)(g_v + idx);
    v.x = fmaxf(fmaf(v.x, sc, sh), 0.f);
    v.y = fmaxf(fmaf(v.y, sc, sh), 0.f);
    v.z = fmaxf(fmaf(v.z, sc, sh), 0.f);
    v.w = fmaxf(fmaf(v.w, sc, sh), 0.f);
    *(float4*)(out + 43008 + idx) = v;
}

// ---------------- launch (fork/join on side streams) ----------------
extern "C" void kernel_launch(void* const* d_in, const int* in_sizes, int n_in,
                              void* d_out, int out_size)
{
    const float* x            = (const float*)d_in[0];
    const float* adj_mask     = (const float*)d_in[1];
    const float* region_W     = (const float*)d_in[2];
    const float* region_b     = (const float*)d_in[3];
    const float* region_gamma = (const float*)d_in[4];
    const float* region_beta  = (const float*)d_in[5];
    const float* upfc_W  = (const float*)d_in[6];
    const float* upfc_b  = (const float*)d_in[7];
    const float* midfc_W = (const float*)d_in[8];
    const float* midfc_b = (const float*)d_in[9];
    const float* d1fc_W  = (const float*)d_in[10];
    const float* d1fc_b  = (const float*)d_in[11];
    const float* d2fc_W  = (const float*)d_in[12];
    const float* d2fc_b  = (const float*)d_in[13];
    const float* class_W     = (const float*)d_in[14];
    const float* class_b     = (const float*)d_in[15];
    const float* class_gamma = (const float*)d_in[16];
    const float* class_beta  = (const float*)d_in[17];
    const float* gat_W  = (const float*)d_in[18];
    const float* gat_al = (const float*)d_in[19];
    const float* gat_ar = (const float*)d_in[20];
    const float* tconv_W   = (const float*)d_in[21];
    const float* tconv_b   = (const float*)d_in[22];
    const float* tbn_gamma = (const float*)d_in[23];
    const float* tbn_beta  = (const float*)d_in[24];
    float* out = (float*)d_out;

    cudaFuncSetAttribute(gemm_h, cudaFuncAttributeMaxDynamicSharedMemorySize, SMEM_DYN);

    cudaStream_t sd1, sd2;
    cudaStreamCreateWithFlags(&sd1, cudaStreamNonBlocking);
    cudaStreamCreateWithFlags(&sd2, cudaStreamNonBlocking);
    cudaEvent_t e0, e2, e3, e4;
    cudaEventCreateWithFlags(&e0, cudaEventDisableTiming);
    cudaEventCreateWithFlags(&e2, cudaEventDisableTiming);
    cudaEventCreateWithFlags(&e3, cudaEventDisableTiming);
    cudaEventCreateWithFlags(&e4, cudaEventDisableTiming);

    cudaEventRecord(e0, 0);
    cudaStreamWaitEvent(sd1, e0, 0);

    prep_kernel<<<12544, 256>>>(x);
    pack_wt<<<dim3(32, 32, 4), 256>>>(region_W, class_W, gat_W, 0);
    pack_wt<<<dim3(32, 32, 13), 256, 0, sd1>>>(region_W, class_W, gat_W, 4);
    cudaEventRecord(e3, sd1);

    gemm_h<<<dim3(4, 168, 4), 256, SMEM_DYN>>>(region_b, 21504, 0);
    hmean_kernel<<<dim3(1024, 4), 64>>>(region_gamma, region_beta);
    cudaEventRecord(e2, 0);

    cudaStreamWaitEvent(sd2, e2, 0);
    preds_kernel<<<1024, 256, 0, sd2>>>(upfc_W, upfc_b, midfc_W, midfc_b,
                                        d1fc_W, d1fc_b, d2fc_W, d2fc_b, out);
    cudaEventRecord(e4, sd2);

    cudaStreamWaitEvent(0, e3, 0);
    gemm_h<<<dim3(4, 168, 12), 256, SMEM_DYN>>>(class_b, 21504, 1);
    bn_y_kernel<<<dim3(1024, 12), 64>>>(class_gamma, class_beta);
    gemm_h<<<dim3(4, 96, 1), 256, SMEM_DYN>>>(nullptr, 12288, 2);
    gat_kernel<<<1024, 256>>>(adj_mask, gat_al, gat_ar);
    tconv_kernel<<<dim3(32, 12), 512>>>(tconv_W, tconv_b);
    tbn_kernel<<<dim3(1024, 12), 128>>>(tbn_gamma, tbn_beta, out);

    cudaStreamWaitEvent(0, e4, 0);

    cudaEventDestroy(e0);
    cudaEventDestroy(e2);
    cudaEventDestroy(e3);
    cudaEventDestroy(e4);
    cudaStreamDestroy(sd1);
    cudaStreamDestroy(sd2);
}